// round 9
// baseline (speedup 1.0000x reference)
#include <cuda_runtime.h>

typedef unsigned long long ull;
typedef unsigned int uint_;

#define B_   8
#define C_   256
#define H_   128
#define W_   128
#define CR_  32
#define HW_  (H_ * W_)

// ---------------- scratch (device globals; no runtime allocation) -------------
__device__ float g_q  [B_ * CR_ * HW_];   // (b, cr, h, w)
__device__ float g_k  [B_ * CR_ * HW_];
__device__ float g_v  [B_ * CR_ * HW_];
__device__ float g_qt [B_ * CR_ * HW_];   // (b, cr, w, h)
__device__ float g_kt [B_ * CR_ * HW_];
__device__ float g_vt [B_ * CR_ * HW_];
__device__ float g_oH [B_ * CR_ * HW_];   // (b, cr, w, h)
__device__ float g_oHt[B_ * CR_ * HW_];   // (b, cr, h, w)
__device__ float g_oW [B_ * CR_ * HW_];   // (b, cr, h, w)
__device__ float g_mH [B_ * HW_];
__device__ float g_sH [B_ * HW_];
__device__ float g_mW [B_ * HW_];
__device__ float g_sW [B_ * HW_];

// ---------------- packed f32x2 helpers ---------------------------------------
__device__ __forceinline__ ull fma2(ull a, ull b, ull c) {
    ull d;
    asm("fma.rn.f32x2 %0, %1, %2, %3;" : "=l"(d) : "l"(a), "l"(b), "l"(c));
    return d;
}
__device__ __forceinline__ ull splat2(float f) {
    ull r; uint_ u = __float_as_uint(f);
    asm("mov.b64 %0, {%1, %1};" : "=l"(r) : "r"(u));
    return r;
}
__device__ __forceinline__ ull pack2(float lo, float hi) {
    ull r;
    asm("mov.b64 %0, {%1, %2};" : "=l"(r)
        : "r"(__float_as_uint(lo)), "r"(__float_as_uint(hi)));
    return r;
}
__device__ __forceinline__ float2 unpack2(ull u) {
    uint_ lo, hi;
    asm("mov.b64 {%0, %1}, %2;" : "=r"(lo), "=r"(hi) : "l"(u));
    return make_float2(__uint_as_float(lo), __uint_as_float(hi));
}
__device__ __forceinline__ ull ldpair(const float* p) {
    union { float2 f2; ull u; } t;
    t.f2 = *reinterpret_cast<const float2*>(p);
    return t.u;
}

union F4U { float4 f4; ull u[2]; };

// bf16 hi/lo split: hi2/lo2 pack (elem0 -> low half, elem1 -> high half)
__device__ __forceinline__ void split_bf16(float x0, float x1, uint_& hi2, uint_& lo2) {
    asm("cvt.rn.satfinite.bf16x2.f32 %0, %1, %2;" : "=r"(hi2) : "f"(x1), "f"(x0));
    float h0 = __uint_as_float(hi2 << 16);
    float h1 = __uint_as_float(hi2 & 0xffff0000u);
    float l0 = x0 - h0, l1 = x1 - h1;
    asm("cvt.rn.satfinite.bf16x2.f32 %0, %1, %2;" : "=r"(lo2) : "f"(l1), "f"(l0));
}

// warp-level bf16 MMA: D(16x8,f32) += A(16x16,bf16 row) * B(16x8,bf16 col)
__device__ __forceinline__ void mma_bf16(float* d, const uint_* a, const uint_* b) {
    asm volatile(
        "mma.sync.aligned.m16n8k16.row.col.f32.bf16.bf16.f32 "
        "{%0,%1,%2,%3}, {%4,%5,%6,%7}, {%8,%9}, {%0,%1,%2,%3};"
        : "+f"(d[0]), "+f"(d[1]), "+f"(d[2]), "+f"(d[3])
        : "r"(a[0]), "r"(a[1]), "r"(a[2]), "r"(a[3]), "r"(b[0]), "r"(b[1]));
}

// ---------------- kernel 1: q/k/v projection via mma.sync bf16-split ----------
// grid (H, B), 256 threads. D[96 out][128 pix] = W(96x256) . x(256x128)
#define PJ_WPH   0
#define PJ_WPL   (96 * 36)
#define PJ_XPH   (2 * 96 * 36)
#define PJ_XPL   (2 * 96 * 36 + 32 * 136)
#define PJ_BIAS  (2 * 96 * 36 + 2 * 32 * 136)
#define PROJ_SMEM ((2 * 96 * 36 + 2 * 32 * 136 + 96) * 4)

__global__ void __launch_bounds__(256, 2) proj_mma_kernel(
    const float* __restrict__ x,
    const float* __restrict__ Wq, const float* __restrict__ bq,
    const float* __restrict__ Wk, const float* __restrict__ bk,
    const float* __restrict__ Wv, const float* __restrict__ bv)
{
    extern __shared__ uint_ ps[];
    uint_* Wph = ps + PJ_WPH;
    uint_* Wpl = ps + PJ_WPL;
    uint_* Xph = ps + PJ_XPH;
    uint_* Xpl = ps + PJ_XPL;
    float* bsm = reinterpret_cast<float*>(ps + PJ_BIAS);

    int h = blockIdx.x, b = blockIdx.y;
    int tid = threadIdx.x;
    int wid = tid >> 5, lane = tid & 31;
    int g = lane >> 2, tg = lane & 3;
    int wm = wid >> 2, wn = wid & 3;           // 2 x 4 warp grid
    int m0 = wm * 48, n0 = wn * 32;

    if (tid < 96) {
        float bv_;
        if (tid < 32)      bv_ = bq[tid];
        else if (tid < 64) bv_ = bk[tid - 32];
        else               bv_ = bv[tid - 64];
        bsm[tid] = bv_;
    }

    const float* xb = x + (size_t)b * C_ * HW_ + (size_t)h * W_;

    float acc[3][4][4];
#pragma unroll
    for (int mt = 0; mt < 3; mt++)
#pragma unroll
        for (int nt = 0; nt < 4; nt++)
#pragma unroll
            for (int u = 0; u < 4; u++) acc[mt][nt][u] = 0.f;

    int pixld = tid & 127, halfld = tid >> 7;

    for (int kc = 0; kc < 4; kc++) {
        if (kc) __syncthreads();
        for (int idx = tid; idx < 96 * 32; idx += 256) {
            int r = idx >> 5, kp = idx & 31;
            const float* wsrc;
            if (r < 32)      wsrc = Wq + (size_t)r * C_;
            else if (r < 64) wsrc = Wk + (size_t)(r - 32) * C_;
            else             wsrc = Wv + (size_t)(r - 64) * C_;
            float w0 = wsrc[kc * 64 + 2 * kp];
            float w1 = wsrc[kc * 64 + 2 * kp + 1];
            uint_ hi2, lo2;
            split_bf16(w0, w1, hi2, lo2);
            Wph[r * 36 + kp] = hi2;
            Wpl[r * 36 + kp] = lo2;
        }
#pragma unroll 4
        for (int kp2 = 0; kp2 < 16; kp2++) {
            int kp = kp2 * 2 + halfld;
            int c = kc * 64 + 2 * kp;
            float x0 = xb[(size_t)c * HW_ + pixld];
            float x1 = xb[(size_t)(c + 1) * HW_ + pixld];
            uint_ hi2, lo2;
            split_bf16(x0, x1, hi2, lo2);
            Xph[kp * 136 + pixld] = hi2;
            Xpl[kp * 136 + pixld] = lo2;
        }
        __syncthreads();

#pragma unroll
        for (int ks = 0; ks < 4; ks++) {
            int kpb = ks * 8;
            uint_ bh[4][2], bl[4][2];
#pragma unroll
            for (int nt = 0; nt < 4; nt++) {
                int n = n0 + nt * 8 + g;
                bh[nt][0] = Xph[(kpb + tg) * 136 + n];
                bh[nt][1] = Xph[(kpb + tg + 4) * 136 + n];
                bl[nt][0] = Xpl[(kpb + tg) * 136 + n];
                bl[nt][1] = Xpl[(kpb + tg + 4) * 136 + n];
            }
#pragma unroll
            for (int mt = 0; mt < 3; mt++) {
                int m = m0 + mt * 16 + g;
                uint_ ah[4], al[4];
                ah[0] = Wph[m * 36 + kpb + tg];
                ah[1] = Wph[(m + 8) * 36 + kpb + tg];
                ah[2] = Wph[m * 36 + kpb + tg + 4];
                ah[3] = Wph[(m + 8) * 36 + kpb + tg + 4];
                al[0] = Wpl[m * 36 + kpb + tg];
                al[1] = Wpl[(m + 8) * 36 + kpb + tg];
                al[2] = Wpl[m * 36 + kpb + tg + 4];
                al[3] = Wpl[(m + 8) * 36 + kpb + tg + 4];
#pragma unroll
                for (int nt = 0; nt < 4; nt++) {
                    mma_bf16(acc[mt][nt], ah, bh[nt]);
                    mma_bf16(acc[mt][nt], ah, bl[nt]);
                    mma_bf16(acc[mt][nt], al, bh[nt]);
                }
            }
        }
    }

#pragma unroll
    for (int mt = 0; mt < 3; mt++) {
#pragma unroll
        for (int half = 0; half < 2; half++) {
            int r = m0 + mt * 16 + g + 8 * half;
            float bias = bsm[r];
            float* dstb;
            int ch;
            if (r < 32)      { dstb = g_q; ch = r; }
            else if (r < 64) { dstb = g_k; ch = r - 32; }
            else             { dstb = g_v; ch = r - 64; }
            float* drow = dstb + ((size_t)(b * CR_ + ch) * H_ + h) * W_;
#pragma unroll
            for (int nt = 0; nt < 4; nt++) {
                int pix = n0 + nt * 8 + 2 * tg;
                float2 v;
                v.x = acc[mt][nt][2 * half]     + bias;
                v.y = acc[mt][nt][2 * half + 1] + bias;
                *reinterpret_cast<float2*>(&drow[pix]) = v;
            }
        }
    }
}

// ---------------- kernel 2: HxW tile transpose --------------------------------
__global__ void __launch_bounds__(256) transpose_kernel(int base_arr)
{
    __shared__ float tile[32][33];
    int zc = blockIdx.z;
    int arr = base_arr + (zc >> 8), m = zc & 255;
    const float* src; float* dst;
    if      (arr == 0) { src = g_q;  dst = g_qt;  }
    else if (arr == 1) { src = g_k;  dst = g_kt;  }
    else if (arr == 2) { src = g_v;  dst = g_vt;  }
    else               { src = g_oH; dst = g_oHt; }
    src += (size_t)m * HW_;
    dst += (size_t)m * HW_;
    int x0 = blockIdx.x * 32, y0 = blockIdx.y * 32;
    int tx = threadIdx.x, ty = threadIdx.y;
#pragma unroll
    for (int r = 0; r < 32; r += 8)
        tile[ty + r][tx] = src[(size_t)(y0 + ty + r) * W_ + x0 + tx];
    __syncthreads();
#pragma unroll
    for (int r = 0; r < 32; r += 8)
        dst[(size_t)(x0 + ty + r) * H_ + y0 + tx] = tile[tx][ty + r];
}

// ---------------- kernel 3: attention, two-pass E (3 CTAs/SM) -----------------
// grid (128, B, 2), 256 threads. z=1: H path, z=0: W path.
// Rows processed in two groups of 64; E is 64x128. Smem = 74752 B.
#define ATTN_SMEM ((32 * 68 + 32 * 128 + 128 * 33 + 64 * 128) * 4)

__global__ void __launch_bounds__(256, 3) attn_kernel()
{
    extern __shared__ float sm[];
    float* Qs  = sm;                        // 32 x 68  (per-pass Q / output stage)
    float* Ks  = sm + 32 * 68;              // 32 x 128
    float* Vst = Ks + 32 * 128;             // 128 x 33  ([i][c])
    float* E   = Vst + 128 * 33;            // 64 x 128

    int transposed = blockIdx.z;
    const float* qin = transposed ? g_qt : g_q;
    const float* kin = transposed ? g_kt : g_k;
    const float* vin = transposed ? g_vt : g_v;
    float* outp  = transposed ? g_oH : g_oW;
    float* mstat = transposed ? g_mH : g_mW;
    float* sstat = transposed ? g_sH : g_sW;

    int X = blockIdx.x, b = blockIdx.y;
    size_t base = (size_t)b * CR_ * HW_ + (size_t)X * W_;
    int tid = threadIdx.x, warp = tid >> 5, lane = tid & 31;

    // K and V^T resident for the whole block
    for (int idx = tid; idx < CR_ * 128; idx += 256) {
        int c = idx >> 7, e = idx & 127;
        Ks[c * 128 + e] = kin[base + (size_t)c * HW_ + e];
        Vst[e * 33 + c] = vin[base + (size_t)c * HW_ + e];
    }

    for (int pass = 0; pass < 2; pass++) {
        __syncthreads();   // Ks/Vst ready (pass 0); prev stage-read done (pass 1)
        // ---- load Q half: rows pass*64 .. +63 ----
        for (int idx = tid; idx < CR_ * 64; idx += 256) {
            int c = idx >> 6, r = idx & 63;
            Qs[c * 68 + r] = qin[base + (size_t)c * HW_ + pass * 64 + r];
        }
        __syncthreads();

        // ---- gram: 8 rows per warp; lane owns i = {2l,2l+1,2l+64,2l+65} ----
        ull acc[8][2];
#pragma unroll
        for (int t = 0; t < 8; t++) { acc[t][0] = 0ull; acc[t][1] = 0ull; }

#pragma unroll 4
        for (int c = 0; c < 32; c++) {
            ull k0 = ldpair(&Ks[c * 128 + 2 * lane]);
            ull k1 = ldpair(&Ks[c * 128 + 2 * lane + 64]);
            float4 q0 = *reinterpret_cast<const float4*>(&Qs[c * 68 + 8 * warp]);
            float4 q1 = *reinterpret_cast<const float4*>(&Qs[c * 68 + 8 * warp + 4]);
#define GSTEP(T, QF) { ull qv = splat2(QF); \
            acc[T][0] = fma2(qv, k0, acc[T][0]); acc[T][1] = fma2(qv, k1, acc[T][1]); }
            GSTEP(0, q0.x) GSTEP(1, q0.y) GSTEP(2, q0.z) GSTEP(3, q0.w)
            GSTEP(4, q1.x) GSTEP(5, q1.y) GSTEP(6, q1.z) GSTEP(7, q1.w)
#undef GSTEP
        }

        // ---- per-row softmax; probs into E (local row index), stats to gmem ----
#pragma unroll
        for (int t = 0; t < 8; t++) {
            int rl = warp * 8 + t;             // local row 0..63
            int r  = pass * 64 + rl;           // global row
            float2 a0 = unpack2(acc[t][0]);
            float2 a1 = unpack2(acc[t][1]);
            if (transposed) {
                int i0 = 2 * lane;
                if (i0      == r) a0.x = -1e30f;
                if (i0 + 1  == r) a0.y = -1e30f;
                if (i0 + 64 == r) a1.x = -1e30f;
                if (i0 + 65 == r) a1.y = -1e30f;
            }
            float mx = fmaxf(fmaxf(a0.x, a0.y), fmaxf(a1.x, a1.y));
#pragma unroll
            for (int o = 16; o > 0; o >>= 1) mx = fmaxf(mx, __shfl_xor_sync(0xffffffffu, mx, o));
            float p0 = __expf(a0.x - mx), p1 = __expf(a0.y - mx);
            float p2 = __expf(a1.x - mx), p3 = __expf(a1.y - mx);
            float sum = (p0 + p1) + (p2 + p3);
#pragma unroll
            for (int o = 16; o > 0; o >>= 1) sum += __shfl_xor_sync(0xffffffffu, sum, o);
            *reinterpret_cast<float2*>(&E[rl * 128 + 2 * lane])      = make_float2(p0, p1);
            *reinterpret_cast<float2*>(&E[rl * 128 + 2 * lane + 64]) = make_float2(p2, p3);
            if (lane == 0) {
                size_t sidx = transposed ? ((size_t)(b * H_ + r) * W_ + X)
                                         : ((size_t)(b * H_ + X) * W_ + r);
                mstat[sidx] = mx;
                sstat[sidx] = sum;
            }
        }
        __syncthreads();

        // ---- aggregation: out[c=lane][r] = sum_i V[i][c] * P[r][i] ----
        ull agg[8];
#pragma unroll
        for (int t = 0; t < 8; t++) agg[t] = 0ull;

        for (int i = 0; i < 128; i += 8) {
            ull vv[4];
#pragma unroll
            for (int u = 0; u < 4; u++)
                vv[u] = pack2(Vst[(i + 2 * u) * 33 + lane], Vst[(i + 2 * u + 1) * 33 + lane]);
#pragma unroll
            for (int t = 0; t < 8; t++) {
                F4U e0, e1;
                e0.f4 = *reinterpret_cast<const float4*>(&E[(warp * 8 + t) * 128 + i]);
                e1.f4 = *reinterpret_cast<const float4*>(&E[(warp * 8 + t) * 128 + i + 4]);
                agg[t] = fma2(e0.u[0], vv[0], agg[t]);
                agg[t] = fma2(e0.u[1], vv[1], agg[t]);
                agg[t] = fma2(e1.u[0], vv[2], agg[t]);
                agg[t] = fma2(e1.u[1], vv[3], agg[t]);
            }
        }

        // ---- stage transposed into Qs region + coalesced writeout ----
#pragma unroll
        for (int t = 0; t < 8; t++) {
            float2 s = unpack2(agg[t]);
            Qs[lane * 68 + warp * 8 + t] = s.x + s.y;
        }
        __syncthreads();
        for (int idx = tid; idx < CR_ * 64; idx += 256) {
            int c = idx >> 6, e = idx & 63;
            outp[base + (size_t)c * HW_ + pass * 64 + e] = Qs[c * 68 + e];
        }
    }
}

// ---------------- kernel 4: softmax merge + Wz conv + bias + residual --------
#define COMB_SMEM ((32 * 130 + 256 * 32 + 256) * 4)

__global__ void __launch_bounds__(512) combine_kernel(
    const float* __restrict__ x, const float* __restrict__ Wz,
    const float* __restrict__ bz, float* __restrict__ out)
{
    extern __shared__ float sm[];
    float* mg  = sm;                        // 32 x 130
    float* Wzs = sm + 32 * 130;             // 256 x 32
    float* fH  = sm + 32 * 130 + 256 * 32;  // 128
    float* fW  = fH + 128;                  // 128

    int h = blockIdx.x, b = blockIdx.y;
    int tid = threadIdx.x, wp = tid >> 5, lane = tid & 31;

    if (tid < 128) {
        int w = tid;
        size_t sidx = (size_t)(b * H_ + h) * W_ + w;
        float mh = g_mH[sidx], mw = g_mW[sidx];
        float sh = g_sH[sidx], sw = g_sW[sidx];
        float m  = fmaxf(mh, mw);
        float eh = __expf(mh - m), ew = __expf(mw - m);
        float inv = 1.0f / (sh * eh + sw * ew);
        fH[w] = eh * inv;
        fW[w] = ew * inv;
    }
    for (int idx = tid; idx < 256 * 32; idx += 512)
        Wzs[idx] = Wz[idx];
    __syncthreads();

    for (int idx = tid; idx < 32 * 128; idx += 512) {
        int c = idx >> 7, w = idx & 127;
        size_t off = (size_t)(b * CR_ + c) * HW_ + (size_t)h * W_ + w;
        mg[c * 130 + w] = g_oHt[off] * fH[w] + g_oW[off] * fW[w];
    }
    __syncthreads();

    ull acc[16][2];
#pragma unroll
    for (int j = 0; j < 16; j++) { acc[j][0] = 0ull; acc[j][1] = 0ull; }

#pragma unroll 4
    for (int c = 0; c < 32; c++) {
        ull m0 = ldpair(&mg[c * 130 + 2 * lane]);
        ull m1 = ldpair(&mg[c * 130 + 2 * lane + 64]);
#pragma unroll
        for (int j = 0; j < 16; j++) {
            ull wv = splat2(Wzs[(wp + 16 * j) * 32 + c]);
            acc[j][0] = fma2(wv, m0, acc[j][0]);
            acc[j][1] = fma2(wv, m1, acc[j][1]);
        }
    }

#pragma unroll
    for (int j = 0; j < 16; j++) {
        int o = wp + 16 * j;
        float bias = bz[o];
        size_t obase = ((size_t)(b * C_ + o) * H_ + h) * W_;
#pragma unroll
        for (int u = 0; u < 2; u++) {
            int w = 2 * lane + 64 * u;
            float2 xv = *reinterpret_cast<const float2*>(&x[obase + w]);
            float2 a  = unpack2(acc[j][u]);
            a.x += bias + xv.x;
            a.y += bias + xv.y;
            *reinterpret_cast<float2*>(&out[obase + w]) = a;
        }
    }
}

// ---------------- launch ------------------------------------------------------
extern "C" void kernel_launch(void* const* d_in, const int* in_sizes, int n_in,
                              void* d_out, int out_size)
{
    const float* x  = (const float*)d_in[0];
    const float* Wq = (const float*)d_in[1];
    const float* bq = (const float*)d_in[2];
    const float* Wk = (const float*)d_in[3];
    const float* bk = (const float*)d_in[4];
    const float* Wv = (const float*)d_in[5];
    const float* bv = (const float*)d_in[6];
    const float* Wz = (const float*)d_in[7];
    const float* bz = (const float*)d_in[8];
    float* out = (float*)d_out;

    cudaFuncSetAttribute(proj_mma_kernel, cudaFuncAttributeMaxDynamicSharedMemorySize, PROJ_SMEM);
    cudaFuncSetAttribute(attn_kernel,     cudaFuncAttributeMaxDynamicSharedMemorySize, ATTN_SMEM);
    cudaFuncSetAttribute(combine_kernel,  cudaFuncAttributeMaxDynamicSharedMemorySize, COMB_SMEM);

    proj_mma_kernel<<<dim3(H_, B_), 256, PROJ_SMEM>>>(x, Wq, bq, Wk, bk, Wv, bv);
    transpose_kernel<<<dim3(4, 4, 3 * 256), dim3(32, 8)>>>(0);   // q,k,v -> qt,kt,vt
    attn_kernel<<<dim3(128, B_, 2), 256, ATTN_SMEM>>>();         // H + W paths
    transpose_kernel<<<dim3(4, 4, 256), dim3(32, 8)>>>(3);       // oH -> oHt
    combine_kernel<<<dim3(H_, B_), 512, COMB_SMEM>>>(x, Wz, bz, out);
}

// round 10
// speedup vs baseline: 1.3113x; 1.3113x over previous
#include <cuda_runtime.h>

typedef unsigned long long ull;
typedef unsigned int uint_;

#define B_   8
#define C_   256
#define H_   128
#define W_   128
#define CR_  32
#define HW_  (H_ * W_)

// ---------------- scratch (device globals; no runtime allocation) -------------
__device__ float g_q  [B_ * CR_ * HW_];   // (b, cr, h, w)
__device__ float g_k  [B_ * CR_ * HW_];
__device__ float g_v  [B_ * CR_ * HW_];
__device__ float g_qt [B_ * CR_ * HW_];   // (b, cr, w, h)
__device__ float g_kt [B_ * CR_ * HW_];
__device__ float g_vt [B_ * CR_ * HW_];
__device__ float g_oH [B_ * CR_ * HW_];   // (b, cr, w, h)
__device__ float g_oHt[B_ * CR_ * HW_];   // (b, cr, h, w)
__device__ float g_oW [B_ * CR_ * HW_];   // (b, cr, h, w)
__device__ float g_mH [B_ * HW_];
__device__ float g_sH [B_ * HW_];
__device__ float g_mW [B_ * HW_];
__device__ float g_sW [B_ * HW_];

// ---------------- packed f32x2 helpers ---------------------------------------
__device__ __forceinline__ ull fma2(ull a, ull b, ull c) {
    ull d;
    asm("fma.rn.f32x2 %0, %1, %2, %3;" : "=l"(d) : "l"(a), "l"(b), "l"(c));
    return d;
}
__device__ __forceinline__ ull splat2(float f) {
    ull r; uint_ u = __float_as_uint(f);
    asm("mov.b64 %0, {%1, %1};" : "=l"(r) : "r"(u));
    return r;
}
__device__ __forceinline__ ull pack2(float lo, float hi) {
    ull r;
    asm("mov.b64 %0, {%1, %2};" : "=l"(r)
        : "r"(__float_as_uint(lo)), "r"(__float_as_uint(hi)));
    return r;
}
__device__ __forceinline__ float2 unpack2(ull u) {
    uint_ lo, hi;
    asm("mov.b64 {%0, %1}, %2;" : "=r"(lo), "=r"(hi) : "l"(u));
    return make_float2(__uint_as_float(lo), __uint_as_float(hi));
}
__device__ __forceinline__ ull ldpair(const float* p) {
    union { float2 f2; ull u; } t;
    t.f2 = *reinterpret_cast<const float2*>(p);
    return t.u;
}

union F4U { float4 f4; ull u[2]; };

// bf16 hi/lo split: hi2/lo2 pack (elem0 -> low half, elem1 -> high half)
__device__ __forceinline__ void split_bf16(float x0, float x1, uint_& hi2, uint_& lo2) {
    asm("cvt.rn.satfinite.bf16x2.f32 %0, %1, %2;" : "=r"(hi2) : "f"(x1), "f"(x0));
    float h0 = __uint_as_float(hi2 << 16);
    float h1 = __uint_as_float(hi2 & 0xffff0000u);
    float l0 = x0 - h0, l1 = x1 - h1;
    asm("cvt.rn.satfinite.bf16x2.f32 %0, %1, %2;" : "=r"(lo2) : "f"(l1), "f"(l0));
}

// warp-level bf16 MMA: D(16x8,f32) += A(16x16,bf16 row) * B(16x8,bf16 col)
__device__ __forceinline__ void mma_bf16(float* d, const uint_* a, const uint_* b) {
    asm volatile(
        "mma.sync.aligned.m16n8k16.row.col.f32.bf16.bf16.f32 "
        "{%0,%1,%2,%3}, {%4,%5,%6,%7}, {%8,%9}, {%0,%1,%2,%3};"
        : "+f"(d[0]), "+f"(d[1]), "+f"(d[2]), "+f"(d[3])
        : "r"(a[0]), "r"(a[1]), "r"(a[2]), "r"(a[3]), "r"(b[0]), "r"(b[1]));
}

// ---------------- kernel 1: q/k/v projection via mma.sync bf16-split ----------
// grid (H, B), 256 threads. D[96 out][128 pix] = W(96x256) . x(256x128)
#define PJ_WPH   0
#define PJ_WPL   (96 * 36)
#define PJ_XPH   (2 * 96 * 36)
#define PJ_XPL   (2 * 96 * 36 + 32 * 136)
#define PJ_BIAS  (2 * 96 * 36 + 2 * 32 * 136)
#define PROJ_SMEM ((2 * 96 * 36 + 2 * 32 * 136 + 96) * 4)

__global__ void __launch_bounds__(256, 2) proj_mma_kernel(
    const float* __restrict__ x,
    const float* __restrict__ Wq, const float* __restrict__ bq,
    const float* __restrict__ Wk, const float* __restrict__ bk,
    const float* __restrict__ Wv, const float* __restrict__ bv)
{
    extern __shared__ uint_ ps[];
    uint_* Wph = ps + PJ_WPH;
    uint_* Wpl = ps + PJ_WPL;
    uint_* Xph = ps + PJ_XPH;
    uint_* Xpl = ps + PJ_XPL;
    float* bsm = reinterpret_cast<float*>(ps + PJ_BIAS);

    int h = blockIdx.x, b = blockIdx.y;
    int tid = threadIdx.x;
    int wid = tid >> 5, lane = tid & 31;
    int g = lane >> 2, tg = lane & 3;
    int wm = wid >> 2, wn = wid & 3;           // 2 x 4 warp grid
    int m0 = wm * 48, n0 = wn * 32;

    if (tid < 96) {
        float bv_;
        if (tid < 32)      bv_ = bq[tid];
        else if (tid < 64) bv_ = bk[tid - 32];
        else               bv_ = bv[tid - 64];
        bsm[tid] = bv_;
    }

    const float* xb = x + (size_t)b * C_ * HW_ + (size_t)h * W_;

    float acc[3][4][4];
#pragma unroll
    for (int mt = 0; mt < 3; mt++)
#pragma unroll
        for (int nt = 0; nt < 4; nt++)
#pragma unroll
            for (int u = 0; u < 4; u++) acc[mt][nt][u] = 0.f;

    int pixld = tid & 127, halfld = tid >> 7;

    for (int kc = 0; kc < 4; kc++) {
        if (kc) __syncthreads();
        for (int idx = tid; idx < 96 * 32; idx += 256) {
            int r = idx >> 5, kp = idx & 31;
            const float* wsrc;
            if (r < 32)      wsrc = Wq + (size_t)r * C_;
            else if (r < 64) wsrc = Wk + (size_t)(r - 32) * C_;
            else             wsrc = Wv + (size_t)(r - 64) * C_;
            float w0 = wsrc[kc * 64 + 2 * kp];
            float w1 = wsrc[kc * 64 + 2 * kp + 1];
            uint_ hi2, lo2;
            split_bf16(w0, w1, hi2, lo2);
            Wph[r * 36 + kp] = hi2;
            Wpl[r * 36 + kp] = lo2;
        }
#pragma unroll 4
        for (int kp2 = 0; kp2 < 16; kp2++) {
            int kp = kp2 * 2 + halfld;
            int c = kc * 64 + 2 * kp;
            float x0 = xb[(size_t)c * HW_ + pixld];
            float x1 = xb[(size_t)(c + 1) * HW_ + pixld];
            uint_ hi2, lo2;
            split_bf16(x0, x1, hi2, lo2);
            Xph[kp * 136 + pixld] = hi2;
            Xpl[kp * 136 + pixld] = lo2;
        }
        __syncthreads();

#pragma unroll
        for (int ks = 0; ks < 4; ks++) {
            int kpb = ks * 8;
            uint_ bh[4][2], bl[4][2];
#pragma unroll
            for (int nt = 0; nt < 4; nt++) {
                int n = n0 + nt * 8 + g;
                bh[nt][0] = Xph[(kpb + tg) * 136 + n];
                bh[nt][1] = Xph[(kpb + tg + 4) * 136 + n];
                bl[nt][0] = Xpl[(kpb + tg) * 136 + n];
                bl[nt][1] = Xpl[(kpb + tg + 4) * 136 + n];
            }
#pragma unroll
            for (int mt = 0; mt < 3; mt++) {
                int m = m0 + mt * 16 + g;
                uint_ ah[4], al[4];
                ah[0] = Wph[m * 36 + kpb + tg];
                ah[1] = Wph[(m + 8) * 36 + kpb + tg];
                ah[2] = Wph[m * 36 + kpb + tg + 4];
                ah[3] = Wph[(m + 8) * 36 + kpb + tg + 4];
                al[0] = Wpl[m * 36 + kpb + tg];
                al[1] = Wpl[(m + 8) * 36 + kpb + tg];
                al[2] = Wpl[m * 36 + kpb + tg + 4];
                al[3] = Wpl[(m + 8) * 36 + kpb + tg + 4];
#pragma unroll
                for (int nt = 0; nt < 4; nt++) {
                    mma_bf16(acc[mt][nt], ah, bh[nt]);
                    mma_bf16(acc[mt][nt], ah, bl[nt]);
                    mma_bf16(acc[mt][nt], al, bh[nt]);
                }
            }
        }
    }

#pragma unroll
    for (int mt = 0; mt < 3; mt++) {
#pragma unroll
        for (int half = 0; half < 2; half++) {
            int r = m0 + mt * 16 + g + 8 * half;
            float bias = bsm[r];
            float* dstb;
            int ch;
            if (r < 32)      { dstb = g_q; ch = r; }
            else if (r < 64) { dstb = g_k; ch = r - 32; }
            else             { dstb = g_v; ch = r - 64; }
            float* drow = dstb + ((size_t)(b * CR_ + ch) * H_ + h) * W_;
#pragma unroll
            for (int nt = 0; nt < 4; nt++) {
                int pix = n0 + nt * 8 + 2 * tg;
                float2 v;
                v.x = acc[mt][nt][2 * half]     + bias;
                v.y = acc[mt][nt][2 * half + 1] + bias;
                *reinterpret_cast<float2*>(&drow[pix]) = v;
            }
        }
    }
}

// ---------------- kernel 2: HxW tile transpose --------------------------------
__global__ void __launch_bounds__(256) transpose_kernel(int base_arr)
{
    __shared__ float tile[32][33];
    int zc = blockIdx.z;
    int arr = base_arr + (zc >> 8), m = zc & 255;
    const float* src; float* dst;
    if      (arr == 0) { src = g_q;  dst = g_qt;  }
    else if (arr == 1) { src = g_k;  dst = g_kt;  }
    else if (arr == 2) { src = g_v;  dst = g_vt;  }
    else               { src = g_oH; dst = g_oHt; }
    src += (size_t)m * HW_;
    dst += (size_t)m * HW_;
    int x0 = blockIdx.x * 32, y0 = blockIdx.y * 32;
    int tx = threadIdx.x, ty = threadIdx.y;
#pragma unroll
    for (int r = 0; r < 32; r += 8)
        tile[ty + r][tx] = src[(size_t)(y0 + ty + r) * W_ + x0 + tx];
    __syncthreads();
#pragma unroll
    for (int r = 0; r < 32; r += 8)
        dst[(size_t)(x0 + ty + r) * H_ + y0 + tx] = tile[tx][ty + r];
}

// ---------------- kernel 3: attention path (round-8 body, merged launch) -----
// grid (128, B, 2), 256 threads. z=1: H path (transposed), z=0: W path.
// Smem = 115712 B -> 2 CTAs/SM.
#define ATTN_SMEM ((32 * 132 + 32 * 128 + 128 * 33 + 128 * 128) * 4)

__global__ void __launch_bounds__(256) attn_kernel()
{
    extern __shared__ float sm[];
    float* Qs  = sm;                        // 32 x 132
    float* Ks  = sm + 32 * 132;             // 32 x 128
    float* Vst = Ks + 32 * 128;             // 128 x 33
    float* E   = Vst + 128 * 33;            // 128 x 128

    int transposed = blockIdx.z;
    const float* qin = transposed ? g_qt : g_q;
    const float* kin = transposed ? g_kt : g_k;
    const float* vin = transposed ? g_vt : g_v;
    float* outp  = transposed ? g_oH : g_oW;
    float* mstat = transposed ? g_mH : g_mW;
    float* sstat = transposed ? g_sH : g_sW;

    int X = blockIdx.x, b = blockIdx.y;
    size_t base = (size_t)b * CR_ * HW_ + (size_t)X * W_;
    int tid = threadIdx.x, warp = tid >> 5, lane = tid & 31;

    for (int idx = tid; idx < CR_ * 128; idx += 256) {
        int c = idx >> 7, e = idx & 127;
        Qs[c * 132 + e] = qin[base + (size_t)c * HW_ + e];
        Ks[c * 128 + e] = kin[base + (size_t)c * HW_ + e];
        Vst[e * 33 + c] = vin[base + (size_t)c * HW_ + e];
    }
    __syncthreads();

    ull acc[16][2];
#pragma unroll
    for (int t = 0; t < 16; t++) { acc[t][0] = 0ull; acc[t][1] = 0ull; }

#pragma unroll 2
    for (int c = 0; c < 32; c++) {
        ull k0 = ldpair(&Ks[c * 128 + 2 * lane]);
        ull k1 = ldpair(&Ks[c * 128 + 2 * lane + 64]);
        float4 q0 = *reinterpret_cast<const float4*>(&Qs[c * 132 + 16 * warp]);
        float4 q1 = *reinterpret_cast<const float4*>(&Qs[c * 132 + 16 * warp + 4]);
        float4 q2 = *reinterpret_cast<const float4*>(&Qs[c * 132 + 16 * warp + 8]);
        float4 q3 = *reinterpret_cast<const float4*>(&Qs[c * 132 + 16 * warp + 12]);
#define GSTEP(T, QF) { ull qv = splat2(QF); \
        acc[T][0] = fma2(qv, k0, acc[T][0]); acc[T][1] = fma2(qv, k1, acc[T][1]); }
        GSTEP(0,  q0.x) GSTEP(1,  q0.y) GSTEP(2,  q0.z) GSTEP(3,  q0.w)
        GSTEP(4,  q1.x) GSTEP(5,  q1.y) GSTEP(6,  q1.z) GSTEP(7,  q1.w)
        GSTEP(8,  q2.x) GSTEP(9,  q2.y) GSTEP(10, q2.z) GSTEP(11, q2.w)
        GSTEP(12, q3.x) GSTEP(13, q3.y) GSTEP(14, q3.z) GSTEP(15, q3.w)
#undef GSTEP
    }

#pragma unroll
    for (int t = 0; t < 16; t++) {
        int r = warp * 16 + t;
        float2 a0 = unpack2(acc[t][0]);
        float2 a1 = unpack2(acc[t][1]);
        if (transposed) {
            int i0 = 2 * lane;
            if (i0      == r) a0.x = -1e30f;
            if (i0 + 1  == r) a0.y = -1e30f;
            if (i0 + 64 == r) a1.x = -1e30f;
            if (i0 + 65 == r) a1.y = -1e30f;
        }
        float mx = fmaxf(fmaxf(a0.x, a0.y), fmaxf(a1.x, a1.y));
#pragma unroll
        for (int o = 16; o > 0; o >>= 1) mx = fmaxf(mx, __shfl_xor_sync(0xffffffffu, mx, o));
        float p0 = __expf(a0.x - mx), p1 = __expf(a0.y - mx);
        float p2 = __expf(a1.x - mx), p3 = __expf(a1.y - mx);
        float sum = (p0 + p1) + (p2 + p3);
#pragma unroll
        for (int o = 16; o > 0; o >>= 1) sum += __shfl_xor_sync(0xffffffffu, sum, o);
        *reinterpret_cast<float2*>(&E[r * 128 + 2 * lane])      = make_float2(p0, p1);
        *reinterpret_cast<float2*>(&E[r * 128 + 2 * lane + 64]) = make_float2(p2, p3);
        if (lane == 0) {
            size_t sidx = transposed ? ((size_t)(b * H_ + r) * W_ + X)
                                     : ((size_t)(b * H_ + X) * W_ + r);
            mstat[sidx] = mx;
            sstat[sidx] = sum;
        }
    }
    __syncthreads();

    ull agg[16];
#pragma unroll
    for (int t = 0; t < 16; t++) agg[t] = 0ull;

    for (int i = 0; i < 128; i += 8) {
        ull vv[4];
#pragma unroll
        for (int u = 0; u < 4; u++)
            vv[u] = pack2(Vst[(i + 2 * u) * 33 + lane], Vst[(i + 2 * u + 1) * 33 + lane]);
#pragma unroll
        for (int t = 0; t < 16; t++) {
            F4U e0, e1;
            e0.f4 = *reinterpret_cast<const float4*>(&E[(warp * 16 + t) * 128 + i]);
            e1.f4 = *reinterpret_cast<const float4*>(&E[(warp * 16 + t) * 128 + i + 4]);
            agg[t] = fma2(e0.u[0], vv[0], agg[t]);
            agg[t] = fma2(e0.u[1], vv[1], agg[t]);
            agg[t] = fma2(e1.u[0], vv[2], agg[t]);
            agg[t] = fma2(e1.u[1], vv[3], agg[t]);
        }
    }

#pragma unroll
    for (int t = 0; t < 16; t++) {
        float2 s = unpack2(agg[t]);
        Qs[lane * 130 + warp * 16 + t] = s.x + s.y;
    }
    __syncthreads();
    for (int idx = tid; idx < CR_ * 128; idx += 256) {
        int c = idx >> 7, e = idx & 127;
        outp[base + (size_t)c * HW_ + e] = Qs[c * 130 + e];
    }
}

// ---------------- kernel 4: softmax merge + Wz conv + bias + residual --------
#define COMB_SMEM ((32 * 130 + 256 * 32 + 256) * 4)

__global__ void __launch_bounds__(512) combine_kernel(
    const float* __restrict__ x, const float* __restrict__ Wz,
    const float* __restrict__ bz, float* __restrict__ out)
{
    extern __shared__ float sm[];
    float* mg  = sm;                        // 32 x 130
    float* Wzs = sm + 32 * 130;             // 256 x 32
    float* fH  = sm + 32 * 130 + 256 * 32;  // 128
    float* fW  = fH + 128;                  // 128

    int h = blockIdx.x, b = blockIdx.y;
    int tid = threadIdx.x, wp = tid >> 5, lane = tid & 31;

    if (tid < 128) {
        int w = tid;
        size_t sidx = (size_t)(b * H_ + h) * W_ + w;
        float mh = g_mH[sidx], mw = g_mW[sidx];
        float sh = g_sH[sidx], sw = g_sW[sidx];
        float m  = fmaxf(mh, mw);
        float eh = __expf(mh - m), ew = __expf(mw - m);
        float inv = 1.0f / (sh * eh + sw * ew);
        fH[w] = eh * inv;
        fW[w] = ew * inv;
    }
    for (int idx = tid; idx < 256 * 32; idx += 512)
        Wzs[idx] = Wz[idx];
    __syncthreads();

    for (int idx = tid; idx < 32 * 128; idx += 512) {
        int c = idx >> 7, w = idx & 127;
        size_t off = (size_t)(b * CR_ + c) * HW_ + (size_t)h * W_ + w;
        mg[c * 130 + w] = g_oHt[off] * fH[w] + g_oW[off] * fW[w];
    }
    __syncthreads();

    ull acc[16][2];
#pragma unroll
    for (int j = 0; j < 16; j++) { acc[j][0] = 0ull; acc[j][1] = 0ull; }

#pragma unroll 4
    for (int c = 0; c < 32; c++) {
        ull m0 = ldpair(&mg[c * 130 + 2 * lane]);
        ull m1 = ldpair(&mg[c * 130 + 2 * lane + 64]);
#pragma unroll
        for (int j = 0; j < 16; j++) {
            ull wv = splat2(Wzs[(wp + 16 * j) * 32 + c]);
            acc[j][0] = fma2(wv, m0, acc[j][0]);
            acc[j][1] = fma2(wv, m1, acc[j][1]);
        }
    }

#pragma unroll
    for (int j = 0; j < 16; j++) {
        int o = wp + 16 * j;
        float bias = bz[o];
        size_t obase = ((size_t)(b * C_ + o) * H_ + h) * W_;
#pragma unroll
        for (int u = 0; u < 2; u++) {
            int w = 2 * lane + 64 * u;
            float2 xv = *reinterpret_cast<const float2*>(&x[obase + w]);
            float2 a  = unpack2(acc[j][u]);
            a.x += bias + xv.x;
            a.y += bias + xv.y;
            *reinterpret_cast<float2*>(&out[obase + w]) = a;
        }
    }
}

// ---------------- launch ------------------------------------------------------
extern "C" void kernel_launch(void* const* d_in, const int* in_sizes, int n_in,
                              void* d_out, int out_size)
{
    const float* x  = (const float*)d_in[0];
    const float* Wq = (const float*)d_in[1];
    const float* bq = (const float*)d_in[2];
    const float* Wk = (const float*)d_in[3];
    const float* bk = (const float*)d_in[4];
    const float* Wv = (const float*)d_in[5];
    const float* bv = (const float*)d_in[6];
    const float* Wz = (const float*)d_in[7];
    const float* bz = (const float*)d_in[8];
    float* out = (float*)d_out;

    cudaFuncSetAttribute(proj_mma_kernel, cudaFuncAttributeMaxDynamicSharedMemorySize, PROJ_SMEM);
    cudaFuncSetAttribute(attn_kernel,     cudaFuncAttributeMaxDynamicSharedMemorySize, ATTN_SMEM);
    cudaFuncSetAttribute(combine_kernel,  cudaFuncAttributeMaxDynamicSharedMemorySize, COMB_SMEM);

    proj_mma_kernel<<<dim3(H_, B_), 256, PROJ_SMEM>>>(x, Wq, bq, Wk, bk, Wv, bv);
    transpose_kernel<<<dim3(4, 4, 3 * 256), dim3(32, 8)>>>(0);   // q,k,v -> qt,kt,vt
    attn_kernel<<<dim3(128, B_, 2), 256, ATTN_SMEM>>>();         // H + W paths merged
    transpose_kernel<<<dim3(4, 4, 256), dim3(32, 8)>>>(3);       // oH -> oHt
    combine_kernel<<<dim3(H_, B_), 512, COMB_SMEM>>>(x, Wz, bz, out);
}

// round 11
// speedup vs baseline: 1.5849x; 1.2087x over previous
#include <cuda_runtime.h>

typedef unsigned long long ull;
typedef unsigned int uint_;

#define B_   8
#define C_   256
#define H_   128
#define W_   128
#define CR_  32
#define HW_  (H_ * W_)

// ---------------- scratch (device globals; no runtime allocation) -------------
__device__ float g_q  [B_ * CR_ * HW_];   // (b, cr, h, w)
__device__ float g_k  [B_ * CR_ * HW_];
__device__ float g_v  [B_ * CR_ * HW_];
__device__ float g_qt [B_ * CR_ * HW_];   // (b, cr, w, h)
__device__ float g_kt [B_ * CR_ * HW_];
__device__ float g_vt [B_ * CR_ * HW_];
__device__ float g_oH [B_ * CR_ * HW_];   // (b, cr, w, h)
__device__ float g_oHt[B_ * CR_ * HW_];   // (b, cr, h, w)
__device__ float g_oW [B_ * CR_ * HW_];   // (b, cr, h, w)
__device__ float g_mH [B_ * HW_];
__device__ float g_sH [B_ * HW_];
__device__ float g_mW [B_ * HW_];
__device__ float g_sW [B_ * HW_];

// ---------------- packed f32x2 helpers ---------------------------------------
__device__ __forceinline__ ull fma2(ull a, ull b, ull c) {
    ull d;
    asm("fma.rn.f32x2 %0, %1, %2, %3;" : "=l"(d) : "l"(a), "l"(b), "l"(c));
    return d;
}
__device__ __forceinline__ ull splat2(float f) {
    ull r; uint_ u = __float_as_uint(f);
    asm("mov.b64 %0, {%1, %1};" : "=l"(r) : "r"(u));
    return r;
}
__device__ __forceinline__ float2 unpack2(ull u) {
    uint_ lo, hi;
    asm("mov.b64 {%0, %1}, %2;" : "=r"(lo), "=r"(hi) : "l"(u));
    return make_float2(__uint_as_float(lo), __uint_as_float(hi));
}
__device__ __forceinline__ ull ldpair(const float* p) {
    union { float2 f2; ull u; } t;
    t.f2 = *reinterpret_cast<const float2*>(p);
    return t.u;
}

// bf16 hi/lo split: hi2/lo2 pack (elem0 -> low half, elem1 -> high half)
__device__ __forceinline__ void split_bf16(float x0, float x1, uint_& hi2, uint_& lo2) {
    asm("cvt.rn.satfinite.bf16x2.f32 %0, %1, %2;" : "=r"(hi2) : "f"(x1), "f"(x0));
    float h0 = __uint_as_float(hi2 << 16);
    float h1 = __uint_as_float(hi2 & 0xffff0000u);
    float l0 = x0 - h0, l1 = x1 - h1;
    asm("cvt.rn.satfinite.bf16x2.f32 %0, %1, %2;" : "=r"(lo2) : "f"(l1), "f"(l0));
}

// warp-level bf16 MMA: D(16x8,f32) += A(16x16,bf16 row) * B(16x8,bf16 col)
__device__ __forceinline__ void mma_bf16(float* d, const uint_* a, const uint_* b) {
    asm volatile(
        "mma.sync.aligned.m16n8k16.row.col.f32.bf16.bf16.f32 "
        "{%0,%1,%2,%3}, {%4,%5,%6,%7}, {%8,%9}, {%0,%1,%2,%3};"
        : "+f"(d[0]), "+f"(d[1]), "+f"(d[2]), "+f"(d[3])
        : "r"(a[0]), "r"(a[1]), "r"(a[2]), "r"(a[3]), "r"(b[0]), "r"(b[1]));
}

// ---------------- kernel 1: q/k/v projection via mma.sync bf16-split ----------
#define PJ_WPH   0
#define PJ_WPL   (96 * 36)
#define PJ_XPH   (2 * 96 * 36)
#define PJ_XPL   (2 * 96 * 36 + 32 * 136)
#define PJ_BIAS  (2 * 96 * 36 + 2 * 32 * 136)
#define PROJ_SMEM ((2 * 96 * 36 + 2 * 32 * 136 + 96) * 4)

__global__ void __launch_bounds__(256, 2) proj_mma_kernel(
    const float* __restrict__ x,
    const float* __restrict__ Wq, const float* __restrict__ bq,
    const float* __restrict__ Wk, const float* __restrict__ bk,
    const float* __restrict__ Wv, const float* __restrict__ bv)
{
    extern __shared__ uint_ ps[];
    uint_* Wph = ps + PJ_WPH;
    uint_* Wpl = ps + PJ_WPL;
    uint_* Xph = ps + PJ_XPH;
    uint_* Xpl = ps + PJ_XPL;
    float* bsm = reinterpret_cast<float*>(ps + PJ_BIAS);

    int h = blockIdx.x, b = blockIdx.y;
    int tid = threadIdx.x;
    int wid = tid >> 5, lane = tid & 31;
    int g = lane >> 2, tg = lane & 3;
    int wm = wid >> 2, wn = wid & 3;
    int m0 = wm * 48, n0 = wn * 32;

    if (tid < 96) {
        float bv_;
        if (tid < 32)      bv_ = bq[tid];
        else if (tid < 64) bv_ = bk[tid - 32];
        else               bv_ = bv[tid - 64];
        bsm[tid] = bv_;
    }

    const float* xb = x + (size_t)b * C_ * HW_ + (size_t)h * W_;

    float acc[3][4][4];
#pragma unroll
    for (int mt = 0; mt < 3; mt++)
#pragma unroll
        for (int nt = 0; nt < 4; nt++)
#pragma unroll
            for (int u = 0; u < 4; u++) acc[mt][nt][u] = 0.f;

    int pixld = tid & 127, halfld = tid >> 7;

    for (int kc = 0; kc < 4; kc++) {
        if (kc) __syncthreads();
        for (int idx = tid; idx < 96 * 32; idx += 256) {
            int r = idx >> 5, kp = idx & 31;
            const float* wsrc;
            if (r < 32)      wsrc = Wq + (size_t)r * C_;
            else if (r < 64) wsrc = Wk + (size_t)(r - 32) * C_;
            else             wsrc = Wv + (size_t)(r - 64) * C_;
            float w0 = wsrc[kc * 64 + 2 * kp];
            float w1 = wsrc[kc * 64 + 2 * kp + 1];
            uint_ hi2, lo2;
            split_bf16(w0, w1, hi2, lo2);
            Wph[r * 36 + kp] = hi2;
            Wpl[r * 36 + kp] = lo2;
        }
#pragma unroll 4
        for (int kp2 = 0; kp2 < 16; kp2++) {
            int kp = kp2 * 2 + halfld;
            int c = kc * 64 + 2 * kp;
            float x0 = xb[(size_t)c * HW_ + pixld];
            float x1 = xb[(size_t)(c + 1) * HW_ + pixld];
            uint_ hi2, lo2;
            split_bf16(x0, x1, hi2, lo2);
            Xph[kp * 136 + pixld] = hi2;
            Xpl[kp * 136 + pixld] = lo2;
        }
        __syncthreads();

#pragma unroll
        for (int ks = 0; ks < 4; ks++) {
            int kpb = ks * 8;
            uint_ bh[4][2], bl[4][2];
#pragma unroll
            for (int nt = 0; nt < 4; nt++) {
                int n = n0 + nt * 8 + g;
                bh[nt][0] = Xph[(kpb + tg) * 136 + n];
                bh[nt][1] = Xph[(kpb + tg + 4) * 136 + n];
                bl[nt][0] = Xpl[(kpb + tg) * 136 + n];
                bl[nt][1] = Xpl[(kpb + tg + 4) * 136 + n];
            }
#pragma unroll
            for (int mt = 0; mt < 3; mt++) {
                int m = m0 + mt * 16 + g;
                uint_ ah[4], al[4];
                ah[0] = Wph[m * 36 + kpb + tg];
                ah[1] = Wph[(m + 8) * 36 + kpb + tg];
                ah[2] = Wph[m * 36 + kpb + tg + 4];
                ah[3] = Wph[(m + 8) * 36 + kpb + tg + 4];
                al[0] = Wpl[m * 36 + kpb + tg];
                al[1] = Wpl[(m + 8) * 36 + kpb + tg];
                al[2] = Wpl[m * 36 + kpb + tg + 4];
                al[3] = Wpl[(m + 8) * 36 + kpb + tg + 4];
#pragma unroll
                for (int nt = 0; nt < 4; nt++) {
                    mma_bf16(acc[mt][nt], ah, bh[nt]);
                    mma_bf16(acc[mt][nt], ah, bl[nt]);
                    mma_bf16(acc[mt][nt], al, bh[nt]);
                }
            }
        }
    }

#pragma unroll
    for (int mt = 0; mt < 3; mt++) {
#pragma unroll
        for (int half = 0; half < 2; half++) {
            int r = m0 + mt * 16 + g + 8 * half;
            float bias = bsm[r];
            float* dstb;
            int ch;
            if (r < 32)      { dstb = g_q; ch = r; }
            else if (r < 64) { dstb = g_k; ch = r - 32; }
            else             { dstb = g_v; ch = r - 64; }
            float* drow = dstb + ((size_t)(b * CR_ + ch) * H_ + h) * W_;
#pragma unroll
            for (int nt = 0; nt < 4; nt++) {
                int pix = n0 + nt * 8 + 2 * tg;
                float2 v;
                v.x = acc[mt][nt][2 * half]     + bias;
                v.y = acc[mt][nt][2 * half + 1] + bias;
                *reinterpret_cast<float2*>(&drow[pix]) = v;
            }
        }
    }
}

// ---------------- kernel 2: HxW tile transpose --------------------------------
__global__ void __launch_bounds__(256) transpose_kernel(int base_arr)
{
    __shared__ float tile[32][33];
    int zc = blockIdx.z;
    int arr = base_arr + (zc >> 8), m = zc & 255;
    const float* src; float* dst;
    if      (arr == 0) { src = g_q;  dst = g_qt;  }
    else if (arr == 1) { src = g_k;  dst = g_kt;  }
    else if (arr == 2) { src = g_v;  dst = g_vt;  }
    else               { src = g_oH; dst = g_oHt; }
    src += (size_t)m * HW_;
    dst += (size_t)m * HW_;
    int x0 = blockIdx.x * 32, y0 = blockIdx.y * 32;
    int tx = threadIdx.x, ty = threadIdx.y;
#pragma unroll
    for (int r = 0; r < 32; r += 8)
        tile[ty + r][tx] = src[(size_t)(y0 + ty + r) * W_ + x0 + tx];
    __syncthreads();
#pragma unroll
    for (int r = 0; r < 32; r += 8)
        dst[(size_t)(x0 + ty + r) * H_ + y0 + tx] = tile[tx][ty + r];
}

// ---------------- kernel 3: HMMA attention (register-resident P) --------------
// grid (128, B), 256 threads (8 warps). Warp w owns E rows 16w..16w+15.
// smem (uint units): Qph[128][17], Qpl[128][17], Kph[16][132], Kpl[16][132],
//                    Vph[32][66], Vpl[32][66].  Total 51200 B -> 2 CTAs/SM (regs).
#define AQ_PH  0
#define AQ_PL  2176
#define AK_PH  4352
#define AK_PL  6464
#define AV_PH  8576
#define AV_PL  10688
#define ATTN_SMEM (12800 * 4)

__global__ void __launch_bounds__(256, 2) attn_kernel(int transposed)
{
    extern __shared__ uint_ su[];
    uint_* Qph = su + AQ_PH;
    uint_* Qpl = su + AQ_PL;
    uint_* Kph = su + AK_PH;
    uint_* Kpl = su + AK_PL;
    uint_* Vph = su + AV_PH;
    uint_* Vpl = su + AV_PL;
    float* stg = reinterpret_cast<float*>(su);   // 32x130, reuses Qp after gram

    const float* qin = transposed ? g_qt : g_q;
    const float* kin = transposed ? g_kt : g_k;
    const float* vin = transposed ? g_vt : g_v;
    float* outp  = transposed ? g_oH : g_oW;
    float* mstat = transposed ? g_mH : g_mW;
    float* sstat = transposed ? g_sH : g_sW;

    int X = blockIdx.x, b = blockIdx.y;
    size_t base = (size_t)b * CR_ * HW_ + (size_t)X * W_;
    int tid = threadIdx.x, warp = tid >> 5, lane = tid & 31;
    int g = lane >> 2, tg = lane & 3;

    // ---- load Q (row-major by pixel) and K (row-major by channel-pair) ----
    for (int idx = tid; idx < 16 * 128; idx += 256) {
        int e = idx & 127, cp = idx >> 7;
        float q0 = qin[base + (size_t)(2 * cp) * HW_ + e];
        float q1 = qin[base + (size_t)(2 * cp + 1) * HW_ + e];
        uint_ h2, l2;
        split_bf16(q0, q1, h2, l2);
        Qph[e * 17 + cp] = h2;
        Qpl[e * 17 + cp] = l2;
        float k0 = kin[base + (size_t)(2 * cp) * HW_ + e];
        float k1 = kin[base + (size_t)(2 * cp + 1) * HW_ + e];
        split_bf16(k0, k1, h2, l2);
        Kph[cp * 132 + e] = h2;
        Kpl[cp * 132 + e] = l2;
    }
    // ---- load V packed by i-pair: Vp[c][ip] ----
    for (int idx = tid; idx < 32 * 64; idx += 256) {
        int ip = idx & 63, c = idx >> 6;
        float2 v2 = *reinterpret_cast<const float2*>(&vin[base + (size_t)c * HW_ + 2 * ip]);
        uint_ h2, l2;
        split_bf16(v2.x, v2.y, h2, l2);
        Vph[c * 66 + ip] = h2;
        Vpl[c * 66 + ip] = l2;
    }
    __syncthreads();

    int r0 = warp * 16 + g;
    int r1 = r0 + 8;

    // ---- gram: E[r][i] = sum_c Q[c][r] * K[c][i]  (A = Q^T, B = K) ----
    float dE[16][4];
#pragma unroll
    for (int nt = 0; nt < 16; nt++)
#pragma unroll
        for (int u = 0; u < 4; u++) dE[nt][u] = 0.f;

#pragma unroll
    for (int ks = 0; ks < 2; ks++) {
        int kpb = ks * 8;
        uint_ ah[4], al[4];
        ah[0] = Qph[r0 * 17 + kpb + tg];
        ah[1] = Qph[r1 * 17 + kpb + tg];
        ah[2] = Qph[r0 * 17 + kpb + tg + 4];
        ah[3] = Qph[r1 * 17 + kpb + tg + 4];
        al[0] = Qpl[r0 * 17 + kpb + tg];
        al[1] = Qpl[r1 * 17 + kpb + tg];
        al[2] = Qpl[r0 * 17 + kpb + tg + 4];
        al[3] = Qpl[r1 * 17 + kpb + tg + 4];
#pragma unroll
        for (int nt = 0; nt < 16; nt++) {
            int n = nt * 8 + g;
            uint_ bh[2], bl[2];
            bh[0] = Kph[(kpb + tg) * 132 + n];
            bh[1] = Kph[(kpb + tg + 4) * 132 + n];
            bl[0] = Kpl[(kpb + tg) * 132 + n];
            bl[1] = Kpl[(kpb + tg + 4) * 132 + n];
            mma_bf16(dE[nt], ah, bh);
            mma_bf16(dE[nt], ah, bl);
            mma_bf16(dE[nt], al, bh);
        }
    }

    // ---- diagonal mask (H path) ----
    if (transposed) {
#pragma unroll
        for (int nt = 0; nt < 16; nt++) {
            int c0 = nt * 8 + 2 * tg, c1 = c0 + 1;
            if (c0 == r0) dE[nt][0] = -1e30f;
            if (c1 == r0) dE[nt][1] = -1e30f;
            if (c0 == r1) dE[nt][2] = -1e30f;
            if (c1 == r1) dE[nt][3] = -1e30f;
        }
    }

    // ---- softmax over each row (quad shuffle over tg lanes) ----
    float m0 = -1e30f, m1 = -1e30f;
#pragma unroll
    for (int nt = 0; nt < 16; nt++) {
        m0 = fmaxf(m0, fmaxf(dE[nt][0], dE[nt][1]));
        m1 = fmaxf(m1, fmaxf(dE[nt][2], dE[nt][3]));
    }
    m0 = fmaxf(m0, __shfl_xor_sync(0xffffffffu, m0, 1));
    m0 = fmaxf(m0, __shfl_xor_sync(0xffffffffu, m0, 2));
    m1 = fmaxf(m1, __shfl_xor_sync(0xffffffffu, m1, 1));
    m1 = fmaxf(m1, __shfl_xor_sync(0xffffffffu, m1, 2));

    float s0 = 0.f, s1 = 0.f;
#pragma unroll
    for (int nt = 0; nt < 16; nt++) {
        dE[nt][0] = __expf(dE[nt][0] - m0);
        dE[nt][1] = __expf(dE[nt][1] - m0);
        dE[nt][2] = __expf(dE[nt][2] - m1);
        dE[nt][3] = __expf(dE[nt][3] - m1);
        s0 += dE[nt][0] + dE[nt][1];
        s1 += dE[nt][2] + dE[nt][3];
    }
    s0 += __shfl_xor_sync(0xffffffffu, s0, 1);
    s0 += __shfl_xor_sync(0xffffffffu, s0, 2);
    s1 += __shfl_xor_sync(0xffffffffu, s1, 1);
    s1 += __shfl_xor_sync(0xffffffffu, s1, 2);

    if (tg == 0) {
        size_t s0i = transposed ? ((size_t)(b * H_ + r0) * W_ + X)
                                : ((size_t)(b * H_ + X) * W_ + r0);
        size_t s1i = transposed ? ((size_t)(b * H_ + r1) * W_ + X)
                                : ((size_t)(b * H_ + X) * W_ + r1);
        mstat[s0i] = m0;  sstat[s0i] = s0;
        mstat[s1i] = m1;  sstat[s1i] = s1;
    }

    // ---- aggregation: O[r][c] = sum_i P[r][i] * V[c][i]  (A = P, B = V^T) ----
    // P's D-fragment IS the A-fragment after bf16 convert (hi/lo split kept).
    float dO[4][4];
#pragma unroll
    for (int nt = 0; nt < 4; nt++)
#pragma unroll
        for (int u = 0; u < 4; u++) dO[nt][u] = 0.f;

#pragma unroll
    for (int kb = 0; kb < 8; kb++) {
        uint_ ah[4], al[4];
        split_bf16(dE[2 * kb][0],     dE[2 * kb][1],     ah[0], al[0]);
        split_bf16(dE[2 * kb][2],     dE[2 * kb][3],     ah[1], al[1]);
        split_bf16(dE[2 * kb + 1][0], dE[2 * kb + 1][1], ah[2], al[2]);
        split_bf16(dE[2 * kb + 1][2], dE[2 * kb + 1][3], ah[3], al[3]);
#pragma unroll
        for (int nt = 0; nt < 4; nt++) {
            int c = nt * 8 + g;
            uint_ bh[2], bl[2];
            bh[0] = Vph[c * 66 + 8 * kb + tg];
            bh[1] = Vph[c * 66 + 8 * kb + tg + 4];
            bl[0] = Vpl[c * 66 + 8 * kb + tg];
            bl[1] = Vpl[c * 66 + 8 * kb + tg + 4];
            mma_bf16(dO[nt], ah, bh);
            mma_bf16(dO[nt], ah, bl);
            mma_bf16(dO[nt], al, bh);
        }
    }

    // ---- stage [c][r] then coalesced global write ----
    __syncthreads();
#pragma unroll
    for (int nt = 0; nt < 4; nt++) {
        int c0 = nt * 8 + 2 * tg;
        stg[c0 * 130 + r0]       = dO[nt][0];
        stg[(c0 + 1) * 130 + r0] = dO[nt][1];
        stg[c0 * 130 + r1]       = dO[nt][2];
        stg[(c0 + 1) * 130 + r1] = dO[nt][3];
    }
    __syncthreads();
    for (int idx = tid; idx < CR_ * 128; idx += 256) {
        int c = idx >> 7, e = idx & 127;
        outp[base + (size_t)c * HW_ + e] = stg[c * 130 + e];
    }
}

// ---------------- kernel 4: softmax merge + Wz conv + bias + residual --------
#define COMB_SMEM ((32 * 130 + 256 * 32 + 256) * 4)

__global__ void __launch_bounds__(512) combine_kernel(
    const float* __restrict__ x, const float* __restrict__ Wz,
    const float* __restrict__ bz, float* __restrict__ out)
{
    extern __shared__ float sm[];
    float* mg  = sm;                        // 32 x 130
    float* Wzs = sm + 32 * 130;             // 256 x 32
    float* fH  = sm + 32 * 130 + 256 * 32;  // 128
    float* fW  = fH + 128;                  // 128

    int h = blockIdx.x, b = blockIdx.y;
    int tid = threadIdx.x, wp = tid >> 5, lane = tid & 31;

    if (tid < 128) {
        int w = tid;
        size_t sidx = (size_t)(b * H_ + h) * W_ + w;
        float mh = g_mH[sidx], mw = g_mW[sidx];
        float sh = g_sH[sidx], sw = g_sW[sidx];
        float m  = fmaxf(mh, mw);
        float eh = __expf(mh - m), ew = __expf(mw - m);
        float inv = 1.0f / (sh * eh + sw * ew);
        fH[w] = eh * inv;
        fW[w] = ew * inv;
    }
    for (int idx = tid; idx < 256 * 32; idx += 512)
        Wzs[idx] = Wz[idx];
    __syncthreads();

    for (int idx = tid; idx < 32 * 128; idx += 512) {
        int c = idx >> 7, w = idx & 127;
        size_t off = (size_t)(b * CR_ + c) * HW_ + (size_t)h * W_ + w;
        mg[c * 130 + w] = g_oHt[off] * fH[w] + g_oW[off] * fW[w];
    }
    __syncthreads();

    ull acc[16][2];
#pragma unroll
    for (int j = 0; j < 16; j++) { acc[j][0] = 0ull; acc[j][1] = 0ull; }

#pragma unroll 4
    for (int c = 0; c < 32; c++) {
        ull m0 = ldpair(&mg[c * 130 + 2 * lane]);
        ull m1 = ldpair(&mg[c * 130 + 2 * lane + 64]);
#pragma unroll
        for (int j = 0; j < 16; j++) {
            ull wv = splat2(Wzs[(wp + 16 * j) * 32 + c]);
            acc[j][0] = fma2(wv, m0, acc[j][0]);
            acc[j][1] = fma2(wv, m1, acc[j][1]);
        }
    }

#pragma unroll
    for (int j = 0; j < 16; j++) {
        int o = wp + 16 * j;
        float bias = bz[o];
        size_t obase = ((size_t)(b * C_ + o) * H_ + h) * W_;
#pragma unroll
        for (int u = 0; u < 2; u++) {
            int w = 2 * lane + 64 * u;
            float2 xv = *reinterpret_cast<const float2*>(&x[obase + w]);
            float2 a  = unpack2(acc[j][u]);
            a.x += bias + xv.x;
            a.y += bias + xv.y;
            *reinterpret_cast<float2*>(&out[obase + w]) = a;
        }
    }
}

// ---------------- launch ------------------------------------------------------
extern "C" void kernel_launch(void* const* d_in, const int* in_sizes, int n_in,
                              void* d_out, int out_size)
{
    const float* x  = (const float*)d_in[0];
    const float* Wq = (const float*)d_in[1];
    const float* bq = (const float*)d_in[2];
    const float* Wk = (const float*)d_in[3];
    const float* bk = (const float*)d_in[4];
    const float* Wv = (const float*)d_in[5];
    const float* bv = (const float*)d_in[6];
    const float* Wz = (const float*)d_in[7];
    const float* bz = (const float*)d_in[8];
    float* out = (float*)d_out;

    cudaFuncSetAttribute(proj_mma_kernel, cudaFuncAttributeMaxDynamicSharedMemorySize, PROJ_SMEM);
    cudaFuncSetAttribute(attn_kernel,     cudaFuncAttributeMaxDynamicSharedMemorySize, ATTN_SMEM);
    cudaFuncSetAttribute(combine_kernel,  cudaFuncAttributeMaxDynamicSharedMemorySize, COMB_SMEM);

    proj_mma_kernel<<<dim3(H_, B_), 256, PROJ_SMEM>>>(x, Wq, bq, Wk, bk, Wv, bv);
    transpose_kernel<<<dim3(4, 4, 3 * 256), dim3(32, 8)>>>(0);   // q,k,v -> qt,kt,vt
    attn_kernel<<<dim3(W_, B_), 256, ATTN_SMEM>>>(1);            // H path
    attn_kernel<<<dim3(H_, B_), 256, ATTN_SMEM>>>(0);            // W path
    transpose_kernel<<<dim3(4, 4, 256), dim3(32, 8)>>>(3);       // oH -> oHt
    combine_kernel<<<dim3(H_, B_), 512, COMB_SMEM>>>(x, Wz, bz, out);
}

// round 12
// speedup vs baseline: 1.9111x; 1.2058x over previous
#include <cuda_runtime.h>

typedef unsigned long long ull;
typedef unsigned int uint_;

#define B_   8
#define C_   256
#define H_   128
#define W_   128
#define CR_  32
#define HW_  (H_ * W_)

// ---------------- scratch (device globals; no runtime allocation) -------------
__device__ float g_q  [B_ * CR_ * HW_];   // (b, cr, h, w)
__device__ float g_k  [B_ * CR_ * HW_];
__device__ float g_v  [B_ * CR_ * HW_];
__device__ float g_qt [B_ * CR_ * HW_];   // (b, cr, w, h)
__device__ float g_kt [B_ * CR_ * HW_];
__device__ float g_vt [B_ * CR_ * HW_];
__device__ float g_oH [B_ * CR_ * HW_];   // (b, cr, w, h)
__device__ float g_oHt[B_ * CR_ * HW_];   // (b, cr, h, w)
__device__ float g_oW [B_ * CR_ * HW_];   // (b, cr, h, w)
__device__ float g_mH [B_ * HW_];
__device__ float g_sH [B_ * HW_];
__device__ float g_mW [B_ * HW_];
__device__ float g_sW [B_ * HW_];

// ---------------- packed f32x2 helpers ---------------------------------------
__device__ __forceinline__ ull fma2(ull a, ull b, ull c) {
    ull d;
    asm("fma.rn.f32x2 %0, %1, %2, %3;" : "=l"(d) : "l"(a), "l"(b), "l"(c));
    return d;
}
__device__ __forceinline__ ull splat2(float f) {
    ull r; uint_ u = __float_as_uint(f);
    asm("mov.b64 %0, {%1, %1};" : "=l"(r) : "r"(u));
    return r;
}
__device__ __forceinline__ float2 unpack2(ull u) {
    uint_ lo, hi;
    asm("mov.b64 {%0, %1}, %2;" : "=r"(lo), "=r"(hi) : "l"(u));
    return make_float2(__uint_as_float(lo), __uint_as_float(hi));
}
__device__ __forceinline__ ull ldpair(const float* p) {
    union { float2 f2; ull u; } t;
    t.f2 = *reinterpret_cast<const float2*>(p);
    return t.u;
}

// bf16 hi/lo split: hi2/lo2 pack (elem0 -> low half, elem1 -> high half)
__device__ __forceinline__ void split_bf16(float x0, float x1, uint_& hi2, uint_& lo2) {
    asm("cvt.rn.satfinite.bf16x2.f32 %0, %1, %2;" : "=r"(hi2) : "f"(x1), "f"(x0));
    float h0 = __uint_as_float(hi2 << 16);
    float h1 = __uint_as_float(hi2 & 0xffff0000u);
    float l0 = x0 - h0, l1 = x1 - h1;
    asm("cvt.rn.satfinite.bf16x2.f32 %0, %1, %2;" : "=r"(lo2) : "f"(l1), "f"(l0));
}

// warp-level bf16 MMA: D(16x8,f32) += A(16x16,bf16 row) * B(16x8,bf16 col)
__device__ __forceinline__ void mma_bf16(float* d, const uint_* a, const uint_* b) {
    asm volatile(
        "mma.sync.aligned.m16n8k16.row.col.f32.bf16.bf16.f32 "
        "{%0,%1,%2,%3}, {%4,%5,%6,%7}, {%8,%9}, {%0,%1,%2,%3};"
        : "+f"(d[0]), "+f"(d[1]), "+f"(d[2]), "+f"(d[3])
        : "r"(a[0]), "r"(a[1]), "r"(a[2]), "r"(a[3]), "r"(b[0]), "r"(b[1]));
}

// ---------------- kernel 1: q/k/v projection via mma.sync bf16-split ----------
// grid (H, B), 256 threads. Vectorized float4 streaming of x.
#define PJ_WPH   0
#define PJ_WPL   (96 * 36)
#define PJ_XPH   (2 * 96 * 36)
#define PJ_XPL   (2 * 96 * 36 + 32 * 136)
#define PJ_BIAS  (2 * 96 * 36 + 2 * 32 * 136)
#define PROJ_SMEM ((2 * 96 * 36 + 2 * 32 * 136 + 96) * 4)

__global__ void __launch_bounds__(256, 2) proj_mma_kernel(
    const float* __restrict__ x,
    const float* __restrict__ Wq, const float* __restrict__ bq,
    const float* __restrict__ Wk, const float* __restrict__ bk,
    const float* __restrict__ Wv, const float* __restrict__ bv)
{
    extern __shared__ uint_ ps[];
    uint_* Wph = ps + PJ_WPH;
    uint_* Wpl = ps + PJ_WPL;
    uint_* Xph = ps + PJ_XPH;
    uint_* Xpl = ps + PJ_XPL;
    float* bsm = reinterpret_cast<float*>(ps + PJ_BIAS);

    int h = blockIdx.x, b = blockIdx.y;
    int tid = threadIdx.x;
    int wid = tid >> 5, lane = tid & 31;
    int g = lane >> 2, tg = lane & 3;
    int wm = wid >> 2, wn = wid & 3;
    int m0 = wm * 48, n0 = wn * 32;

    if (tid < 96) {
        float bv_;
        if (tid < 32)      bv_ = bq[tid];
        else if (tid < 64) bv_ = bk[tid - 32];
        else               bv_ = bv[tid - 64];
        bsm[tid] = bv_;
    }

    const float* xb = x + (size_t)b * C_ * HW_ + (size_t)h * W_;

    float acc[3][4][4];
#pragma unroll
    for (int mt = 0; mt < 3; mt++)
#pragma unroll
        for (int nt = 0; nt < 4; nt++)
#pragma unroll
            for (int u = 0; u < 4; u++) acc[mt][nt][u] = 0.f;

    int cpld = tid >> 3;           // 0..31 channel-pair
    int pbld = (tid & 7) * 16;     // pixel strip base

    for (int kc = 0; kc < 4; kc++) {
        if (kc) __syncthreads();
        // ---- weights chunk: 96 rows x 16 float4 ----
        for (int idx = tid; idx < 96 * 16; idx += 256) {
            int r = idx >> 4, f4 = idx & 15;
            const float* wsrc;
            if (r < 32)      wsrc = Wq + (size_t)r * C_;
            else if (r < 64) wsrc = Wk + (size_t)(r - 32) * C_;
            else             wsrc = Wv + (size_t)(r - 64) * C_;
            float4 w4 = *reinterpret_cast<const float4*>(&wsrc[kc * 64 + 4 * f4]);
            uint_ h0, l0, h1, l1;
            split_bf16(w4.x, w4.y, h0, l0);
            split_bf16(w4.z, w4.w, h1, l1);
            Wph[r * 36 + 2 * f4]     = h0;
            Wph[r * 36 + 2 * f4 + 1] = h1;
            Wpl[r * 36 + 2 * f4]     = l0;
            Wpl[r * 36 + 2 * f4 + 1] = l1;
        }
        // ---- x chunk: channel-pair cpld, 16-pixel strip, float4 loads ----
        {
            const float* x0p = xb + (size_t)(kc * 64 + 2 * cpld) * HW_;
            const float* x1p = x0p + HW_;
#pragma unroll
            for (int it = 0; it < 4; it++) {
                int p = pbld + 4 * it;
                float4 a4 = *reinterpret_cast<const float4*>(&x0p[p]);
                float4 b4 = *reinterpret_cast<const float4*>(&x1p[p]);
                uint_ hh[4], ll[4];
                split_bf16(a4.x, b4.x, hh[0], ll[0]);
                split_bf16(a4.y, b4.y, hh[1], ll[1]);
                split_bf16(a4.z, b4.z, hh[2], ll[2]);
                split_bf16(a4.w, b4.w, hh[3], ll[3]);
                *reinterpret_cast<uint4*>(&Xph[cpld * 136 + p]) =
                    make_uint4(hh[0], hh[1], hh[2], hh[3]);
                *reinterpret_cast<uint4*>(&Xpl[cpld * 136 + p]) =
                    make_uint4(ll[0], ll[1], ll[2], ll[3]);
            }
        }
        __syncthreads();

#pragma unroll
        for (int ks = 0; ks < 4; ks++) {
            int kpb = ks * 8;
            uint_ bh[4][2], bl[4][2];
#pragma unroll
            for (int nt = 0; nt < 4; nt++) {
                int n = n0 + nt * 8 + g;
                bh[nt][0] = Xph[(kpb + tg) * 136 + n];
                bh[nt][1] = Xph[(kpb + tg + 4) * 136 + n];
                bl[nt][0] = Xpl[(kpb + tg) * 136 + n];
                bl[nt][1] = Xpl[(kpb + tg + 4) * 136 + n];
            }
#pragma unroll
            for (int mt = 0; mt < 3; mt++) {
                int m = m0 + mt * 16 + g;
                uint_ ah[4], al[4];
                ah[0] = Wph[m * 36 + kpb + tg];
                ah[1] = Wph[(m + 8) * 36 + kpb + tg];
                ah[2] = Wph[m * 36 + kpb + tg + 4];
                ah[3] = Wph[(m + 8) * 36 + kpb + tg + 4];
                al[0] = Wpl[m * 36 + kpb + tg];
                al[1] = Wpl[(m + 8) * 36 + kpb + tg];
                al[2] = Wpl[m * 36 + kpb + tg + 4];
                al[3] = Wpl[(m + 8) * 36 + kpb + tg + 4];
#pragma unroll
                for (int nt = 0; nt < 4; nt++) {
                    mma_bf16(acc[mt][nt], ah, bh[nt]);
                    mma_bf16(acc[mt][nt], ah, bl[nt]);
                    mma_bf16(acc[mt][nt], al, bh[nt]);
                }
            }
        }
    }

#pragma unroll
    for (int mt = 0; mt < 3; mt++) {
#pragma unroll
        for (int half = 0; half < 2; half++) {
            int r = m0 + mt * 16 + g + 8 * half;
            float bias = bsm[r];
            float* dstb;
            int ch;
            if (r < 32)      { dstb = g_q; ch = r; }
            else if (r < 64) { dstb = g_k; ch = r - 32; }
            else             { dstb = g_v; ch = r - 64; }
            float* drow = dstb + ((size_t)(b * CR_ + ch) * H_ + h) * W_;
#pragma unroll
            for (int nt = 0; nt < 4; nt++) {
                int pix = n0 + nt * 8 + 2 * tg;
                float2 v;
                v.x = acc[mt][nt][2 * half]     + bias;
                v.y = acc[mt][nt][2 * half + 1] + bias;
                *reinterpret_cast<float2*>(&drow[pix]) = v;
            }
        }
    }
}

// ---------------- kernel 2: HxW tile transpose --------------------------------
__global__ void __launch_bounds__(256) transpose_kernel(int base_arr)
{
    __shared__ float tile[32][33];
    int zc = blockIdx.z;
    int arr = base_arr + (zc >> 8), m = zc & 255;
    const float* src; float* dst;
    if      (arr == 0) { src = g_q;  dst = g_qt;  }
    else if (arr == 1) { src = g_k;  dst = g_kt;  }
    else if (arr == 2) { src = g_v;  dst = g_vt;  }
    else               { src = g_oH; dst = g_oHt; }
    src += (size_t)m * HW_;
    dst += (size_t)m * HW_;
    int x0 = blockIdx.x * 32, y0 = blockIdx.y * 32;
    int tx = threadIdx.x, ty = threadIdx.y;
#pragma unroll
    for (int r = 0; r < 32; r += 8)
        tile[ty + r][tx] = src[(size_t)(y0 + ty + r) * W_ + x0 + tx];
    __syncthreads();
#pragma unroll
    for (int r = 0; r < 32; r += 8)
        dst[(size_t)(x0 + ty + r) * H_ + y0 + tx] = tile[tx][ty + r];
}

// ---------------- kernel 3: HMMA attention (round-11, unchanged) --------------
#define AQ_PH  0
#define AQ_PL  2176
#define AK_PH  4352
#define AK_PL  6464
#define AV_PH  8576
#define AV_PL  10688
#define ATTN_SMEM (12800 * 4)

__global__ void __launch_bounds__(256, 2) attn_kernel(int transposed)
{
    extern __shared__ uint_ su[];
    uint_* Qph = su + AQ_PH;
    uint_* Qpl = su + AQ_PL;
    uint_* Kph = su + AK_PH;
    uint_* Kpl = su + AK_PL;
    uint_* Vph = su + AV_PH;
    uint_* Vpl = su + AV_PL;
    float* stg = reinterpret_cast<float*>(su);

    const float* qin = transposed ? g_qt : g_q;
    const float* kin = transposed ? g_kt : g_k;
    const float* vin = transposed ? g_vt : g_v;
    float* outp  = transposed ? g_oH : g_oW;
    float* mstat = transposed ? g_mH : g_mW;
    float* sstat = transposed ? g_sH : g_sW;

    int X = blockIdx.x, b = blockIdx.y;
    size_t base = (size_t)b * CR_ * HW_ + (size_t)X * W_;
    int tid = threadIdx.x, warp = tid >> 5, lane = tid & 31;
    int g = lane >> 2, tg = lane & 3;

    for (int idx = tid; idx < 16 * 128; idx += 256) {
        int e = idx & 127, cp = idx >> 7;
        float q0 = qin[base + (size_t)(2 * cp) * HW_ + e];
        float q1 = qin[base + (size_t)(2 * cp + 1) * HW_ + e];
        uint_ h2, l2;
        split_bf16(q0, q1, h2, l2);
        Qph[e * 17 + cp] = h2;
        Qpl[e * 17 + cp] = l2;
        float k0 = kin[base + (size_t)(2 * cp) * HW_ + e];
        float k1 = kin[base + (size_t)(2 * cp + 1) * HW_ + e];
        split_bf16(k0, k1, h2, l2);
        Kph[cp * 132 + e] = h2;
        Kpl[cp * 132 + e] = l2;
    }
    for (int idx = tid; idx < 32 * 64; idx += 256) {
        int ip = idx & 63, c = idx >> 6;
        float2 v2 = *reinterpret_cast<const float2*>(&vin[base + (size_t)c * HW_ + 2 * ip]);
        uint_ h2, l2;
        split_bf16(v2.x, v2.y, h2, l2);
        Vph[c * 66 + ip] = h2;
        Vpl[c * 66 + ip] = l2;
    }
    __syncthreads();

    int r0 = warp * 16 + g;
    int r1 = r0 + 8;

    float dE[16][4];
#pragma unroll
    for (int nt = 0; nt < 16; nt++)
#pragma unroll
        for (int u = 0; u < 4; u++) dE[nt][u] = 0.f;

#pragma unroll
    for (int ks = 0; ks < 2; ks++) {
        int kpb = ks * 8;
        uint_ ah[4], al[4];
        ah[0] = Qph[r0 * 17 + kpb + tg];
        ah[1] = Qph[r1 * 17 + kpb + tg];
        ah[2] = Qph[r0 * 17 + kpb + tg + 4];
        ah[3] = Qph[r1 * 17 + kpb + tg + 4];
        al[0] = Qpl[r0 * 17 + kpb + tg];
        al[1] = Qpl[r1 * 17 + kpb + tg];
        al[2] = Qpl[r0 * 17 + kpb + tg + 4];
        al[3] = Qpl[r1 * 17 + kpb + tg + 4];
#pragma unroll
        for (int nt = 0; nt < 16; nt++) {
            int n = nt * 8 + g;
            uint_ bh[2], bl[2];
            bh[0] = Kph[(kpb + tg) * 132 + n];
            bh[1] = Kph[(kpb + tg + 4) * 132 + n];
            bl[0] = Kpl[(kpb + tg) * 132 + n];
            bl[1] = Kpl[(kpb + tg + 4) * 132 + n];
            mma_bf16(dE[nt], ah, bh);
            mma_bf16(dE[nt], ah, bl);
            mma_bf16(dE[nt], al, bh);
        }
    }

    if (transposed) {
#pragma unroll
        for (int nt = 0; nt < 16; nt++) {
            int c0 = nt * 8 + 2 * tg, c1 = c0 + 1;
            if (c0 == r0) dE[nt][0] = -1e30f;
            if (c1 == r0) dE[nt][1] = -1e30f;
            if (c0 == r1) dE[nt][2] = -1e30f;
            if (c1 == r1) dE[nt][3] = -1e30f;
        }
    }

    float m0 = -1e30f, m1 = -1e30f;
#pragma unroll
    for (int nt = 0; nt < 16; nt++) {
        m0 = fmaxf(m0, fmaxf(dE[nt][0], dE[nt][1]));
        m1 = fmaxf(m1, fmaxf(dE[nt][2], dE[nt][3]));
    }
    m0 = fmaxf(m0, __shfl_xor_sync(0xffffffffu, m0, 1));
    m0 = fmaxf(m0, __shfl_xor_sync(0xffffffffu, m0, 2));
    m1 = fmaxf(m1, __shfl_xor_sync(0xffffffffu, m1, 1));
    m1 = fmaxf(m1, __shfl_xor_sync(0xffffffffu, m1, 2));

    float s0 = 0.f, s1 = 0.f;
#pragma unroll
    for (int nt = 0; nt < 16; nt++) {
        dE[nt][0] = __expf(dE[nt][0] - m0);
        dE[nt][1] = __expf(dE[nt][1] - m0);
        dE[nt][2] = __expf(dE[nt][2] - m1);
        dE[nt][3] = __expf(dE[nt][3] - m1);
        s0 += dE[nt][0] + dE[nt][1];
        s1 += dE[nt][2] + dE[nt][3];
    }
    s0 += __shfl_xor_sync(0xffffffffu, s0, 1);
    s0 += __shfl_xor_sync(0xffffffffu, s0, 2);
    s1 += __shfl_xor_sync(0xffffffffu, s1, 1);
    s1 += __shfl_xor_sync(0xffffffffu, s1, 2);

    if (tg == 0) {
        size_t s0i = transposed ? ((size_t)(b * H_ + r0) * W_ + X)
                                : ((size_t)(b * H_ + X) * W_ + r0);
        size_t s1i = transposed ? ((size_t)(b * H_ + r1) * W_ + X)
                                : ((size_t)(b * H_ + X) * W_ + r1);
        mstat[s0i] = m0;  sstat[s0i] = s0;
        mstat[s1i] = m1;  sstat[s1i] = s1;
    }

    float dO[4][4];
#pragma unroll
    for (int nt = 0; nt < 4; nt++)
#pragma unroll
        for (int u = 0; u < 4; u++) dO[nt][u] = 0.f;

#pragma unroll
    for (int kb = 0; kb < 8; kb++) {
        uint_ ah[4], al[4];
        split_bf16(dE[2 * kb][0],     dE[2 * kb][1],     ah[0], al[0]);
        split_bf16(dE[2 * kb][2],     dE[2 * kb][3],     ah[1], al[1]);
        split_bf16(dE[2 * kb + 1][0], dE[2 * kb + 1][1], ah[2], al[2]);
        split_bf16(dE[2 * kb + 1][2], dE[2 * kb + 1][3], ah[3], al[3]);
#pragma unroll
        for (int nt = 0; nt < 4; nt++) {
            int c = nt * 8 + g;
            uint_ bh[2], bl[2];
            bh[0] = Vph[c * 66 + 8 * kb + tg];
            bh[1] = Vph[c * 66 + 8 * kb + tg + 4];
            bl[0] = Vpl[c * 66 + 8 * kb + tg];
            bl[1] = Vpl[c * 66 + 8 * kb + tg + 4];
            mma_bf16(dO[nt], ah, bh);
            mma_bf16(dO[nt], ah, bl);
            mma_bf16(dO[nt], al, bh);
        }
    }

    __syncthreads();
#pragma unroll
    for (int nt = 0; nt < 4; nt++) {
        int c0 = nt * 8 + 2 * tg;
        stg[c0 * 130 + r0]       = dO[nt][0];
        stg[(c0 + 1) * 130 + r0] = dO[nt][1];
        stg[c0 * 130 + r1]       = dO[nt][2];
        stg[(c0 + 1) * 130 + r1] = dO[nt][3];
    }
    __syncthreads();
    for (int idx = tid; idx < CR_ * 128; idx += 256) {
        int c = idx >> 7, e = idx & 127;
        outp[base + (size_t)c * HW_ + e] = stg[c * 130 + e];
    }
}

// ---------------- kernel 4: combine, float4 streaming -------------------------
// grid (H, B), 512 threads. Lane owns pixels 4*lane..4*lane+3.
#define COMB_SMEM ((32 * 132 + 256 * 32 + 256) * 4)

__global__ void __launch_bounds__(512) combine_kernel(
    const float* __restrict__ x, const float* __restrict__ Wz,
    const float* __restrict__ bz, float* __restrict__ out)
{
    extern __shared__ float sm[];
    float* mg  = sm;                        // 32 x 132
    float* Wzs = sm + 32 * 132;             // 256 x 32
    float* fH  = sm + 32 * 132 + 256 * 32;  // 128
    float* fW  = fH + 128;                  // 128

    int h = blockIdx.x, b = blockIdx.y;
    int tid = threadIdx.x, wp = tid >> 5, lane = tid & 31;

    if (tid < 128) {
        int w = tid;
        size_t sidx = (size_t)(b * H_ + h) * W_ + w;
        float mh = g_mH[sidx], mw = g_mW[sidx];
        float sh = g_sH[sidx], sw = g_sW[sidx];
        float m  = fmaxf(mh, mw);
        float eh = __expf(mh - m), ew = __expf(mw - m);
        float inv = 1.0f / (sh * eh + sw * ew);
        fH[w] = eh * inv;
        fW[w] = ew * inv;
    }
    for (int idx = tid; idx < 256 * 32 / 4; idx += 512)
        *reinterpret_cast<float4*>(&Wzs[idx * 4]) =
            *reinterpret_cast<const float4*>(&Wz[idx * 4]);
    __syncthreads();

    for (int idx = tid; idx < 32 * 32; idx += 512) {
        int c = idx >> 5, w4 = (idx & 31) * 4;
        size_t off = (size_t)(b * CR_ + c) * HW_ + (size_t)h * W_ + w4;
        float4 oh = *reinterpret_cast<const float4*>(&g_oHt[off]);
        float4 ow = *reinterpret_cast<const float4*>(&g_oW[off]);
        float4 r;
        r.x = oh.x * fH[w4]     + ow.x * fW[w4];
        r.y = oh.y * fH[w4 + 1] + ow.y * fW[w4 + 1];
        r.z = oh.z * fH[w4 + 2] + ow.z * fW[w4 + 2];
        r.w = oh.w * fH[w4 + 3] + ow.w * fW[w4 + 3];
        *reinterpret_cast<float4*>(&mg[c * 132 + w4]) = r;
    }
    __syncthreads();

    ull acc[16][2];
#pragma unroll
    for (int j = 0; j < 16; j++) { acc[j][0] = 0ull; acc[j][1] = 0ull; }

#pragma unroll 4
    for (int c = 0; c < 32; c++) {
        ull m0 = ldpair(&mg[c * 132 + 4 * lane]);
        ull m1 = ldpair(&mg[c * 132 + 4 * lane + 2]);
#pragma unroll
        for (int j = 0; j < 16; j++) {
            ull wv = splat2(Wzs[(wp + 16 * j) * 32 + c]);
            acc[j][0] = fma2(wv, m0, acc[j][0]);
            acc[j][1] = fma2(wv, m1, acc[j][1]);
        }
    }

#pragma unroll
    for (int j = 0; j < 16; j++) {
        int o = wp + 16 * j;
        float bias = bz[o];
        size_t obase = ((size_t)(b * C_ + o) * H_ + h) * W_;
        int p = 4 * lane;
        float4 xv = *reinterpret_cast<const float4*>(&x[obase + p]);
        float2 a0 = unpack2(acc[j][0]);
        float2 a1 = unpack2(acc[j][1]);
        float4 ov;
        ov.x = a0.x + bias + xv.x;
        ov.y = a0.y + bias + xv.y;
        ov.z = a1.x + bias + xv.z;
        ov.w = a1.y + bias + xv.w;
        *reinterpret_cast<float4*>(&out[obase + p]) = ov;
    }
}

// ---------------- launch ------------------------------------------------------
extern "C" void kernel_launch(void* const* d_in, const int* in_sizes, int n_in,
                              void* d_out, int out_size)
{
    const float* x  = (const float*)d_in[0];
    const float* Wq = (const float*)d_in[1];
    const float* bq = (const float*)d_in[2];
    const float* Wk = (const float*)d_in[3];
    const float* bk = (const float*)d_in[4];
    const float* Wv = (const float*)d_in[5];
    const float* bv = (const float*)d_in[6];
    const float* Wz = (const float*)d_in[7];
    const float* bz = (const float*)d_in[8];
    float* out = (float*)d_out;

    cudaFuncSetAttribute(proj_mma_kernel, cudaFuncAttributeMaxDynamicSharedMemorySize, PROJ_SMEM);
    cudaFuncSetAttribute(attn_kernel,     cudaFuncAttributeMaxDynamicSharedMemorySize, ATTN_SMEM);
    cudaFuncSetAttribute(combine_kernel,  cudaFuncAttributeMaxDynamicSharedMemorySize, COMB_SMEM);

    proj_mma_kernel<<<dim3(H_, B_), 256, PROJ_SMEM>>>(x, Wq, bq, Wk, bk, Wv, bv);
    transpose_kernel<<<dim3(4, 4, 3 * 256), dim3(32, 8)>>>(0);   // q,k,v -> qt,kt,vt
    attn_kernel<<<dim3(W_, B_), 256, ATTN_SMEM>>>(1);            // H path
    attn_kernel<<<dim3(H_, B_), 256, ATTN_SMEM>>>(0);            // W path
    transpose_kernel<<<dim3(4, 4, 256), dim3(32, 8)>>>(3);       // oH -> oHt
    combine_kernel<<<dim3(H_, B_), 512, COMB_SMEM>>>(x, Wz, bz, out);
}

// round 13
// speedup vs baseline: 2.0350x; 1.0649x over previous
#include <cuda_runtime.h>

typedef unsigned long long ull;
typedef unsigned int uint_;

#define B_   8
#define C_   256
#define H_   128
#define W_   128
#define CR_  32
#define HW_  (H_ * W_)

// ---------------- scratch (device globals; no runtime allocation) -------------
__device__ float g_q  [B_ * CR_ * HW_];   // (b, cr, h, w)
__device__ float g_k  [B_ * CR_ * HW_];
__device__ float g_v  [B_ * CR_ * HW_];
__device__ float g_qt [B_ * CR_ * HW_];   // (b, cr, w, h)
__device__ float g_kt [B_ * CR_ * HW_];
__device__ float g_vt [B_ * CR_ * HW_];
__device__ float g_oH [B_ * CR_ * HW_];   // (b, cr, w, h)
__device__ float g_oHt[B_ * CR_ * HW_];   // (b, cr, h, w)
__device__ float g_oW [B_ * CR_ * HW_];   // (b, cr, h, w)
__device__ float g_mH [B_ * HW_];
__device__ float g_sH [B_ * HW_];
__device__ float g_mW [B_ * HW_];
__device__ float g_sW [B_ * HW_];

// ---------------- packed f32x2 helpers ---------------------------------------
__device__ __forceinline__ ull fma2(ull a, ull b, ull c) {
    ull d;
    asm("fma.rn.f32x2 %0, %1, %2, %3;" : "=l"(d) : "l"(a), "l"(b), "l"(c));
    return d;
}
__device__ __forceinline__ ull splat2(float f) {
    ull r; uint_ u = __float_as_uint(f);
    asm("mov.b64 %0, {%1, %1};" : "=l"(r) : "r"(u));
    return r;
}
__device__ __forceinline__ float2 unpack2(ull u) {
    uint_ lo, hi;
    asm("mov.b64 {%0, %1}, %2;" : "=r"(lo), "=r"(hi) : "l"(u));
    return make_float2(__uint_as_float(lo), __uint_as_float(hi));
}
__device__ __forceinline__ ull ldpair(const float* p) {
    union { float2 f2; ull u; } t;
    t.f2 = *reinterpret_cast<const float2*>(p);
    return t.u;
}

// bf16 hi/lo split: hi2/lo2 pack (elem0 -> low half, elem1 -> high half)
__device__ __forceinline__ void split_bf16(float x0, float x1, uint_& hi2, uint_& lo2) {
    asm("cvt.rn.satfinite.bf16x2.f32 %0, %1, %2;" : "=r"(hi2) : "f"(x1), "f"(x0));
    float h0 = __uint_as_float(hi2 << 16);
    float h1 = __uint_as_float(hi2 & 0xffff0000u);
    float l0 = x0 - h0, l1 = x1 - h1;
    asm("cvt.rn.satfinite.bf16x2.f32 %0, %1, %2;" : "=r"(lo2) : "f"(l1), "f"(l0));
}

// warp-level bf16 MMA: D(16x8,f32) += A(16x16,bf16 row) * B(16x8,bf16 col)
__device__ __forceinline__ void mma_bf16(float* d, const uint_* a, const uint_* b) {
    asm volatile(
        "mma.sync.aligned.m16n8k16.row.col.f32.bf16.bf16.f32 "
        "{%0,%1,%2,%3}, {%4,%5,%6,%7}, {%8,%9}, {%0,%1,%2,%3};"
        : "+f"(d[0]), "+f"(d[1]), "+f"(d[2]), "+f"(d[3])
        : "r"(a[0]), "r"(a[1]), "r"(a[2]), "r"(a[3]), "r"(b[0]), "r"(b[1]));
}

// ---------------- kernel 1: q/k/v projection via mma.sync bf16-split ----------
// grid (H, B), 256 threads. Vectorized float4 streaming of x.
#define PJ_WPH   0
#define PJ_WPL   (96 * 36)
#define PJ_XPH   (2 * 96 * 36)
#define PJ_XPL   (2 * 96 * 36 + 32 * 136)
#define PJ_BIAS  (2 * 96 * 36 + 2 * 32 * 136)
#define PROJ_SMEM ((2 * 96 * 36 + 2 * 32 * 136 + 96) * 4)

__global__ void __launch_bounds__(256, 2) proj_mma_kernel(
    const float* __restrict__ x,
    const float* __restrict__ Wq, const float* __restrict__ bq,
    const float* __restrict__ Wk, const float* __restrict__ bk,
    const float* __restrict__ Wv, const float* __restrict__ bv)
{
    extern __shared__ uint_ ps[];
    uint_* Wph = ps + PJ_WPH;
    uint_* Wpl = ps + PJ_WPL;
    uint_* Xph = ps + PJ_XPH;
    uint_* Xpl = ps + PJ_XPL;
    float* bsm = reinterpret_cast<float*>(ps + PJ_BIAS);

    int h = blockIdx.x, b = blockIdx.y;
    int tid = threadIdx.x;
    int wid = tid >> 5, lane = tid & 31;
    int g = lane >> 2, tg = lane & 3;
    int wm = wid >> 2, wn = wid & 3;
    int m0 = wm * 48, n0 = wn * 32;

    if (tid < 96) {
        float bv_;
        if (tid < 32)      bv_ = bq[tid];
        else if (tid < 64) bv_ = bk[tid - 32];
        else               bv_ = bv[tid - 64];
        bsm[tid] = bv_;
    }

    const float* xb = x + (size_t)b * C_ * HW_ + (size_t)h * W_;

    float acc[3][4][4];
#pragma unroll
    for (int mt = 0; mt < 3; mt++)
#pragma unroll
        for (int nt = 0; nt < 4; nt++)
#pragma unroll
            for (int u = 0; u < 4; u++) acc[mt][nt][u] = 0.f;

    int cpld = tid >> 3;           // 0..31 channel-pair
    int pbld = (tid & 7) * 16;     // pixel strip base

    for (int kc = 0; kc < 4; kc++) {
        if (kc) __syncthreads();
        for (int idx = tid; idx < 96 * 16; idx += 256) {
            int r = idx >> 4, f4 = idx & 15;
            const float* wsrc;
            if (r < 32)      wsrc = Wq + (size_t)r * C_;
            else if (r < 64) wsrc = Wk + (size_t)(r - 32) * C_;
            else             wsrc = Wv + (size_t)(r - 64) * C_;
            float4 w4 = *reinterpret_cast<const float4*>(&wsrc[kc * 64 + 4 * f4]);
            uint_ h0, l0, h1, l1;
            split_bf16(w4.x, w4.y, h0, l0);
            split_bf16(w4.z, w4.w, h1, l1);
            Wph[r * 36 + 2 * f4]     = h0;
            Wph[r * 36 + 2 * f4 + 1] = h1;
            Wpl[r * 36 + 2 * f4]     = l0;
            Wpl[r * 36 + 2 * f4 + 1] = l1;
        }
        {
            const float* x0p = xb + (size_t)(kc * 64 + 2 * cpld) * HW_;
            const float* x1p = x0p + HW_;
#pragma unroll
            for (int it = 0; it < 4; it++) {
                int p = pbld + 4 * it;
                float4 a4 = *reinterpret_cast<const float4*>(&x0p[p]);
                float4 b4 = *reinterpret_cast<const float4*>(&x1p[p]);
                uint_ hh[4], ll[4];
                split_bf16(a4.x, b4.x, hh[0], ll[0]);
                split_bf16(a4.y, b4.y, hh[1], ll[1]);
                split_bf16(a4.z, b4.z, hh[2], ll[2]);
                split_bf16(a4.w, b4.w, hh[3], ll[3]);
                *reinterpret_cast<uint4*>(&Xph[cpld * 136 + p]) =
                    make_uint4(hh[0], hh[1], hh[2], hh[3]);
                *reinterpret_cast<uint4*>(&Xpl[cpld * 136 + p]) =
                    make_uint4(ll[0], ll[1], ll[2], ll[3]);
            }
        }
        __syncthreads();

#pragma unroll
        for (int ks = 0; ks < 4; ks++) {
            int kpb = ks * 8;
            uint_ bh[4][2], bl[4][2];
#pragma unroll
            for (int nt = 0; nt < 4; nt++) {
                int n = n0 + nt * 8 + g;
                bh[nt][0] = Xph[(kpb + tg) * 136 + n];
                bh[nt][1] = Xph[(kpb + tg + 4) * 136 + n];
                bl[nt][0] = Xpl[(kpb + tg) * 136 + n];
                bl[nt][1] = Xpl[(kpb + tg + 4) * 136 + n];
            }
#pragma unroll
            for (int mt = 0; mt < 3; mt++) {
                int m = m0 + mt * 16 + g;
                uint_ ah[4], al[4];
                ah[0] = Wph[m * 36 + kpb + tg];
                ah[1] = Wph[(m + 8) * 36 + kpb + tg];
                ah[2] = Wph[m * 36 + kpb + tg + 4];
                ah[3] = Wph[(m + 8) * 36 + kpb + tg + 4];
                al[0] = Wpl[m * 36 + kpb + tg];
                al[1] = Wpl[(m + 8) * 36 + kpb + tg];
                al[2] = Wpl[m * 36 + kpb + tg + 4];
                al[3] = Wpl[(m + 8) * 36 + kpb + tg + 4];
#pragma unroll
                for (int nt = 0; nt < 4; nt++) {
                    mma_bf16(acc[mt][nt], ah, bh[nt]);
                    mma_bf16(acc[mt][nt], ah, bl[nt]);
                    mma_bf16(acc[mt][nt], al, bh[nt]);
                }
            }
        }
    }

#pragma unroll
    for (int mt = 0; mt < 3; mt++) {
#pragma unroll
        for (int half = 0; half < 2; half++) {
            int r = m0 + mt * 16 + g + 8 * half;
            float bias = bsm[r];
            float* dstb;
            int ch;
            if (r < 32)      { dstb = g_q; ch = r; }
            else if (r < 64) { dstb = g_k; ch = r - 32; }
            else             { dstb = g_v; ch = r - 64; }
            float* drow = dstb + ((size_t)(b * CR_ + ch) * H_ + h) * W_;
#pragma unroll
            for (int nt = 0; nt < 4; nt++) {
                int pix = n0 + nt * 8 + 2 * tg;
                float2 v;
                v.x = acc[mt][nt][2 * half]     + bias;
                v.y = acc[mt][nt][2 * half + 1] + bias;
                *reinterpret_cast<float2*>(&drow[pix]) = v;
            }
        }
    }
}

// ---------------- kernel 2: HxW tile transpose --------------------------------
__global__ void __launch_bounds__(256) transpose_kernel(int base_arr)
{
    __shared__ float tile[32][33];
    int zc = blockIdx.z;
    int arr = base_arr + (zc >> 8), m = zc & 255;
    const float* src; float* dst;
    if      (arr == 0) { src = g_q;  dst = g_qt;  }
    else if (arr == 1) { src = g_k;  dst = g_kt;  }
    else if (arr == 2) { src = g_v;  dst = g_vt;  }
    else               { src = g_oH; dst = g_oHt; }
    src += (size_t)m * HW_;
    dst += (size_t)m * HW_;
    int x0 = blockIdx.x * 32, y0 = blockIdx.y * 32;
    int tx = threadIdx.x, ty = threadIdx.y;
#pragma unroll
    for (int r = 0; r < 32; r += 8)
        tile[ty + r][tx] = src[(size_t)(y0 + ty + r) * W_ + x0 + tx];
    __syncthreads();
#pragma unroll
    for (int r = 0; r < 32; r += 8)
        dst[(size_t)(x0 + ty + r) * H_ + y0 + tx] = tile[tx][ty + r];
}

// ---------------- kernel 3: HMMA attention (round-11, unchanged) --------------
#define AQ_PH  0
#define AQ_PL  2176
#define AK_PH  4352
#define AK_PL  6464
#define AV_PH  8576
#define AV_PL  10688
#define ATTN_SMEM (12800 * 4)

__global__ void __launch_bounds__(256, 2) attn_kernel(int transposed)
{
    extern __shared__ uint_ su[];
    uint_* Qph = su + AQ_PH;
    uint_* Qpl = su + AQ_PL;
    uint_* Kph = su + AK_PH;
    uint_* Kpl = su + AK_PL;
    uint_* Vph = su + AV_PH;
    uint_* Vpl = su + AV_PL;
    float* stg = reinterpret_cast<float*>(su);

    const float* qin = transposed ? g_qt : g_q;
    const float* kin = transposed ? g_kt : g_k;
    const float* vin = transposed ? g_vt : g_v;
    float* outp  = transposed ? g_oH : g_oW;
    float* mstat = transposed ? g_mH : g_mW;
    float* sstat = transposed ? g_sH : g_sW;

    int X = blockIdx.x, b = blockIdx.y;
    size_t base = (size_t)b * CR_ * HW_ + (size_t)X * W_;
    int tid = threadIdx.x, warp = tid >> 5, lane = tid & 31;
    int g = lane >> 2, tg = lane & 3;

    for (int idx = tid; idx < 16 * 128; idx += 256) {
        int e = idx & 127, cp = idx >> 7;
        float q0 = qin[base + (size_t)(2 * cp) * HW_ + e];
        float q1 = qin[base + (size_t)(2 * cp + 1) * HW_ + e];
        uint_ h2, l2;
        split_bf16(q0, q1, h2, l2);
        Qph[e * 17 + cp] = h2;
        Qpl[e * 17 + cp] = l2;
        float k0 = kin[base + (size_t)(2 * cp) * HW_ + e];
        float k1 = kin[base + (size_t)(2 * cp + 1) * HW_ + e];
        split_bf16(k0, k1, h2, l2);
        Kph[cp * 132 + e] = h2;
        Kpl[cp * 132 + e] = l2;
    }
    for (int idx = tid; idx < 32 * 64; idx += 256) {
        int ip = idx & 63, c = idx >> 6;
        float2 v2 = *reinterpret_cast<const float2*>(&vin[base + (size_t)c * HW_ + 2 * ip]);
        uint_ h2, l2;
        split_bf16(v2.x, v2.y, h2, l2);
        Vph[c * 66 + ip] = h2;
        Vpl[c * 66 + ip] = l2;
    }
    __syncthreads();

    int r0 = warp * 16 + g;
    int r1 = r0 + 8;

    float dE[16][4];
#pragma unroll
    for (int nt = 0; nt < 16; nt++)
#pragma unroll
        for (int u = 0; u < 4; u++) dE[nt][u] = 0.f;

#pragma unroll
    for (int ks = 0; ks < 2; ks++) {
        int kpb = ks * 8;
        uint_ ah[4], al[4];
        ah[0] = Qph[r0 * 17 + kpb + tg];
        ah[1] = Qph[r1 * 17 + kpb + tg];
        ah[2] = Qph[r0 * 17 + kpb + tg + 4];
        ah[3] = Qph[r1 * 17 + kpb + tg + 4];
        al[0] = Qpl[r0 * 17 + kpb + tg];
        al[1] = Qpl[r1 * 17 + kpb + tg];
        al[2] = Qpl[r0 * 17 + kpb + tg + 4];
        al[3] = Qpl[r1 * 17 + kpb + tg + 4];
#pragma unroll
        for (int nt = 0; nt < 16; nt++) {
            int n = nt * 8 + g;
            uint_ bh[2], bl[2];
            bh[0] = Kph[(kpb + tg) * 132 + n];
            bh[1] = Kph[(kpb + tg + 4) * 132 + n];
            bl[0] = Kpl[(kpb + tg) * 132 + n];
            bl[1] = Kpl[(kpb + tg + 4) * 132 + n];
            mma_bf16(dE[nt], ah, bh);
            mma_bf16(dE[nt], ah, bl);
            mma_bf16(dE[nt], al, bh);
        }
    }

    if (transposed) {
#pragma unroll
        for (int nt = 0; nt < 16; nt++) {
            int c0 = nt * 8 + 2 * tg, c1 = c0 + 1;
            if (c0 == r0) dE[nt][0] = -1e30f;
            if (c1 == r0) dE[nt][1] = -1e30f;
            if (c0 == r1) dE[nt][2] = -1e30f;
            if (c1 == r1) dE[nt][3] = -1e30f;
        }
    }

    float m0 = -1e30f, m1 = -1e30f;
#pragma unroll
    for (int nt = 0; nt < 16; nt++) {
        m0 = fmaxf(m0, fmaxf(dE[nt][0], dE[nt][1]));
        m1 = fmaxf(m1, fmaxf(dE[nt][2], dE[nt][3]));
    }
    m0 = fmaxf(m0, __shfl_xor_sync(0xffffffffu, m0, 1));
    m0 = fmaxf(m0, __shfl_xor_sync(0xffffffffu, m0, 2));
    m1 = fmaxf(m1, __shfl_xor_sync(0xffffffffu, m1, 1));
    m1 = fmaxf(m1, __shfl_xor_sync(0xffffffffu, m1, 2));

    float s0 = 0.f, s1 = 0.f;
#pragma unroll
    for (int nt = 0; nt < 16; nt++) {
        dE[nt][0] = __expf(dE[nt][0] - m0);
        dE[nt][1] = __expf(dE[nt][1] - m0);
        dE[nt][2] = __expf(dE[nt][2] - m1);
        dE[nt][3] = __expf(dE[nt][3] - m1);
        s0 += dE[nt][0] + dE[nt][1];
        s1 += dE[nt][2] + dE[nt][3];
    }
    s0 += __shfl_xor_sync(0xffffffffu, s0, 1);
    s0 += __shfl_xor_sync(0xffffffffu, s0, 2);
    s1 += __shfl_xor_sync(0xffffffffu, s1, 1);
    s1 += __shfl_xor_sync(0xffffffffu, s1, 2);

    if (tg == 0) {
        size_t s0i = transposed ? ((size_t)(b * H_ + r0) * W_ + X)
                                : ((size_t)(b * H_ + X) * W_ + r0);
        size_t s1i = transposed ? ((size_t)(b * H_ + r1) * W_ + X)
                                : ((size_t)(b * H_ + X) * W_ + r1);
        mstat[s0i] = m0;  sstat[s0i] = s0;
        mstat[s1i] = m1;  sstat[s1i] = s1;
    }

    float dO[4][4];
#pragma unroll
    for (int nt = 0; nt < 4; nt++)
#pragma unroll
        for (int u = 0; u < 4; u++) dO[nt][u] = 0.f;

#pragma unroll
    for (int kb = 0; kb < 8; kb++) {
        uint_ ah[4], al[4];
        split_bf16(dE[2 * kb][0],     dE[2 * kb][1],     ah[0], al[0]);
        split_bf16(dE[2 * kb][2],     dE[2 * kb][3],     ah[1], al[1]);
        split_bf16(dE[2 * kb + 1][0], dE[2 * kb + 1][1], ah[2], al[2]);
        split_bf16(dE[2 * kb + 1][2], dE[2 * kb + 1][3], ah[3], al[3]);
#pragma unroll
        for (int nt = 0; nt < 4; nt++) {
            int c = nt * 8 + g;
            uint_ bh[2], bl[2];
            bh[0] = Vph[c * 66 + 8 * kb + tg];
            bh[1] = Vph[c * 66 + 8 * kb + tg + 4];
            bl[0] = Vpl[c * 66 + 8 * kb + tg];
            bl[1] = Vpl[c * 66 + 8 * kb + tg + 4];
            mma_bf16(dO[nt], ah, bh);
            mma_bf16(dO[nt], ah, bl);
            mma_bf16(dO[nt], al, bh);
        }
    }

    __syncthreads();
#pragma unroll
    for (int nt = 0; nt < 4; nt++) {
        int c0 = nt * 8 + 2 * tg;
        stg[c0 * 130 + r0]       = dO[nt][0];
        stg[(c0 + 1) * 130 + r0] = dO[nt][1];
        stg[c0 * 130 + r1]       = dO[nt][2];
        stg[(c0 + 1) * 130 + r1] = dO[nt][3];
    }
    __syncthreads();
    for (int idx = tid; idx < CR_ * 128; idx += 256) {
        int c = idx >> 7, e = idx & 127;
        outp[base + (size_t)c * HW_ + e] = stg[c * 130 + e];
    }
}

// ---------------- kernel 4: combine via mma.sync bf16-split -------------------
// grid (H, B), 512 threads (16 warps, 4x4). D[256 out][128 pix] = Wz . mg
// smem (uint units): Wzh[256][18], Wzl[256][18], Mgh[16][132], Mgl[16][132],
//                    fH[128], fW[128]
#define CB_WZH  0
#define CB_WZL  (256 * 18)
#define CB_MGH  (2 * 256 * 18)
#define CB_MGL  (2 * 256 * 18 + 16 * 132)
#define CB_F    (2 * 256 * 18 + 2 * 16 * 132)
#define COMB_SMEM ((2 * 256 * 18 + 2 * 16 * 132 + 256) * 4)

__global__ void __launch_bounds__(512) combine_kernel(
    const float* __restrict__ x, const float* __restrict__ Wz,
    const float* __restrict__ bz, float* __restrict__ out)
{
    extern __shared__ uint_ cu[];
    uint_* Wzh = cu + CB_WZH;
    uint_* Wzl = cu + CB_WZL;
    uint_* Mgh = cu + CB_MGH;
    uint_* Mgl = cu + CB_MGL;
    float* fH  = reinterpret_cast<float*>(cu + CB_F);
    float* fW  = fH + 128;

    int h = blockIdx.x, b = blockIdx.y;
    int tid = threadIdx.x;
    int wp = tid >> 5, lane = tid & 31;
    int g = lane >> 2, tg = lane & 3;
    int wm = wp >> 2, wn = wp & 3;           // 4 x 4 warp grid
    int m0 = wm * 64, n0 = wn * 32;

    // ---- softmax merge factors ----
    if (tid < 128) {
        int w = tid;
        size_t sidx = (size_t)(b * H_ + h) * W_ + w;
        float mh = g_mH[sidx], mw = g_mW[sidx];
        float sh = g_sH[sidx], sw = g_sW[sidx];
        float m  = fmaxf(mh, mw);
        float eh = __expf(mh - m), ew = __expf(mw - m);
        float inv = 1.0f / (sh * eh + sw * ew);
        fH[w] = eh * inv;
        fW[w] = ew * inv;
    }
    // ---- Wz split: 256 rows x 8 float4 ----
    for (int idx = tid; idx < 256 * 8; idx += 512) {
        int r = idx >> 3, f4 = idx & 7;
        float4 w4 = *reinterpret_cast<const float4*>(&Wz[r * 32 + 4 * f4]);
        uint_ h0, l0, h1, l1;
        split_bf16(w4.x, w4.y, h0, l0);
        split_bf16(w4.z, w4.w, h1, l1);
        Wzh[r * 18 + 2 * f4]     = h0;
        Wzh[r * 18 + 2 * f4 + 1] = h1;
        Wzl[r * 18 + 2 * f4]     = l0;
        Wzl[r * 18 + 2 * f4 + 1] = l1;
    }
    __syncthreads();

    // ---- merged attention output -> bf16 hi/lo B tile ----
    // thread handles channel-pair kp, 4 pixels (float4 loads of both channels)
    for (int idx = tid; idx < 16 * 32; idx += 512) {
        int kp = idx >> 5, w4 = (idx & 31) * 4;
        size_t off0 = (size_t)(b * CR_ + 2 * kp) * HW_ + (size_t)h * W_ + w4;
        size_t off1 = off0 + HW_;
        float4 oh0 = *reinterpret_cast<const float4*>(&g_oHt[off0]);
        float4 ow0 = *reinterpret_cast<const float4*>(&g_oW [off0]);
        float4 oh1 = *reinterpret_cast<const float4*>(&g_oHt[off1]);
        float4 ow1 = *reinterpret_cast<const float4*>(&g_oW [off1]);
        float fh0 = fH[w4], fh1 = fH[w4 + 1], fh2 = fH[w4 + 2], fh3 = fH[w4 + 3];
        float fw0 = fW[w4], fw1 = fW[w4 + 1], fw2 = fW[w4 + 2], fw3 = fW[w4 + 3];
        float c0p0 = oh0.x * fh0 + ow0.x * fw0;
        float c0p1 = oh0.y * fh1 + ow0.y * fw1;
        float c0p2 = oh0.z * fh2 + ow0.z * fw2;
        float c0p3 = oh0.w * fh3 + ow0.w * fw3;
        float c1p0 = oh1.x * fh0 + ow1.x * fw0;
        float c1p1 = oh1.y * fh1 + ow1.y * fw1;
        float c1p2 = oh1.z * fh2 + ow1.z * fw2;
        float c1p3 = oh1.w * fh3 + ow1.w * fw3;
        uint_ hh[4], ll[4];
        split_bf16(c0p0, c1p0, hh[0], ll[0]);
        split_bf16(c0p1, c1p1, hh[1], ll[1]);
        split_bf16(c0p2, c1p2, hh[2], ll[2]);
        split_bf16(c0p3, c1p3, hh[3], ll[3]);
        *reinterpret_cast<uint4*>(&Mgh[kp * 132 + w4]) = make_uint4(hh[0], hh[1], hh[2], hh[3]);
        *reinterpret_cast<uint4*>(&Mgl[kp * 132 + w4]) = make_uint4(ll[0], ll[1], ll[2], ll[3]);
    }
    __syncthreads();

    // ---- MMA: warp tile 64 rows x 32 pixels (4 mt x 4 nt), K=32 (2 k16) ----
    float acc[4][4][4];
#pragma unroll
    for (int mt = 0; mt < 4; mt++)
#pragma unroll
        for (int nt = 0; nt < 4; nt++)
#pragma unroll
            for (int u = 0; u < 4; u++) acc[mt][nt][u] = 0.f;

#pragma unroll
    for (int ks = 0; ks < 2; ks++) {
        int kpb = ks * 8;
        uint_ bh[4][2], bl[4][2];
#pragma unroll
        for (int nt = 0; nt < 4; nt++) {
            int n = n0 + nt * 8 + g;
            bh[nt][0] = Mgh[(kpb + tg) * 132 + n];
            bh[nt][1] = Mgh[(kpb + tg + 4) * 132 + n];
            bl[nt][0] = Mgl[(kpb + tg) * 132 + n];
            bl[nt][1] = Mgl[(kpb + tg + 4) * 132 + n];
        }
#pragma unroll
        for (int mt = 0; mt < 4; mt++) {
            int m = m0 + mt * 16 + g;
            uint_ ah[4], al[4];
            ah[0] = Wzh[m * 18 + kpb + tg];
            ah[1] = Wzh[(m + 8) * 18 + kpb + tg];
            ah[2] = Wzh[m * 18 + kpb + tg + 4];
            ah[3] = Wzh[(m + 8) * 18 + kpb + tg + 4];
            al[0] = Wzl[m * 18 + kpb + tg];
            al[1] = Wzl[(m + 8) * 18 + kpb + tg];
            al[2] = Wzl[m * 18 + kpb + tg + 4];
            al[3] = Wzl[(m + 8) * 18 + kpb + tg + 4];
#pragma unroll
            for (int nt = 0; nt < 4; nt++) {
                mma_bf16(acc[mt][nt], ah, bh[nt]);
                mma_bf16(acc[mt][nt], ah, bl[nt]);
                mma_bf16(acc[mt][nt], al, bh[nt]);
            }
        }
    }

    // ---- epilogue: bias + residual + store ----
#pragma unroll
    for (int mt = 0; mt < 4; mt++) {
#pragma unroll
        for (int half = 0; half < 2; half++) {
            int o = m0 + mt * 16 + g + 8 * half;
            float bias = bz[o];
            size_t obase = ((size_t)(b * C_ + o) * H_ + h) * W_;
#pragma unroll
            for (int nt = 0; nt < 4; nt++) {
                int pix = n0 + nt * 8 + 2 * tg;
                float2 xv = *reinterpret_cast<const float2*>(&x[obase + pix]);
                float2 v;
                v.x = acc[mt][nt][2 * half]     + bias + xv.x;
                v.y = acc[mt][nt][2 * half + 1] + bias + xv.y;
                *reinterpret_cast<float2*>(&out[obase + pix]) = v;
            }
        }
    }
}

// ---------------- launch ------------------------------------------------------
extern "C" void kernel_launch(void* const* d_in, const int* in_sizes, int n_in,
                              void* d_out, int out_size)
{
    const float* x  = (const float*)d_in[0];
    const float* Wq = (const float*)d_in[1];
    const float* bq = (const float*)d_in[2];
    const float* Wk = (const float*)d_in[3];
    const float* bk = (const float*)d_in[4];
    const float* Wv = (const float*)d_in[5];
    const float* bv = (const float*)d_in[6];
    const float* Wz = (const float*)d_in[7];
    const float* bz = (const float*)d_in[8];
    float* out = (float*)d_out;

    cudaFuncSetAttribute(proj_mma_kernel, cudaFuncAttributeMaxDynamicSharedMemorySize, PROJ_SMEM);
    cudaFuncSetAttribute(attn_kernel,     cudaFuncAttributeMaxDynamicSharedMemorySize, ATTN_SMEM);
    cudaFuncSetAttribute(combine_kernel,  cudaFuncAttributeMaxDynamicSharedMemorySize, COMB_SMEM);

    proj_mma_kernel<<<dim3(H_, B_), 256, PROJ_SMEM>>>(x, Wq, bq, Wk, bk, Wv, bv);
    transpose_kernel<<<dim3(4, 4, 3 * 256), dim3(32, 8)>>>(0);   // q,k,v -> qt,kt,vt
    attn_kernel<<<dim3(W_, B_), 256, ATTN_SMEM>>>(1);            // H path
    attn_kernel<<<dim3(H_, B_), 256, ATTN_SMEM>>>(0);            // W path
    transpose_kernel<<<dim3(4, 4, 256), dim3(32, 8)>>>(3);       // oH -> oHt
    combine_kernel<<<dim3(H_, B_), 512, COMB_SMEM>>>(x, Wz, bz, out);
}

// round 15
// speedup vs baseline: 2.3805x; 1.1697x over previous
#include <cuda_runtime.h>

typedef unsigned long long ull;
typedef unsigned int uint_;

#define B_   8
#define C_   256
#define H_   128
#define W_   128
#define CR_  32
#define HW_  (H_ * W_)

// ---------------- scratch (device globals; no runtime allocation) -------------
__device__ float g_q  [B_ * CR_ * HW_];   // (b, cr, h, w)
__device__ float g_k  [B_ * CR_ * HW_];
__device__ float g_v  [B_ * CR_ * HW_];
__device__ float g_qt [B_ * CR_ * HW_];   // (b, cr, w, h)
__device__ float g_kt [B_ * CR_ * HW_];
__device__ float g_vt [B_ * CR_ * HW_];
__device__ float g_oH [B_ * CR_ * HW_];   // (b, cr, w, h)
__device__ float g_oHt[B_ * CR_ * HW_];   // (b, cr, h, w)
__device__ float g_oW [B_ * CR_ * HW_];   // (b, cr, h, w)
__device__ float g_mH [B_ * HW_];
__device__ float g_sH [B_ * HW_];
__device__ float g_mW [B_ * HW_];
__device__ float g_sW [B_ * HW_];

// ---------------- packed f32x2 helpers ---------------------------------------
__device__ __forceinline__ ull fma2(ull a, ull b, ull c) {
    ull d;
    asm("fma.rn.f32x2 %0, %1, %2, %3;" : "=l"(d) : "l"(a), "l"(b), "l"(c));
    return d;
}
__device__ __forceinline__ ull splat2(float f) {
    ull r; uint_ u = __float_as_uint(f);
    asm("mov.b64 %0, {%1, %1};" : "=l"(r) : "r"(u));
    return r;
}
__device__ __forceinline__ float2 unpack2(ull u) {
    uint_ lo, hi;
    asm("mov.b64 {%0, %1}, %2;" : "=r"(lo), "=r"(hi) : "l"(u));
    return make_float2(__uint_as_float(lo), __uint_as_float(hi));
}
__device__ __forceinline__ ull ldpair(const float* p) {
    union { float2 f2; ull u; } t;
    t.f2 = *reinterpret_cast<const float2*>(p);
    return t.u;
}

// bf16 hi/lo split: hi2/lo2 pack (elem0 -> low half, elem1 -> high half)
__device__ __forceinline__ void split_bf16(float x0, float x1, uint_& hi2, uint_& lo2) {
    asm("cvt.rn.satfinite.bf16x2.f32 %0, %1, %2;" : "=r"(hi2) : "f"(x1), "f"(x0));
    float h0 = __uint_as_float(hi2 << 16);
    float h1 = __uint_as_float(hi2 & 0xffff0000u);
    float l0 = x0 - h0, l1 = x1 - h1;
    asm("cvt.rn.satfinite.bf16x2.f32 %0, %1, %2;" : "=r"(lo2) : "f"(l1), "f"(l0));
}

// warp-level bf16 MMA: D(16x8,f32) += A(16x16,bf16 row) * B(16x8,bf16 col)
__device__ __forceinline__ void mma_bf16(float* d, const uint_* a, const uint_* b) {
    asm volatile(
        "mma.sync.aligned.m16n8k16.row.col.f32.bf16.bf16.f32 "
        "{%0,%1,%2,%3}, {%4,%5,%6,%7}, {%8,%9}, {%0,%1,%2,%3};"
        : "+f"(d[0]), "+f"(d[1]), "+f"(d[2]), "+f"(d[3])
        : "r"(a[0]), "r"(a[1]), "r"(a[2]), "r"(a[3]), "r"(b[0]), "r"(b[1]));
}

// ---------------- kernel 1: q/k/v projection via mma.sync bf16-split ----------
// grid (H, B), 256 threads. Vectorized float4 streaming of x.
#define PJ_WPH   0
#define PJ_WPL   (96 * 36)
#define PJ_XPH   (2 * 96 * 36)
#define PJ_XPL   (2 * 96 * 36 + 32 * 136)
#define PJ_BIAS  (2 * 96 * 36 + 2 * 32 * 136)
#define PROJ_SMEM ((2 * 96 * 36 + 2 * 32 * 136 + 96) * 4)

__global__ void __launch_bounds__(256, 2) proj_mma_kernel(
    const float* __restrict__ x,
    const float* __restrict__ Wq, const float* __restrict__ bq,
    const float* __restrict__ Wk, const float* __restrict__ bk,
    const float* __restrict__ Wv, const float* __restrict__ bv)
{
    extern __shared__ uint_ ps[];
    uint_* Wph = ps + PJ_WPH;
    uint_* Wpl = ps + PJ_WPL;
    uint_* Xph = ps + PJ_XPH;
    uint_* Xpl = ps + PJ_XPL;
    float* bsm = reinterpret_cast<float*>(ps + PJ_BIAS);

    int h = blockIdx.x, b = blockIdx.y;
    int tid = threadIdx.x;
    int wid = tid >> 5, lane = tid & 31;
    int g = lane >> 2, tg = lane & 3;
    int wm = wid >> 2, wn = wid & 3;
    int m0 = wm * 48, n0 = wn * 32;

    if (tid < 96) {
        float bv_;
        if (tid < 32)      bv_ = bq[tid];
        else if (tid < 64) bv_ = bk[tid - 32];
        else               bv_ = bv[tid - 64];
        bsm[tid] = bv_;
    }

    const float* xb = x + (size_t)b * C_ * HW_ + (size_t)h * W_;

    float acc[3][4][4];
#pragma unroll
    for (int mt = 0; mt < 3; mt++)
#pragma unroll
        for (int nt = 0; nt < 4; nt++)
#pragma unroll
            for (int u = 0; u < 4; u++) acc[mt][nt][u] = 0.f;

    int cpld = tid >> 3;           // 0..31 channel-pair
    int pbld = (tid & 7) * 16;     // pixel strip base

    for (int kc = 0; kc < 4; kc++) {
        if (kc) __syncthreads();
        for (int idx = tid; idx < 96 * 16; idx += 256) {
            int r = idx >> 4, f4 = idx & 15;
            const float* wsrc;
            if (r < 32)      wsrc = Wq + (size_t)r * C_;
            else if (r < 64) wsrc = Wk + (size_t)(r - 32) * C_;
            else             wsrc = Wv + (size_t)(r - 64) * C_;
            float4 w4 = *reinterpret_cast<const float4*>(&wsrc[kc * 64 + 4 * f4]);
            uint_ h0, l0, h1, l1;
            split_bf16(w4.x, w4.y, h0, l0);
            split_bf16(w4.z, w4.w, h1, l1);
            Wph[r * 36 + 2 * f4]     = h0;
            Wph[r * 36 + 2 * f4 + 1] = h1;
            Wpl[r * 36 + 2 * f4]     = l0;
            Wpl[r * 36 + 2 * f4 + 1] = l1;
        }
        {
            const float* x0p = xb + (size_t)(kc * 64 + 2 * cpld) * HW_;
            const float* x1p = x0p + HW_;
#pragma unroll
            for (int it = 0; it < 4; it++) {
                int p = pbld + 4 * it;
                float4 a4 = *reinterpret_cast<const float4*>(&x0p[p]);
                float4 b4 = *reinterpret_cast<const float4*>(&x1p[p]);
                uint_ hh[4], ll[4];
                split_bf16(a4.x, b4.x, hh[0], ll[0]);
                split_bf16(a4.y, b4.y, hh[1], ll[1]);
                split_bf16(a4.z, b4.z, hh[2], ll[2]);
                split_bf16(a4.w, b4.w, hh[3], ll[3]);
                *reinterpret_cast<uint4*>(&Xph[cpld * 136 + p]) =
                    make_uint4(hh[0], hh[1], hh[2], hh[3]);
                *reinterpret_cast<uint4*>(&Xpl[cpld * 136 + p]) =
                    make_uint4(ll[0], ll[1], ll[2], ll[3]);
            }
        }
        __syncthreads();

#pragma unroll
        for (int ks = 0; ks < 4; ks++) {
            int kpb = ks * 8;
            uint_ bh[4][2], bl[4][2];
#pragma unroll
            for (int nt = 0; nt < 4; nt++) {
                int n = n0 + nt * 8 + g;
                bh[nt][0] = Xph[(kpb + tg) * 136 + n];
                bh[nt][1] = Xph[(kpb + tg + 4) * 136 + n];
                bl[nt][0] = Xpl[(kpb + tg) * 136 + n];
                bl[nt][1] = Xpl[(kpb + tg + 4) * 136 + n];
            }
#pragma unroll
            for (int mt = 0; mt < 3; mt++) {
                int m = m0 + mt * 16 + g;
                uint_ ah[4], al[4];
                ah[0] = Wph[m * 36 + kpb + tg];
                ah[1] = Wph[(m + 8) * 36 + kpb + tg];
                ah[2] = Wph[m * 36 + kpb + tg + 4];
                ah[3] = Wph[(m + 8) * 36 + kpb + tg + 4];
                al[0] = Wpl[m * 36 + kpb + tg];
                al[1] = Wpl[(m + 8) * 36 + kpb + tg];
                al[2] = Wpl[m * 36 + kpb + tg + 4];
                al[3] = Wpl[(m + 8) * 36 + kpb + tg + 4];
#pragma unroll
                for (int nt = 0; nt < 4; nt++) {
                    mma_bf16(acc[mt][nt], ah, bh[nt]);
                    mma_bf16(acc[mt][nt], ah, bl[nt]);
                    mma_bf16(acc[mt][nt], al, bh[nt]);
                }
            }
        }
    }

#pragma unroll
    for (int mt = 0; mt < 3; mt++) {
#pragma unroll
        for (int half = 0; half < 2; half++) {
            int r = m0 + mt * 16 + g + 8 * half;
            float bias = bsm[r];
            float* dstb;
            int ch;
            if (r < 32)      { dstb = g_q; ch = r; }
            else if (r < 64) { dstb = g_k; ch = r - 32; }
            else             { dstb = g_v; ch = r - 64; }
            float* drow = dstb + ((size_t)(b * CR_ + ch) * H_ + h) * W_;
#pragma unroll
            for (int nt = 0; nt < 4; nt++) {
                int pix = n0 + nt * 8 + 2 * tg;
                float2 v;
                v.x = acc[mt][nt][2 * half]     + bias;
                v.y = acc[mt][nt][2 * half + 1] + bias;
                *reinterpret_cast<float2*>(&drow[pix]) = v;
            }
        }
    }
}

// ---------------- kernel 2: HxW tile transpose --------------------------------
__global__ void __launch_bounds__(256) transpose_kernel(int base_arr)
{
    __shared__ float tile[32][33];
    int zc = blockIdx.z;
    int arr = base_arr + (zc >> 8), m = zc & 255;
    const float* src; float* dst;
    if      (arr == 0) { src = g_q;  dst = g_qt;  }
    else if (arr == 1) { src = g_k;  dst = g_kt;  }
    else if (arr == 2) { src = g_v;  dst = g_vt;  }
    else               { src = g_oH; dst = g_oHt; }
    src += (size_t)m * HW_;
    dst += (size_t)m * HW_;
    int x0 = blockIdx.x * 32, y0 = blockIdx.y * 32;
    int tx = threadIdx.x, ty = threadIdx.y;
#pragma unroll
    for (int r = 0; r < 32; r += 8)
        tile[ty + r][tx] = src[(size_t)(y0 + ty + r) * W_ + x0 + tx];
    __syncthreads();
#pragma unroll
    for (int r = 0; r < 32; r += 8)
        dst[(size_t)(x0 + ty + r) * H_ + y0 + tx] = tile[tx][ty + r];
}

// ---------------- kernel 3: HMMA attention, float4 global loads ---------------
#define AQ_PH  0
#define AQ_PL  2176
#define AK_PH  4352
#define AK_PL  6464
#define AV_PH  8576
#define AV_PL  10688
#define ATTN_SMEM (12800 * 4)

__global__ void __launch_bounds__(256, 2) attn_kernel(int transposed)
{
    extern __shared__ uint_ su[];
    uint_* Qph = su + AQ_PH;
    uint_* Qpl = su + AQ_PL;
    uint_* Kph = su + AK_PH;
    uint_* Kpl = su + AK_PL;
    uint_* Vph = su + AV_PH;
    uint_* Vpl = su + AV_PL;
    float* stg = reinterpret_cast<float*>(su);

    const float* qin = transposed ? g_qt : g_q;
    const float* kin = transposed ? g_kt : g_k;
    const float* vin = transposed ? g_vt : g_v;
    float* outp  = transposed ? g_oH : g_oW;
    float* mstat = transposed ? g_mH : g_mW;
    float* sstat = transposed ? g_sH : g_sW;

    int X = blockIdx.x, b = blockIdx.y;
    size_t base = (size_t)b * CR_ * HW_ + (size_t)X * W_;
    int tid = threadIdx.x, warp = tid >> 5, lane = tid & 31;
    int g = lane >> 2, tg = lane & 3;

    // ---- Q/K loads: per (cp, e-quad), 2 x float4 each matrix ----
#pragma unroll
    for (int it = 0; it < 2; it++) {
        int idx = tid + it * 256;                 // 0..511
        int cp = idx >> 5, e4 = (idx & 31) * 4;
        const float* q0p = qin + base + (size_t)(2 * cp) * HW_ + e4;
        const float* q1p = q0p + HW_;
        const float* k0p = kin + base + (size_t)(2 * cp) * HW_ + e4;
        const float* k1p = k0p + HW_;
        float4 q0 = *reinterpret_cast<const float4*>(q0p);
        float4 q1 = *reinterpret_cast<const float4*>(q1p);
        float4 k0 = *reinterpret_cast<const float4*>(k0p);
        float4 k1 = *reinterpret_cast<const float4*>(k1p);
        uint_ h2, l2;
        split_bf16(q0.x, q1.x, h2, l2); Qph[(e4 + 0) * 17 + cp] = h2; Qpl[(e4 + 0) * 17 + cp] = l2;
        split_bf16(q0.y, q1.y, h2, l2); Qph[(e4 + 1) * 17 + cp] = h2; Qpl[(e4 + 1) * 17 + cp] = l2;
        split_bf16(q0.z, q1.z, h2, l2); Qph[(e4 + 2) * 17 + cp] = h2; Qpl[(e4 + 2) * 17 + cp] = l2;
        split_bf16(q0.w, q1.w, h2, l2); Qph[(e4 + 3) * 17 + cp] = h2; Qpl[(e4 + 3) * 17 + cp] = l2;
        uint_ kh[4], kl[4];
        split_bf16(k0.x, k1.x, kh[0], kl[0]);
        split_bf16(k0.y, k1.y, kh[1], kl[1]);
        split_bf16(k0.z, k1.z, kh[2], kl[2]);
        split_bf16(k0.w, k1.w, kh[3], kl[3]);
        *reinterpret_cast<uint4*>(&Kph[cp * 132 + e4]) = make_uint4(kh[0], kh[1], kh[2], kh[3]);
        *reinterpret_cast<uint4*>(&Kpl[cp * 132 + e4]) = make_uint4(kl[0], kl[1], kl[2], kl[3]);
    }
    // ---- V loads: per (c, pixel-quad), 1 x float4; 32 c x 32 quads = 1024 ----
#pragma unroll
    for (int it = 0; it < 4; it++) {
        int idx = tid + it * 256;                 // 0..1023
        int c = idx >> 5, p4 = (idx & 31) * 4;    // 4 pixels = 2 ip pairs
        float4 v4 = *reinterpret_cast<const float4*>(&vin[base + (size_t)c * HW_ + p4]);
        uint_ h0, l0, h1, l1;
        split_bf16(v4.x, v4.y, h0, l0);
        split_bf16(v4.z, v4.w, h1, l1);
        int ip = p4 >> 1;
        *reinterpret_cast<uint2*>(&Vph[c * 66 + ip]) = make_uint2(h0, h1);
        *reinterpret_cast<uint2*>(&Vpl[c * 66 + ip]) = make_uint2(l0, l1);
    }
    __syncthreads();

    int r0 = warp * 16 + g;
    int r1 = r0 + 8;

    float dE[16][4];
#pragma unroll
    for (int nt = 0; nt < 16; nt++)
#pragma unroll
        for (int u = 0; u < 4; u++) dE[nt][u] = 0.f;

#pragma unroll
    for (int ks = 0; ks < 2; ks++) {
        int kpb = ks * 8;
        uint_ ah[4], al[4];
        ah[0] = Qph[r0 * 17 + kpb + tg];
        ah[1] = Qph[r1 * 17 + kpb + tg];
        ah[2] = Qph[r0 * 17 + kpb + tg + 4];
        ah[3] = Qph[r1 * 17 + kpb + tg + 4];
        al[0] = Qpl[r0 * 17 + kpb + tg];
        al[1] = Qpl[r1 * 17 + kpb + tg];
        al[2] = Qpl[r0 * 17 + kpb + tg + 4];
        al[3] = Qpl[r1 * 17 + kpb + tg + 4];
#pragma unroll
        for (int nt = 0; nt < 16; nt++) {
            int n = nt * 8 + g;
            uint_ bh[2], bl[2];
            bh[0] = Kph[(kpb + tg) * 132 + n];
            bh[1] = Kph[(kpb + tg + 4) * 132 + n];
            bl[0] = Kpl[(kpb + tg) * 132 + n];
            bl[1] = Kpl[(kpb + tg + 4) * 132 + n];
            mma_bf16(dE[nt], ah, bh);
            mma_bf16(dE[nt], ah, bl);
            mma_bf16(dE[nt], al, bh);
        }
    }

    if (transposed) {
#pragma unroll
        for (int nt = 0; nt < 16; nt++) {
            int c0 = nt * 8 + 2 * tg, c1 = c0 + 1;
            if (c0 == r0) dE[nt][0] = -1e30f;
            if (c1 == r0) dE[nt][1] = -1e30f;
            if (c0 == r1) dE[nt][2] = -1e30f;
            if (c1 == r1) dE[nt][3] = -1e30f;
        }
    }

    float m0 = -1e30f, m1 = -1e30f;
#pragma unroll
    for (int nt = 0; nt < 16; nt++) {
        m0 = fmaxf(m0, fmaxf(dE[nt][0], dE[nt][1]));
        m1 = fmaxf(m1, fmaxf(dE[nt][2], dE[nt][3]));
    }
    m0 = fmaxf(m0, __shfl_xor_sync(0xffffffffu, m0, 1));
    m0 = fmaxf(m0, __shfl_xor_sync(0xffffffffu, m0, 2));
    m1 = fmaxf(m1, __shfl_xor_sync(0xffffffffu, m1, 1));
    m1 = fmaxf(m1, __shfl_xor_sync(0xffffffffu, m1, 2));

    float s0 = 0.f, s1 = 0.f;
#pragma unroll
    for (int nt = 0; nt < 16; nt++) {
        dE[nt][0] = __expf(dE[nt][0] - m0);
        dE[nt][1] = __expf(dE[nt][1] - m0);
        dE[nt][2] = __expf(dE[nt][2] - m1);
        dE[nt][3] = __expf(dE[nt][3] - m1);
        s0 += dE[nt][0] + dE[nt][1];
        s1 += dE[nt][2] + dE[nt][3];
    }
    s0 += __shfl_xor_sync(0xffffffffu, s0, 1);
    s0 += __shfl_xor_sync(0xffffffffu, s0, 2);
    s1 += __shfl_xor_sync(0xffffffffu, s1, 1);
    s1 += __shfl_xor_sync(0xffffffffu, s1, 2);

    if (tg == 0) {
        size_t s0i = transposed ? ((size_t)(b * H_ + r0) * W_ + X)
                                : ((size_t)(b * H_ + X) * W_ + r0);
        size_t s1i = transposed ? ((size_t)(b * H_ + r1) * W_ + X)
                                : ((size_t)(b * H_ + X) * W_ + r1);
        mstat[s0i] = m0;  sstat[s0i] = s0;
        mstat[s1i] = m1;  sstat[s1i] = s1;
    }

    float dO[4][4];
#pragma unroll
    for (int nt = 0; nt < 4; nt++)
#pragma unroll
        for (int u = 0; u < 4; u++) dO[nt][u] = 0.f;

#pragma unroll
    for (int kb = 0; kb < 8; kb++) {
        uint_ ah[4], al[4];
        split_bf16(dE[2 * kb][0],     dE[2 * kb][1],     ah[0], al[0]);
        split_bf16(dE[2 * kb][2],     dE[2 * kb][3],     ah[1], al[1]);
        split_bf16(dE[2 * kb + 1][0], dE[2 * kb + 1][1], ah[2], al[2]);
        split_bf16(dE[2 * kb + 1][2], dE[2 * kb + 1][3], ah[3], al[3]);
#pragma unroll
        for (int nt = 0; nt < 4; nt++) {
            int c = nt * 8 + g;
            uint_ bh[2], bl[2];
            bh[0] = Vph[c * 66 + 8 * kb + tg];
            bh[1] = Vph[c * 66 + 8 * kb + tg + 4];
            bl[0] = Vpl[c * 66 + 8 * kb + tg];
            bl[1] = Vpl[c * 66 + 8 * kb + tg + 4];
            mma_bf16(dO[nt], ah, bh);
            mma_bf16(dO[nt], ah, bl);
            mma_bf16(dO[nt], al, bh);
        }
    }

    __syncthreads();
#pragma unroll
    for (int nt = 0; nt < 4; nt++) {
        int c0 = nt * 8 + 2 * tg;
        stg[c0 * 130 + r0]       = dO[nt][0];
        stg[(c0 + 1) * 130 + r0] = dO[nt][1];
        stg[c0 * 130 + r1]       = dO[nt][2];
        stg[(c0 + 1) * 130 + r1] = dO[nt][3];
    }
    __syncthreads();
    for (int idx = tid; idx < CR_ * 128; idx += 256) {
        int c = idx >> 7, e = idx & 127;
        outp[base + (size_t)c * HW_ + e] = stg[c * 130 + e];
    }
}

// ---------------- kernel 4: combine via mma.sync bf16-split -------------------
#define CB_WZH  0
#define CB_WZL  (256 * 18)
#define CB_MGH  (2 * 256 * 18)
#define CB_MGL  (2 * 256 * 18 + 16 * 132)
#define CB_F    (2 * 256 * 18 + 2 * 16 * 132)
#define COMB_SMEM ((2 * 256 * 18 + 2 * 16 * 132 + 256) * 4)

__global__ void __launch_bounds__(512) combine_kernel(
    const float* __restrict__ x, const float* __restrict__ Wz,
    const float* __restrict__ bz, float* __restrict__ out)
{
    extern __shared__ uint_ cu[];
    uint_* Wzh = cu + CB_WZH;
    uint_* Wzl = cu + CB_WZL;
    uint_* Mgh = cu + CB_MGH;
    uint_* Mgl = cu + CB_MGL;
    float* fH  = reinterpret_cast<float*>(cu + CB_F);
    float* fW  = fH + 128;

    int h = blockIdx.x, b = blockIdx.y;
    int tid = threadIdx.x;
    int wp = tid >> 5, lane = tid & 31;
    int g = lane >> 2, tg = lane & 3;
    int wm = wp >> 2, wn = wp & 3;
    int m0 = wm * 64, n0 = wn * 32;

    if (tid < 128) {
        int w = tid;
        size_t sidx = (size_t)(b * H_ + h) * W_ + w;
        float mh = g_mH[sidx], mw = g_mW[sidx];
        float sh = g_sH[sidx], sw = g_sW[sidx];
        float m  = fmaxf(mh, mw);
        float eh = __expf(mh - m), ew = __expf(mw - m);
        float inv = 1.0f / (sh * eh + sw * ew);
        fH[w] = eh * inv;
        fW[w] = ew * inv;
    }
    for (int idx = tid; idx < 256 * 8; idx += 512) {
        int r = idx >> 3, f4 = idx & 7;
        float4 w4 = *reinterpret_cast<const float4*>(&Wz[r * 32 + 4 * f4]);
        uint_ h0, l0, h1, l1;
        split_bf16(w4.x, w4.y, h0, l0);
        split_bf16(w4.z, w4.w, h1, l1);
        Wzh[r * 18 + 2 * f4]     = h0;
        Wzh[r * 18 + 2 * f4 + 1] = h1;
        Wzl[r * 18 + 2 * f4]     = l0;
        Wzl[r * 18 + 2 * f4 + 1] = l1;
    }
    __syncthreads();

    for (int idx = tid; idx < 16 * 32; idx += 512) {
        int kp = idx >> 5, w4 = (idx & 31) * 4;
        size_t off0 = (size_t)(b * CR_ + 2 * kp) * HW_ + (size_t)h * W_ + w4;
        size_t off1 = off0 + HW_;
        float4 oh0 = *reinterpret_cast<const float4*>(&g_oHt[off0]);
        float4 ow0 = *reinterpret_cast<const float4*>(&g_oW [off0]);
        float4 oh1 = *reinterpret_cast<const float4*>(&g_oHt[off1]);
        float4 ow1 = *reinterpret_cast<const float4*>(&g_oW [off1]);
        float fh0 = fH[w4], fh1 = fH[w4 + 1], fh2 = fH[w4 + 2], fh3 = fH[w4 + 3];
        float fw0 = fW[w4], fw1 = fW[w4 + 1], fw2 = fW[w4 + 2], fw3 = fW[w4 + 3];
        float c0p0 = oh0.x * fh0 + ow0.x * fw0;
        float c0p1 = oh0.y * fh1 + ow0.y * fw1;
        float c0p2 = oh0.z * fh2 + ow0.z * fw2;
        float c0p3 = oh0.w * fh3 + ow0.w * fw3;
        float c1p0 = oh1.x * fh0 + ow1.x * fw0;
        float c1p1 = oh1.y * fh1 + ow1.y * fw1;
        float c1p2 = oh1.z * fh2 + ow1.z * fw2;
        float c1p3 = oh1.w * fh3 + ow1.w * fw3;
        uint_ hh[4], ll[4];
        split_bf16(c0p0, c1p0, hh[0], ll[0]);
        split_bf16(c0p1, c1p1, hh[1], ll[1]);
        split_bf16(c0p2, c1p2, hh[2], ll[2]);
        split_bf16(c0p3, c1p3, hh[3], ll[3]);
        *reinterpret_cast<uint4*>(&Mgh[kp * 132 + w4]) = make_uint4(hh[0], hh[1], hh[2], hh[3]);
        *reinterpret_cast<uint4*>(&Mgl[kp * 132 + w4]) = make_uint4(ll[0], ll[1], ll[2], ll[3]);
    }
    __syncthreads();

    float acc[4][4][4];
#pragma unroll
    for (int mt = 0; mt < 4; mt++)
#pragma unroll
        for (int nt = 0; nt < 4; nt++)
#pragma unroll
            for (int u = 0; u < 4; u++) acc[mt][nt][u] = 0.f;

#pragma unroll
    for (int ks = 0; ks < 2; ks++) {
        int kpb = ks * 8;
        uint_ bh[4][2], bl[4][2];
#pragma unroll
        for (int nt = 0; nt < 4; nt++) {
            int n = n0 + nt * 8 + g;
            bh[nt][0] = Mgh[(kpb + tg) * 132 + n];
            bh[nt][1] = Mgh[(kpb + tg + 4) * 132 + n];
            bl[nt][0] = Mgl[(kpb + tg) * 132 + n];
            bl[nt][1] = Mgl[(kpb + tg + 4) * 132 + n];
        }
#pragma unroll
        for (int mt = 0; mt < 4; mt++) {
            int m = m0 + mt * 16 + g;
            uint_ ah[4], al[4];
            ah[0] = Wzh[m * 18 + kpb + tg];
            ah[1] = Wzh[(m + 8) * 18 + kpb + tg];
            ah[2] = Wzh[m * 18 + kpb + tg + 4];
            ah[3] = Wzh[(m + 8) * 18 + kpb + tg + 4];
            al[0] = Wzl[m * 18 + kpb + tg];
            al[1] = Wzl[(m + 8) * 18 + kpb + tg];
            al[2] = Wzl[m * 18 + kpb + tg + 4];
            al[3] = Wzl[(m + 8) * 18 + kpb + tg + 4];
#pragma unroll
            for (int nt = 0; nt < 4; nt++) {
                mma_bf16(acc[mt][nt], ah, bh[nt]);
                mma_bf16(acc[mt][nt], ah, bl[nt]);
                mma_bf16(acc[mt][nt], al, bh[nt]);
            }
        }
    }

#pragma unroll
    for (int mt = 0; mt < 4; mt++) {
#pragma unroll
        for (int half = 0; half < 2; half++) {
            int o = m0 + mt * 16 + g + 8 * half;
            float bias = bz[o];
            size_t obase = ((size_t)(b * C_ + o) * H_ + h) * W_;
#pragma unroll
            for (int nt = 0; nt < 4; nt++) {
                int pix = n0 + nt * 8 + 2 * tg;
                float2 xv = *reinterpret_cast<const float2*>(&x[obase + pix]);
                float2 v;
                v.x = acc[mt][nt][2 * half]     + bias + xv.x;
                v.y = acc[mt][nt][2 * half + 1] + bias + xv.y;
                *reinterpret_cast<float2*>(&out[obase + pix]) = v;
            }
        }
    }
}

// ---------------- launch ------------------------------------------------------
extern "C" void kernel_launch(void* const* d_in, const int* in_sizes, int n_in,
                              void* d_out, int out_size)
{
    const float* x  = (const float*)d_in[0];
    const float* Wq = (const float*)d_in[1];
    const float* bq = (const float*)d_in[2];
    const float* Wk = (const float*)d_in[3];
    const float* bk = (const float*)d_in[4];
    const float* Wv = (const float*)d_in[5];
    const float* bv = (const float*)d_in[6];
    const float* Wz = (const float*)d_in[7];
    const float* bz = (const float*)d_in[8];
    float* out = (float*)d_out;

    cudaFuncSetAttribute(proj_mma_kernel, cudaFuncAttributeMaxDynamicSharedMemorySize, PROJ_SMEM);
    cudaFuncSetAttribute(attn_kernel,     cudaFuncAttributeMaxDynamicSharedMemorySize, ATTN_SMEM);
    cudaFuncSetAttribute(combine_kernel,  cudaFuncAttributeMaxDynamicSharedMemorySize, COMB_SMEM);

    proj_mma_kernel<<<dim3(H_, B_), 256, PROJ_SMEM>>>(x, Wq, bq, Wk, bk, Wv, bv);
    transpose_kernel<<<dim3(4, 4, 3 * 256), dim3(32, 8)>>>(0);   // q,k,v -> qt,kt,vt
    attn_kernel<<<dim3(W_, B_), 256, ATTN_SMEM>>>(1);            // H path
    attn_kernel<<<dim3(H_, B_), 256, ATTN_SMEM>>>(0);            // W path
    transpose_kernel<<<dim3(4, 4, 256), dim3(32, 8)>>>(3);       // oH -> oHt
    combine_kernel<<<dim3(H_, B_), 512, COMB_SMEM>>>(x, Wz, bz, out);
}

// round 16
// speedup vs baseline: 2.4132x; 1.0138x over previous
#include <cuda_runtime.h>

typedef unsigned long long ull;
typedef unsigned int uint_;

#define B_   8
#define C_   256
#define H_   128
#define W_   128
#define CR_  32
#define HW_  (H_ * W_)

// ---------------- scratch (device globals; no runtime allocation) -------------
__device__ float g_q  [B_ * CR_ * HW_];   // (b, cr, h, w)
__device__ float g_k  [B_ * CR_ * HW_];
__device__ float g_v  [B_ * CR_ * HW_];
__device__ float g_qt [B_ * CR_ * HW_];   // (b, cr, w, h)
__device__ float g_kt [B_ * CR_ * HW_];
__device__ float g_vt [B_ * CR_ * HW_];
__device__ float g_oH [B_ * CR_ * HW_];   // (b, cr, w, h)
__device__ float g_oHt[B_ * CR_ * HW_];   // (b, cr, h, w)
__device__ float g_oW [B_ * CR_ * HW_];   // (b, cr, h, w)
__device__ float g_mH [B_ * HW_];
__device__ float g_sH [B_ * HW_];
__device__ float g_mW [B_ * HW_];
__device__ float g_sW [B_ * HW_];

// ---------------- packed f32x2 helpers ---------------------------------------
__device__ __forceinline__ ull fma2(ull a, ull b, ull c) {
    ull d;
    asm("fma.rn.f32x2 %0, %1, %2, %3;" : "=l"(d) : "l"(a), "l"(b), "l"(c));
    return d;
}
__device__ __forceinline__ ull splat2(float f) {
    ull r; uint_ u = __float_as_uint(f);
    asm("mov.b64 %0, {%1, %1};" : "=l"(r) : "r"(u));
    return r;
}
__device__ __forceinline__ float2 unpack2(ull u) {
    uint_ lo, hi;
    asm("mov.b64 {%0, %1}, %2;" : "=r"(lo), "=r"(hi) : "l"(u));
    return make_float2(__uint_as_float(lo), __uint_as_float(hi));
}
__device__ __forceinline__ ull ldpair(const float* p) {
    union { float2 f2; ull u; } t;
    t.f2 = *reinterpret_cast<const float2*>(p);
    return t.u;
}

// bf16 hi/lo split: hi2/lo2 pack (elem0 -> low half, elem1 -> high half)
__device__ __forceinline__ void split_bf16(float x0, float x1, uint_& hi2, uint_& lo2) {
    asm("cvt.rn.satfinite.bf16x2.f32 %0, %1, %2;" : "=r"(hi2) : "f"(x1), "f"(x0));
    float h0 = __uint_as_float(hi2 << 16);
    float h1 = __uint_as_float(hi2 & 0xffff0000u);
    float l0 = x0 - h0, l1 = x1 - h1;
    asm("cvt.rn.satfinite.bf16x2.f32 %0, %1, %2;" : "=r"(lo2) : "f"(l1), "f"(l0));
}

// warp-level bf16 MMA: D(16x8,f32) += A(16x16,bf16 row) * B(16x8,bf16 col)
__device__ __forceinline__ void mma_bf16(float* d, const uint_* a, const uint_* b) {
    asm volatile(
        "mma.sync.aligned.m16n8k16.row.col.f32.bf16.bf16.f32 "
        "{%0,%1,%2,%3}, {%4,%5,%6,%7}, {%8,%9}, {%0,%1,%2,%3};"
        : "+f"(d[0]), "+f"(d[1]), "+f"(d[2]), "+f"(d[3])
        : "r"(a[0]), "r"(a[1]), "r"(a[2]), "r"(a[3]), "r"(b[0]), "r"(b[1]));
}

// ---------------- kernel 1: q/k/v projection via mma.sync bf16-split ----------
// grid (H, B), 256 threads. Vectorized float4 streaming of x.
#define PJ_WPH   0
#define PJ_WPL   (96 * 36)
#define PJ_XPH   (2 * 96 * 36)
#define PJ_XPL   (2 * 96 * 36 + 32 * 136)
#define PJ_BIAS  (2 * 96 * 36 + 2 * 32 * 136)
#define PROJ_SMEM ((2 * 96 * 36 + 2 * 32 * 136 + 96) * 4)

__global__ void __launch_bounds__(256, 2) proj_mma_kernel(
    const float* __restrict__ x,
    const float* __restrict__ Wq, const float* __restrict__ bq,
    const float* __restrict__ Wk, const float* __restrict__ bk,
    const float* __restrict__ Wv, const float* __restrict__ bv)
{
    extern __shared__ uint_ ps[];
    uint_* Wph = ps + PJ_WPH;
    uint_* Wpl = ps + PJ_WPL;
    uint_* Xph = ps + PJ_XPH;
    uint_* Xpl = ps + PJ_XPL;
    float* bsm = reinterpret_cast<float*>(ps + PJ_BIAS);

    int h = blockIdx.x, b = blockIdx.y;
    int tid = threadIdx.x;
    int wid = tid >> 5, lane = tid & 31;
    int g = lane >> 2, tg = lane & 3;
    int wm = wid >> 2, wn = wid & 3;
    int m0 = wm * 48, n0 = wn * 32;

    if (tid < 96) {
        float bv_;
        if (tid < 32)      bv_ = bq[tid];
        else if (tid < 64) bv_ = bk[tid - 32];
        else               bv_ = bv[tid - 64];
        bsm[tid] = bv_;
    }

    const float* xb = x + (size_t)b * C_ * HW_ + (size_t)h * W_;

    float acc[3][4][4];
#pragma unroll
    for (int mt = 0; mt < 3; mt++)
#pragma unroll
        for (int nt = 0; nt < 4; nt++)
#pragma unroll
            for (int u = 0; u < 4; u++) acc[mt][nt][u] = 0.f;

    int cpld = tid >> 3;           // 0..31 channel-pair
    int pbld = (tid & 7) * 16;     // pixel strip base

    for (int kc = 0; kc < 4; kc++) {
        if (kc) __syncthreads();
        for (int idx = tid; idx < 96 * 16; idx += 256) {
            int r = idx >> 4, f4 = idx & 15;
            const float* wsrc;
            if (r < 32)      wsrc = Wq + (size_t)r * C_;
            else if (r < 64) wsrc = Wk + (size_t)(r - 32) * C_;
            else             wsrc = Wv + (size_t)(r - 64) * C_;
            float4 w4 = *reinterpret_cast<const float4*>(&wsrc[kc * 64 + 4 * f4]);
            uint_ h0, l0, h1, l1;
            split_bf16(w4.x, w4.y, h0, l0);
            split_bf16(w4.z, w4.w, h1, l1);
            Wph[r * 36 + 2 * f4]     = h0;
            Wph[r * 36 + 2 * f4 + 1] = h1;
            Wpl[r * 36 + 2 * f4]     = l0;
            Wpl[r * 36 + 2 * f4 + 1] = l1;
        }
        {
            const float* x0p = xb + (size_t)(kc * 64 + 2 * cpld) * HW_;
            const float* x1p = x0p + HW_;
#pragma unroll
            for (int it = 0; it < 4; it++) {
                int p = pbld + 4 * it;
                float4 a4 = *reinterpret_cast<const float4*>(&x0p[p]);
                float4 b4 = *reinterpret_cast<const float4*>(&x1p[p]);
                uint_ hh[4], ll[4];
                split_bf16(a4.x, b4.x, hh[0], ll[0]);
                split_bf16(a4.y, b4.y, hh[1], ll[1]);
                split_bf16(a4.z, b4.z, hh[2], ll[2]);
                split_bf16(a4.w, b4.w, hh[3], ll[3]);
                *reinterpret_cast<uint4*>(&Xph[cpld * 136 + p]) =
                    make_uint4(hh[0], hh[1], hh[2], hh[3]);
                *reinterpret_cast<uint4*>(&Xpl[cpld * 136 + p]) =
                    make_uint4(ll[0], ll[1], ll[2], ll[3]);
            }
        }
        __syncthreads();

#pragma unroll
        for (int ks = 0; ks < 4; ks++) {
            int kpb = ks * 8;
            uint_ bh[4][2], bl[4][2];
#pragma unroll
            for (int nt = 0; nt < 4; nt++) {
                int n = n0 + nt * 8 + g;
                bh[nt][0] = Xph[(kpb + tg) * 136 + n];
                bh[nt][1] = Xph[(kpb + tg + 4) * 136 + n];
                bl[nt][0] = Xpl[(kpb + tg) * 136 + n];
                bl[nt][1] = Xpl[(kpb + tg + 4) * 136 + n];
            }
#pragma unroll
            for (int mt = 0; mt < 3; mt++) {
                int m = m0 + mt * 16 + g;
                uint_ ah[4], al[4];
                ah[0] = Wph[m * 36 + kpb + tg];
                ah[1] = Wph[(m + 8) * 36 + kpb + tg];
                ah[2] = Wph[m * 36 + kpb + tg + 4];
                ah[3] = Wph[(m + 8) * 36 + kpb + tg + 4];
                al[0] = Wpl[m * 36 + kpb + tg];
                al[1] = Wpl[(m + 8) * 36 + kpb + tg];
                al[2] = Wpl[m * 36 + kpb + tg + 4];
                al[3] = Wpl[(m + 8) * 36 + kpb + tg + 4];
#pragma unroll
                for (int nt = 0; nt < 4; nt++) {
                    mma_bf16(acc[mt][nt], ah, bh[nt]);
                    mma_bf16(acc[mt][nt], ah, bl[nt]);
                    mma_bf16(acc[mt][nt], al, bh[nt]);
                }
            }
        }
    }

#pragma unroll
    for (int mt = 0; mt < 3; mt++) {
#pragma unroll
        for (int half = 0; half < 2; half++) {
            int r = m0 + mt * 16 + g + 8 * half;
            float bias = bsm[r];
            float* dstb;
            int ch;
            if (r < 32)      { dstb = g_q; ch = r; }
            else if (r < 64) { dstb = g_k; ch = r - 32; }
            else             { dstb = g_v; ch = r - 64; }
            float* drow = dstb + ((size_t)(b * CR_ + ch) * H_ + h) * W_;
#pragma unroll
            for (int nt = 0; nt < 4; nt++) {
                int pix = n0 + nt * 8 + 2 * tg;
                float2 v;
                v.x = acc[mt][nt][2 * half]     + bias;
                v.y = acc[mt][nt][2 * half + 1] + bias;
                *reinterpret_cast<float2*>(&drow[pix]) = v;
            }
        }
    }
}

// ---------------- kernel 2: HxW tile transpose --------------------------------
__global__ void __launch_bounds__(256) transpose_kernel(int base_arr)
{
    __shared__ float tile[32][33];
    int zc = blockIdx.z;
    int arr = base_arr + (zc >> 8), m = zc & 255;
    const float* src; float* dst;
    if      (arr == 0) { src = g_q;  dst = g_qt;  }
    else if (arr == 1) { src = g_k;  dst = g_kt;  }
    else if (arr == 2) { src = g_v;  dst = g_vt;  }
    else               { src = g_oH; dst = g_oHt; }
    src += (size_t)m * HW_;
    dst += (size_t)m * HW_;
    int x0 = blockIdx.x * 32, y0 = blockIdx.y * 32;
    int tx = threadIdx.x, ty = threadIdx.y;
#pragma unroll
    for (int r = 0; r < 32; r += 8)
        tile[ty + r][tx] = src[(size_t)(y0 + ty + r) * W_ + x0 + tx];
    __syncthreads();
#pragma unroll
    for (int r = 0; r < 32; r += 8)
        dst[(size_t)(x0 + ty + r) * H_ + y0 + tx] = tile[tx][ty + r];
}

// ---------------- kernel 3: HMMA attention, fragment-ordered K/V smem --------
// K fragment layout: KF[row = ks*16+nt][g][tg*2+pr], row stride 76 uints.
// V fragment layout: VF[row = kb*4+nt][g][tg*2+pr], row stride 76 uints.
#define AQ_PH  0
#define AQ_PL  2176
#define AKF_H  4352
#define AKF_L  (4352 + 2432)
#define AVF_H  (4352 + 2 * 2432)
#define AVF_L  (4352 + 3 * 2432)
#define ATTN_SMEM ((4352 + 4 * 2432) * 4)

__global__ void __launch_bounds__(256, 2) attn_kernel(int transposed)
{
    extern __shared__ uint_ su[];
    uint_* Qph = su + AQ_PH;
    uint_* Qpl = su + AQ_PL;
    uint_* KFh = su + AKF_H;
    uint_* KFl = su + AKF_L;
    uint_* VFh = su + AVF_H;
    uint_* VFl = su + AVF_L;
    float* stg = reinterpret_cast<float*>(su);

    const float* qin = transposed ? g_qt : g_q;
    const float* kin = transposed ? g_kt : g_k;
    const float* vin = transposed ? g_vt : g_v;
    float* outp  = transposed ? g_oH : g_oW;
    float* mstat = transposed ? g_mH : g_mW;
    float* sstat = transposed ? g_sH : g_sW;

    int X = blockIdx.x, b = blockIdx.y;
    size_t base = (size_t)b * CR_ * HW_ + (size_t)X * W_;
    int tid = threadIdx.x, warp = tid >> 5, lane = tid & 31;
    int g = lane >> 2, tg = lane & 3;

    // ---- Q/K loads: per (cp, e-quad), 2 x float4 each matrix ----
#pragma unroll
    for (int it = 0; it < 2; it++) {
        int idx = tid + it * 256;                 // 0..511
        int cp = idx >> 5, e4 = (idx & 31) * 4;
        int ksw = cp >> 3, tgw = cp & 3, prw = (cp >> 2) & 1;
        const float* q0p = qin + base + (size_t)(2 * cp) * HW_ + e4;
        const float* q1p = q0p + HW_;
        const float* k0p = kin + base + (size_t)(2 * cp) * HW_ + e4;
        const float* k1p = k0p + HW_;
        float4 q0 = *reinterpret_cast<const float4*>(q0p);
        float4 q1 = *reinterpret_cast<const float4*>(q1p);
        float4 k0 = *reinterpret_cast<const float4*>(k0p);
        float4 k1 = *reinterpret_cast<const float4*>(k1p);
        uint_ h2, l2;
        split_bf16(q0.x, q1.x, h2, l2); Qph[(e4 + 0) * 17 + cp] = h2; Qpl[(e4 + 0) * 17 + cp] = l2;
        split_bf16(q0.y, q1.y, h2, l2); Qph[(e4 + 1) * 17 + cp] = h2; Qpl[(e4 + 1) * 17 + cp] = l2;
        split_bf16(q0.z, q1.z, h2, l2); Qph[(e4 + 2) * 17 + cp] = h2; Qpl[(e4 + 2) * 17 + cp] = l2;
        split_bf16(q0.w, q1.w, h2, l2); Qph[(e4 + 3) * 17 + cp] = h2; Qpl[(e4 + 3) * 17 + cp] = l2;
        uint_ kh[4], kl[4];
        split_bf16(k0.x, k1.x, kh[0], kl[0]);
        split_bf16(k0.y, k1.y, kh[1], kl[1]);
        split_bf16(k0.z, k1.z, kh[2], kl[2]);
        split_bf16(k0.w, k1.w, kh[3], kl[3]);
#pragma unroll
        for (int j = 0; j < 4; j++) {
            int e = e4 + j;
            int nt = e >> 3, ge = e & 7;
            int off = (ksw * 16 + nt) * 76 + ge * 8 + tgw * 2 + prw;
            KFh[off] = kh[j];
            KFl[off] = kl[j];
        }
    }
    // ---- V loads: warp-tile = 8 channels x 16 pixels, fragment-order store ----
#pragma unroll
    for (int it = 0; it < 4; it++) {
        int t = warp + it * 8;                    // 0..31 warp-tile
        int cb = (t & 3) * 8, pb = (t >> 2) * 16;
        int c = cb + (lane >> 2);
        int p4 = pb + (lane & 3) * 4;
        float4 v4 = *reinterpret_cast<const float4*>(&vin[base + (size_t)c * HW_ + p4]);
        uint_ h0, l0, h1, l1;
        split_bf16(v4.x, v4.y, h0, l0);
        split_bf16(v4.z, v4.w, h1, l1);
        int ip0 = p4 >> 1;
        int kb = ip0 >> 3;
        int t0 = ip0 & 3, p0 = (ip0 >> 2) & 1;
        int ip1 = ip0 + 1;
        int t1 = ip1 & 3, p1 = (ip1 >> 2) & 1;
        int nt = c >> 3, gv = c & 7;
        int rowbase = (kb * 4 + nt) * 76 + gv * 8;
        VFh[rowbase + t0 * 2 + p0] = h0;
        VFh[rowbase + t1 * 2 + p1] = h1;
        VFl[rowbase + t0 * 2 + p0] = l0;
        VFl[rowbase + t1 * 2 + p1] = l1;
    }
    __syncthreads();

    int r0 = warp * 16 + g;
    int r1 = r0 + 8;

    float dE[16][4];
#pragma unroll
    for (int nt = 0; nt < 16; nt++)
#pragma unroll
        for (int u = 0; u < 4; u++) dE[nt][u] = 0.f;

#pragma unroll
    for (int ks = 0; ks < 2; ks++) {
        int kpb = ks * 8;
        uint_ ah[4], al[4];
        ah[0] = Qph[r0 * 17 + kpb + tg];
        ah[1] = Qph[r1 * 17 + kpb + tg];
        ah[2] = Qph[r0 * 17 + kpb + tg + 4];
        ah[3] = Qph[r1 * 17 + kpb + tg + 4];
        al[0] = Qpl[r0 * 17 + kpb + tg];
        al[1] = Qpl[r1 * 17 + kpb + tg];
        al[2] = Qpl[r0 * 17 + kpb + tg + 4];
        al[3] = Qpl[r1 * 17 + kpb + tg + 4];
#pragma unroll
        for (int nt = 0; nt < 16; nt++) {
            int off = (ks * 16 + nt) * 76 + g * 8 + tg * 2;
            uint2 bh2 = *reinterpret_cast<const uint2*>(&KFh[off]);
            uint2 bl2 = *reinterpret_cast<const uint2*>(&KFl[off]);
            uint_ bh[2] = { bh2.x, bh2.y };
            uint_ bl[2] = { bl2.x, bl2.y };
            mma_bf16(dE[nt], ah, bh);
            mma_bf16(dE[nt], ah, bl);
            mma_bf16(dE[nt], al, bh);
        }
    }

    if (transposed) {
#pragma unroll
        for (int nt = 0; nt < 16; nt++) {
            int c0 = nt * 8 + 2 * tg, c1 = c0 + 1;
            if (c0 == r0) dE[nt][0] = -1e30f;
            if (c1 == r0) dE[nt][1] = -1e30f;
            if (c0 == r1) dE[nt][2] = -1e30f;
            if (c1 == r1) dE[nt][3] = -1e30f;
        }
    }

    float m0 = -1e30f, m1 = -1e30f;
#pragma unroll
    for (int nt = 0; nt < 16; nt++) {
        m0 = fmaxf(m0, fmaxf(dE[nt][0], dE[nt][1]));
        m1 = fmaxf(m1, fmaxf(dE[nt][2], dE[nt][3]));
    }
    m0 = fmaxf(m0, __shfl_xor_sync(0xffffffffu, m0, 1));
    m0 = fmaxf(m0, __shfl_xor_sync(0xffffffffu, m0, 2));
    m1 = fmaxf(m1, __shfl_xor_sync(0xffffffffu, m1, 1));
    m1 = fmaxf(m1, __shfl_xor_sync(0xffffffffu, m1, 2));

    float s0 = 0.f, s1 = 0.f;
#pragma unroll
    for (int nt = 0; nt < 16; nt++) {
        dE[nt][0] = __expf(dE[nt][0] - m0);
        dE[nt][1] = __expf(dE[nt][1] - m0);
        dE[nt][2] = __expf(dE[nt][2] - m1);
        dE[nt][3] = __expf(dE[nt][3] - m1);
        s0 += dE[nt][0] + dE[nt][1];
        s1 += dE[nt][2] + dE[nt][3];
    }
    s0 += __shfl_xor_sync(0xffffffffu, s0, 1);
    s0 += __shfl_xor_sync(0xffffffffu, s0, 2);
    s1 += __shfl_xor_sync(0xffffffffu, s1, 1);
    s1 += __shfl_xor_sync(0xffffffffu, s1, 2);

    if (tg == 0) {
        size_t s0i = transposed ? ((size_t)(b * H_ + r0) * W_ + X)
                                : ((size_t)(b * H_ + X) * W_ + r0);
        size_t s1i = transposed ? ((size_t)(b * H_ + r1) * W_ + X)
                                : ((size_t)(b * H_ + X) * W_ + r1);
        mstat[s0i] = m0;  sstat[s0i] = s0;
        mstat[s1i] = m1;  sstat[s1i] = s1;
    }

    float dO[4][4];
#pragma unroll
    for (int nt = 0; nt < 4; nt++)
#pragma unroll
        for (int u = 0; u < 4; u++) dO[nt][u] = 0.f;

#pragma unroll
    for (int kb = 0; kb < 8; kb++) {
        uint_ ah[4], al[4];
        split_bf16(dE[2 * kb][0],     dE[2 * kb][1],     ah[0], al[0]);
        split_bf16(dE[2 * kb][2],     dE[2 * kb][3],     ah[1], al[1]);
        split_bf16(dE[2 * kb + 1][0], dE[2 * kb + 1][1], ah[2], al[2]);
        split_bf16(dE[2 * kb + 1][2], dE[2 * kb + 1][3], ah[3], al[3]);
#pragma unroll
        for (int nt = 0; nt < 4; nt++) {
            int off = (kb * 4 + nt) * 76 + g * 8 + tg * 2;
            uint2 bh2 = *reinterpret_cast<const uint2*>(&VFh[off]);
            uint2 bl2 = *reinterpret_cast<const uint2*>(&VFl[off]);
            uint_ bh[2] = { bh2.x, bh2.y };
            uint_ bl[2] = { bl2.x, bl2.y };
            mma_bf16(dO[nt], ah, bh);
            mma_bf16(dO[nt], ah, bl);
            mma_bf16(dO[nt], al, bh);
        }
    }

    __syncthreads();
#pragma unroll
    for (int nt = 0; nt < 4; nt++) {
        int c0 = nt * 8 + 2 * tg;
        stg[c0 * 130 + r0]       = dO[nt][0];
        stg[(c0 + 1) * 130 + r0] = dO[nt][1];
        stg[c0 * 130 + r1]       = dO[nt][2];
        stg[(c0 + 1) * 130 + r1] = dO[nt][3];
    }
    __syncthreads();
    for (int idx = tid; idx < CR_ * 128; idx += 256) {
        int c = idx >> 7, e = idx & 127;
        outp[base + (size_t)c * HW_ + e] = stg[c * 130 + e];
    }
}

// ---------------- kernel 4: combine via mma.sync bf16-split -------------------
#define CB_WZH  0
#define CB_WZL  (256 * 18)
#define CB_MGH  (2 * 256 * 18)
#define CB_MGL  (2 * 256 * 18 + 16 * 132)
#define CB_F    (2 * 256 * 18 + 2 * 16 * 132)
#define COMB_SMEM ((2 * 256 * 18 + 2 * 16 * 132 + 256) * 4)

__global__ void __launch_bounds__(512) combine_kernel(
    const float* __restrict__ x, const float* __restrict__ Wz,
    const float* __restrict__ bz, float* __restrict__ out)
{
    extern __shared__ uint_ cu[];
    uint_* Wzh = cu + CB_WZH;
    uint_* Wzl = cu + CB_WZL;
    uint_* Mgh = cu + CB_MGH;
    uint_* Mgl = cu + CB_MGL;
    float* fH  = reinterpret_cast<float*>(cu + CB_F);
    float* fW  = fH + 128;

    int h = blockIdx.x, b = blockIdx.y;
    int tid = threadIdx.x;
    int wp = tid >> 5, lane = tid & 31;
    int g = lane >> 2, tg = lane & 3;
    int wm = wp >> 2, wn = wp & 3;
    int m0 = wm * 64, n0 = wn * 32;

    if (tid < 128) {
        int w = tid;
        size_t sidx = (size_t)(b * H_ + h) * W_ + w;
        float mh = g_mH[sidx], mw = g_mW[sidx];
        float sh = g_sH[sidx], sw = g_sW[sidx];
        float m  = fmaxf(mh, mw);
        float eh = __expf(mh - m), ew = __expf(mw - m);
        float inv = 1.0f / (sh * eh + sw * ew);
        fH[w] = eh * inv;
        fW[w] = ew * inv;
    }
    for (int idx = tid; idx < 256 * 8; idx += 512) {
        int r = idx >> 3, f4 = idx & 7;
        float4 w4 = *reinterpret_cast<const float4*>(&Wz[r * 32 + 4 * f4]);
        uint_ h0, l0, h1, l1;
        split_bf16(w4.x, w4.y, h0, l0);
        split_bf16(w4.z, w4.w, h1, l1);
        Wzh[r * 18 + 2 * f4]     = h0;
        Wzh[r * 18 + 2 * f4 + 1] = h1;
        Wzl[r * 18 + 2 * f4]     = l0;
        Wzl[r * 18 + 2 * f4 + 1] = l1;
    }
    __syncthreads();

    for (int idx = tid; idx < 16 * 32; idx += 512) {
        int kp = idx >> 5, w4 = (idx & 31) * 4;
        size_t off0 = (size_t)(b * CR_ + 2 * kp) * HW_ + (size_t)h * W_ + w4;
        size_t off1 = off0 + HW_;
        float4 oh0 = *reinterpret_cast<const float4*>(&g_oHt[off0]);
        float4 ow0 = *reinterpret_cast<const float4*>(&g_oW [off0]);
        float4 oh1 = *reinterpret_cast<const float4*>(&g_oHt[off1]);
        float4 ow1 = *reinterpret_cast<const float4*>(&g_oW [off1]);
        float fh0 = fH[w4], fh1 = fH[w4 + 1], fh2 = fH[w4 + 2], fh3 = fH[w4 + 3];
        float fw0 = fW[w4], fw1 = fW[w4 + 1], fw2 = fW[w4 + 2], fw3 = fW[w4 + 3];
        float c0p0 = oh0.x * fh0 + ow0.x * fw0;
        float c0p1 = oh0.y * fh1 + ow0.y * fw1;
        float c0p2 = oh0.z * fh2 + ow0.z * fw2;
        float c0p3 = oh0.w * fh3 + ow0.w * fw3;
        float c1p0 = oh1.x * fh0 + ow1.x * fw0;
        float c1p1 = oh1.y * fh1 + ow1.y * fw1;
        float c1p2 = oh1.z * fh2 + ow1.z * fw2;
        float c1p3 = oh1.w * fh3 + ow1.w * fw3;
        uint_ hh[4], ll[4];
        split_bf16(c0p0, c1p0, hh[0], ll[0]);
        split_bf16(c0p1, c1p1, hh[1], ll[1]);
        split_bf16(c0p2, c1p2, hh[2], ll[2]);
        split_bf16(c0p3, c1p3, hh[3], ll[3]);
        *reinterpret_cast<uint4*>(&Mgh[kp * 132 + w4]) = make_uint4(hh[0], hh[1], hh[2], hh[3]);
        *reinterpret_cast<uint4*>(&Mgl[kp * 132 + w4]) = make_uint4(ll[0], ll[1], ll[2], ll[3]);
    }
    __syncthreads();

    float acc[4][4][4];
#pragma unroll
    for (int mt = 0; mt < 4; mt++)
#pragma unroll
        for (int nt = 0; nt < 4; nt++)
#pragma unroll
            for (int u = 0; u < 4; u++) acc[mt][nt][u] = 0.f;

#pragma unroll
    for (int ks = 0; ks < 2; ks++) {
        int kpb = ks * 8;
        uint_ bh[4][2], bl[4][2];
#pragma unroll
        for (int nt = 0; nt < 4; nt++) {
            int n = n0 + nt * 8 + g;
            bh[nt][0] = Mgh[(kpb + tg) * 132 + n];
            bh[nt][1] = Mgh[(kpb + tg + 4) * 132 + n];
            bl[nt][0] = Mgl[(kpb + tg) * 132 + n];
            bl[nt][1] = Mgl[(kpb + tg + 4) * 132 + n];
        }
#pragma unroll
        for (int mt = 0; mt < 4; mt++) {
            int m = m0 + mt * 16 + g;
            uint_ ah[4], al[4];
            ah[0] = Wzh[m * 18 + kpb + tg];
            ah[1] = Wzh[(m + 8) * 18 + kpb + tg];
            ah[2] = Wzh[m * 18 + kpb + tg + 4];
            ah[3] = Wzh[(m + 8) * 18 + kpb + tg + 4];
            al[0] = Wzl[m * 18 + kpb + tg];
            al[1] = Wzl[(m + 8) * 18 + kpb + tg];
            al[2] = Wzl[m * 18 + kpb + tg + 4];
            al[3] = Wzl[(m + 8) * 18 + kpb + tg + 4];
#pragma unroll
            for (int nt = 0; nt < 4; nt++) {
                mma_bf16(acc[mt][nt], ah, bh[nt]);
                mma_bf16(acc[mt][nt], ah, bl[nt]);
                mma_bf16(acc[mt][nt], al, bh[nt]);
            }
        }
    }

#pragma unroll
    for (int mt = 0; mt < 4; mt++) {
#pragma unroll
        for (int half = 0; half < 2; half++) {
            int o = m0 + mt * 16 + g + 8 * half;
            float bias = bz[o];
            size_t obase = ((size_t)(b * C_ + o) * H_ + h) * W_;
#pragma unroll
            for (int nt = 0; nt < 4; nt++) {
                int pix = n0 + nt * 8 + 2 * tg;
                float2 xv = *reinterpret_cast<const float2*>(&x[obase + pix]);
                float2 v;
                v.x = acc[mt][nt][2 * half]     + bias + xv.x;
                v.y = acc[mt][nt][2 * half + 1] + bias + xv.y;
                *reinterpret_cast<float2*>(&out[obase + pix]) = v;
            }
        }
    }
}

// ---------------- launch ------------------------------------------------------
extern "C" void kernel_launch(void* const* d_in, const int* in_sizes, int n_in,
                              void* d_out, int out_size)
{
    const float* x  = (const float*)d_in[0];
    const float* Wq = (const float*)d_in[1];
    const float* bq = (const float*)d_in[2];
    const float* Wk = (const float*)d_in[3];
    const float* bk = (const float*)d_in[4];
    const float* Wv = (const float*)d_in[5];
    const float* bv = (const float*)d_in[6];
    const float* Wz = (const float*)d_in[7];
    const float* bz = (const float*)d_in[8];
    float* out = (float*)d_out;

    cudaFuncSetAttribute(proj_mma_kernel, cudaFuncAttributeMaxDynamicSharedMemorySize, PROJ_SMEM);
    cudaFuncSetAttribute(attn_kernel,     cudaFuncAttributeMaxDynamicSharedMemorySize, ATTN_SMEM);
    cudaFuncSetAttribute(combine_kernel,  cudaFuncAttributeMaxDynamicSharedMemorySize, COMB_SMEM);

    proj_mma_kernel<<<dim3(H_, B_), 256, PROJ_SMEM>>>(x, Wq, bq, Wk, bk, Wv, bv);
    transpose_kernel<<<dim3(4, 4, 3 * 256), dim3(32, 8)>>>(0);   // q,k,v -> qt,kt,vt
    attn_kernel<<<dim3(W_, B_), 256, ATTN_SMEM>>>(1);            // H path
    attn_kernel<<<dim3(H_, B_), 256, ATTN_SMEM>>>(0);            // W path
    transpose_kernel<<<dim3(4, 4, 256), dim3(32, 8)>>>(3);       // oH -> oHt
    combine_kernel<<<dim3(H_, B_), 512, COMB_SMEM>>>(x, Wz, bz, out);
}

// round 17
// speedup vs baseline: 2.4763x; 1.0261x over previous
#include <cuda_runtime.h>

typedef unsigned long long ull;
typedef unsigned int uint_;

#define B_   8
#define C_   256
#define H_   128
#define W_   128
#define CR_  32
#define HW_  (H_ * W_)

// ---------------- scratch (device globals; no runtime allocation) -------------
__device__ float g_q  [B_ * CR_ * HW_];   // (b, cr, h, w)
__device__ float g_k  [B_ * CR_ * HW_];
__device__ float g_v  [B_ * CR_ * HW_];
__device__ float g_qt [B_ * CR_ * HW_];   // (b, cr, w, h)
__device__ float g_kt [B_ * CR_ * HW_];
__device__ float g_vt [B_ * CR_ * HW_];
__device__ float g_oH [B_ * CR_ * HW_];   // (b, cr, w, h)
__device__ float g_oHt[B_ * CR_ * HW_];   // (b, cr, h, w)
__device__ float g_oW [B_ * CR_ * HW_];   // (b, cr, h, w)
__device__ float g_mH [B_ * HW_];
__device__ float g_sH [B_ * HW_];
__device__ float g_mW [B_ * HW_];
__device__ float g_sW [B_ * HW_];

// ---------------- helpers -----------------------------------------------------
__device__ __forceinline__ void split_bf16(float x0, float x1, uint_& hi2, uint_& lo2) {
    asm("cvt.rn.satfinite.bf16x2.f32 %0, %1, %2;" : "=r"(hi2) : "f"(x1), "f"(x0));
    float h0 = __uint_as_float(hi2 << 16);
    float h1 = __uint_as_float(hi2 & 0xffff0000u);
    float l0 = x0 - h0, l1 = x1 - h1;
    asm("cvt.rn.satfinite.bf16x2.f32 %0, %1, %2;" : "=r"(lo2) : "f"(l1), "f"(l0));
}

__device__ __forceinline__ void mma_bf16(float* d, const uint_* a, const uint_* b) {
    asm volatile(
        "mma.sync.aligned.m16n8k16.row.col.f32.bf16.bf16.f32 "
        "{%0,%1,%2,%3}, {%4,%5,%6,%7}, {%8,%9}, {%0,%1,%2,%3};"
        : "+f"(d[0]), "+f"(d[1]), "+f"(d[2]), "+f"(d[3])
        : "r"(a[0]), "r"(a[1]), "r"(a[2]), "r"(a[3]), "r"(b[0]), "r"(b[1]));
}

// ---------------- kernel 1: proj, pixel-sliced (grid (H,B,2), 256 thr) --------
// CTA computes 96 out rows x 64 pixels. 3 CTAs/SM.
#define PJ_WPH   0
#define PJ_WPL   (96 * 36)
#define PJ_XPH   (2 * 96 * 36)
#define PJ_XPL   (2 * 96 * 36 + 32 * 72)
#define PJ_BIAS  (2 * 96 * 36 + 2 * 32 * 72)
#define PROJ_SMEM ((2 * 96 * 36 + 2 * 32 * 72 + 96) * 4)

__global__ void __launch_bounds__(256, 3) proj_mma_kernel(
    const float* __restrict__ x,
    const float* __restrict__ Wq, const float* __restrict__ bq,
    const float* __restrict__ Wk, const float* __restrict__ bk,
    const float* __restrict__ Wv, const float* __restrict__ bv)
{
    extern __shared__ uint_ ps[];
    uint_* Wph = ps + PJ_WPH;
    uint_* Wpl = ps + PJ_WPL;
    uint_* Xph = ps + PJ_XPH;
    uint_* Xpl = ps + PJ_XPL;
    float* bsm = reinterpret_cast<float*>(ps + PJ_BIAS);

    int h = blockIdx.x, b = blockIdx.y;
    int pbase = blockIdx.z * 64;
    int tid = threadIdx.x;
    int wid = tid >> 5, lane = tid & 31;
    int g = lane >> 2, tg = lane & 3;
    int wm = wid >> 2, wn = wid & 3;
    int m0 = wm * 48, n0 = wn * 16;

    if (tid < 96) {
        float bv_;
        if (tid < 32)      bv_ = bq[tid];
        else if (tid < 64) bv_ = bk[tid - 32];
        else               bv_ = bv[tid - 64];
        bsm[tid] = bv_;
    }

    const float* xb = x + (size_t)b * C_ * HW_ + (size_t)h * W_ + pbase;

    float acc[3][2][4];
#pragma unroll
    for (int mt = 0; mt < 3; mt++)
#pragma unroll
        for (int nt = 0; nt < 2; nt++)
#pragma unroll
            for (int u = 0; u < 4; u++) acc[mt][nt][u] = 0.f;

    int cpld = tid >> 3;           // 0..31 channel-pair
    int pb   = (tid & 7) * 8;      // pixel sub-strip

    for (int kc = 0; kc < 4; kc++) {
        if (kc) __syncthreads();
        for (int idx = tid; idx < 96 * 16; idx += 256) {
            int r = idx >> 4, f4 = idx & 15;
            const float* wsrc;
            if (r < 32)      wsrc = Wq + (size_t)r * C_;
            else if (r < 64) wsrc = Wk + (size_t)(r - 32) * C_;
            else             wsrc = Wv + (size_t)(r - 64) * C_;
            float4 w4 = *reinterpret_cast<const float4*>(&wsrc[kc * 64 + 4 * f4]);
            uint_ h0, l0, h1, l1;
            split_bf16(w4.x, w4.y, h0, l0);
            split_bf16(w4.z, w4.w, h1, l1);
            Wph[r * 36 + 2 * f4]     = h0;
            Wph[r * 36 + 2 * f4 + 1] = h1;
            Wpl[r * 36 + 2 * f4]     = l0;
            Wpl[r * 36 + 2 * f4 + 1] = l1;
        }
        {
            const float* x0p = xb + (size_t)(kc * 64 + 2 * cpld) * HW_;
            const float* x1p = x0p + HW_;
#pragma unroll
            for (int it = 0; it < 2; it++) {
                int p = pb + 4 * it;
                float4 a4 = *reinterpret_cast<const float4*>(&x0p[p]);
                float4 b4 = *reinterpret_cast<const float4*>(&x1p[p]);
                uint_ hh[4], ll[4];
                split_bf16(a4.x, b4.x, hh[0], ll[0]);
                split_bf16(a4.y, b4.y, hh[1], ll[1]);
                split_bf16(a4.z, b4.z, hh[2], ll[2]);
                split_bf16(a4.w, b4.w, hh[3], ll[3]);
                *reinterpret_cast<uint4*>(&Xph[cpld * 72 + p]) =
                    make_uint4(hh[0], hh[1], hh[2], hh[3]);
                *reinterpret_cast<uint4*>(&Xpl[cpld * 72 + p]) =
                    make_uint4(ll[0], ll[1], ll[2], ll[3]);
            }
        }
        __syncthreads();

#pragma unroll
        for (int ks = 0; ks < 4; ks++) {
            int kpb = ks * 8;
            uint_ bh[2][2], bl[2][2];
#pragma unroll
            for (int nt = 0; nt < 2; nt++) {
                int n = n0 + nt * 8 + g;
                bh[nt][0] = Xph[(kpb + tg) * 72 + n];
                bh[nt][1] = Xph[(kpb + tg + 4) * 72 + n];
                bl[nt][0] = Xpl[(kpb + tg) * 72 + n];
                bl[nt][1] = Xpl[(kpb + tg + 4) * 72 + n];
            }
#pragma unroll
            for (int mt = 0; mt < 3; mt++) {
                int m = m0 + mt * 16 + g;
                uint_ ah[4], al[4];
                ah[0] = Wph[m * 36 + kpb + tg];
                ah[1] = Wph[(m + 8) * 36 + kpb + tg];
                ah[2] = Wph[m * 36 + kpb + tg + 4];
                ah[3] = Wph[(m + 8) * 36 + kpb + tg + 4];
                al[0] = Wpl[m * 36 + kpb + tg];
                al[1] = Wpl[(m + 8) * 36 + kpb + tg];
                al[2] = Wpl[m * 36 + kpb + tg + 4];
                al[3] = Wpl[(m + 8) * 36 + kpb + tg + 4];
#pragma unroll
                for (int nt = 0; nt < 2; nt++) {
                    mma_bf16(acc[mt][nt], ah, bh[nt]);
                    mma_bf16(acc[mt][nt], ah, bl[nt]);
                    mma_bf16(acc[mt][nt], al, bh[nt]);
                }
            }
        }
    }

#pragma unroll
    for (int mt = 0; mt < 3; mt++) {
#pragma unroll
        for (int half = 0; half < 2; half++) {
            int r = m0 + mt * 16 + g + 8 * half;
            float bias = bsm[r];
            float* dstb;
            int ch;
            if (r < 32)      { dstb = g_q; ch = r; }
            else if (r < 64) { dstb = g_k; ch = r - 32; }
            else             { dstb = g_v; ch = r - 64; }
            float* drow = dstb + ((size_t)(b * CR_ + ch) * H_ + h) * W_;
#pragma unroll
            for (int nt = 0; nt < 2; nt++) {
                int pix = pbase + n0 + nt * 8 + 2 * tg;
                float2 v;
                v.x = acc[mt][nt][2 * half]     + bias;
                v.y = acc[mt][nt][2 * half + 1] + bias;
                *reinterpret_cast<float2*>(&drow[pix]) = v;
            }
        }
    }
}

// ---------------- kernel 2: HxW tile transpose --------------------------------
__global__ void __launch_bounds__(256) transpose_kernel(int base_arr)
{
    __shared__ float tile[32][33];
    int zc = blockIdx.z;
    int arr = base_arr + (zc >> 8), m = zc & 255;
    const float* src; float* dst;
    if      (arr == 0) { src = g_q;  dst = g_qt;  }
    else if (arr == 1) { src = g_k;  dst = g_kt;  }
    else if (arr == 2) { src = g_v;  dst = g_vt;  }
    else               { src = g_oH; dst = g_oHt; }
    src += (size_t)m * HW_;
    dst += (size_t)m * HW_;
    int x0 = blockIdx.x * 32, y0 = blockIdx.y * 32;
    int tx = threadIdx.x, ty = threadIdx.y;
#pragma unroll
    for (int r = 0; r < 32; r += 8)
        tile[ty + r][tx] = src[(size_t)(y0 + ty + r) * W_ + x0 + tx];
    __syncthreads();
#pragma unroll
    for (int r = 0; r < 32; r += 8)
        dst[(size_t)(x0 + ty + r) * H_ + y0 + tx] = tile[tx][ty + r];
}

// ---------------- kernel 3: HMMA attention (round-16, unchanged) --------------
#define AQ_PH  0
#define AQ_PL  2176
#define AKF_H  4352
#define AKF_L  (4352 + 2432)
#define AVF_H  (4352 + 2 * 2432)
#define AVF_L  (4352 + 3 * 2432)
#define ATTN_SMEM ((4352 + 4 * 2432) * 4)

__global__ void __launch_bounds__(256, 2) attn_kernel(int transposed)
{
    extern __shared__ uint_ su[];
    uint_* Qph = su + AQ_PH;
    uint_* Qpl = su + AQ_PL;
    uint_* KFh = su + AKF_H;
    uint_* KFl = su + AKF_L;
    uint_* VFh = su + AVF_H;
    uint_* VFl = su + AVF_L;
    float* stg = reinterpret_cast<float*>(su);

    const float* qin = transposed ? g_qt : g_q;
    const float* kin = transposed ? g_kt : g_k;
    const float* vin = transposed ? g_vt : g_v;
    float* outp  = transposed ? g_oH : g_oW;
    float* mstat = transposed ? g_mH : g_mW;
    float* sstat = transposed ? g_sH : g_sW;

    int X = blockIdx.x, b = blockIdx.y;
    size_t base = (size_t)b * CR_ * HW_ + (size_t)X * W_;
    int tid = threadIdx.x, warp = tid >> 5, lane = tid & 31;
    int g = lane >> 2, tg = lane & 3;

#pragma unroll
    for (int it = 0; it < 2; it++) {
        int idx = tid + it * 256;
        int cp = idx >> 5, e4 = (idx & 31) * 4;
        int ksw = cp >> 3, tgw = cp & 3, prw = (cp >> 2) & 1;
        const float* q0p = qin + base + (size_t)(2 * cp) * HW_ + e4;
        const float* q1p = q0p + HW_;
        const float* k0p = kin + base + (size_t)(2 * cp) * HW_ + e4;
        const float* k1p = k0p + HW_;
        float4 q0 = *reinterpret_cast<const float4*>(q0p);
        float4 q1 = *reinterpret_cast<const float4*>(q1p);
        float4 k0 = *reinterpret_cast<const float4*>(k0p);
        float4 k1 = *reinterpret_cast<const float4*>(k1p);
        uint_ h2, l2;
        split_bf16(q0.x, q1.x, h2, l2); Qph[(e4 + 0) * 17 + cp] = h2; Qpl[(e4 + 0) * 17 + cp] = l2;
        split_bf16(q0.y, q1.y, h2, l2); Qph[(e4 + 1) * 17 + cp] = h2; Qpl[(e4 + 1) * 17 + cp] = l2;
        split_bf16(q0.z, q1.z, h2, l2); Qph[(e4 + 2) * 17 + cp] = h2; Qpl[(e4 + 2) * 17 + cp] = l2;
        split_bf16(q0.w, q1.w, h2, l2); Qph[(e4 + 3) * 17 + cp] = h2; Qpl[(e4 + 3) * 17 + cp] = l2;
        uint_ kh[4], kl[4];
        split_bf16(k0.x, k1.x, kh[0], kl[0]);
        split_bf16(k0.y, k1.y, kh[1], kl[1]);
        split_bf16(k0.z, k1.z, kh[2], kl[2]);
        split_bf16(k0.w, k1.w, kh[3], kl[3]);
#pragma unroll
        for (int j = 0; j < 4; j++) {
            int e = e4 + j;
            int nt = e >> 3, ge = e & 7;
            int off = (ksw * 16 + nt) * 76 + ge * 8 + tgw * 2 + prw;
            KFh[off] = kh[j];
            KFl[off] = kl[j];
        }
    }
#pragma unroll
    for (int it = 0; it < 4; it++) {
        int t = warp + it * 8;
        int cb = (t & 3) * 8, pb = (t >> 2) * 16;
        int c = cb + (lane >> 2);
        int p4 = pb + (lane & 3) * 4;
        float4 v4 = *reinterpret_cast<const float4*>(&vin[base + (size_t)c * HW_ + p4]);
        uint_ h0, l0, h1, l1;
        split_bf16(v4.x, v4.y, h0, l0);
        split_bf16(v4.z, v4.w, h1, l1);
        int ip0 = p4 >> 1;
        int kb = ip0 >> 3;
        int t0 = ip0 & 3, p0 = (ip0 >> 2) & 1;
        int ip1 = ip0 + 1;
        int t1 = ip1 & 3, p1 = (ip1 >> 2) & 1;
        int nt = c >> 3, gv = c & 7;
        int rowbase = (kb * 4 + nt) * 76 + gv * 8;
        VFh[rowbase + t0 * 2 + p0] = h0;
        VFh[rowbase + t1 * 2 + p1] = h1;
        VFl[rowbase + t0 * 2 + p0] = l0;
        VFl[rowbase + t1 * 2 + p1] = l1;
    }
    __syncthreads();

    int r0 = warp * 16 + g;
    int r1 = r0 + 8;

    float dE[16][4];
#pragma unroll
    for (int nt = 0; nt < 16; nt++)
#pragma unroll
        for (int u = 0; u < 4; u++) dE[nt][u] = 0.f;

#pragma unroll
    for (int ks = 0; ks < 2; ks++) {
        int kpb = ks * 8;
        uint_ ah[4], al[4];
        ah[0] = Qph[r0 * 17 + kpb + tg];
        ah[1] = Qph[r1 * 17 + kpb + tg];
        ah[2] = Qph[r0 * 17 + kpb + tg + 4];
        ah[3] = Qph[r1 * 17 + kpb + tg + 4];
        al[0] = Qpl[r0 * 17 + kpb + tg];
        al[1] = Qpl[r1 * 17 + kpb + tg];
        al[2] = Qpl[r0 * 17 + kpb + tg + 4];
        al[3] = Qpl[r1 * 17 + kpb + tg + 4];
#pragma unroll
        for (int nt = 0; nt < 16; nt++) {
            int off = (ks * 16 + nt) * 76 + g * 8 + tg * 2;
            uint2 bh2 = *reinterpret_cast<const uint2*>(&KFh[off]);
            uint2 bl2 = *reinterpret_cast<const uint2*>(&KFl[off]);
            uint_ bh[2] = { bh2.x, bh2.y };
            uint_ bl[2] = { bl2.x, bl2.y };
            mma_bf16(dE[nt], ah, bh);
            mma_bf16(dE[nt], ah, bl);
            mma_bf16(dE[nt], al, bh);
        }
    }

    if (transposed) {
#pragma unroll
        for (int nt = 0; nt < 16; nt++) {
            int c0 = nt * 8 + 2 * tg, c1 = c0 + 1;
            if (c0 == r0) dE[nt][0] = -1e30f;
            if (c1 == r0) dE[nt][1] = -1e30f;
            if (c0 == r1) dE[nt][2] = -1e30f;
            if (c1 == r1) dE[nt][3] = -1e30f;
        }
    }

    float m0 = -1e30f, m1 = -1e30f;
#pragma unroll
    for (int nt = 0; nt < 16; nt++) {
        m0 = fmaxf(m0, fmaxf(dE[nt][0], dE[nt][1]));
        m1 = fmaxf(m1, fmaxf(dE[nt][2], dE[nt][3]));
    }
    m0 = fmaxf(m0, __shfl_xor_sync(0xffffffffu, m0, 1));
    m0 = fmaxf(m0, __shfl_xor_sync(0xffffffffu, m0, 2));
    m1 = fmaxf(m1, __shfl_xor_sync(0xffffffffu, m1, 1));
    m1 = fmaxf(m1, __shfl_xor_sync(0xffffffffu, m1, 2));

    float s0 = 0.f, s1 = 0.f;
#pragma unroll
    for (int nt = 0; nt < 16; nt++) {
        dE[nt][0] = __expf(dE[nt][0] - m0);
        dE[nt][1] = __expf(dE[nt][1] - m0);
        dE[nt][2] = __expf(dE[nt][2] - m1);
        dE[nt][3] = __expf(dE[nt][3] - m1);
        s0 += dE[nt][0] + dE[nt][1];
        s1 += dE[nt][2] + dE[nt][3];
    }
    s0 += __shfl_xor_sync(0xffffffffu, s0, 1);
    s0 += __shfl_xor_sync(0xffffffffu, s0, 2);
    s1 += __shfl_xor_sync(0xffffffffu, s1, 1);
    s1 += __shfl_xor_sync(0xffffffffu, s1, 2);

    if (tg == 0) {
        size_t s0i = transposed ? ((size_t)(b * H_ + r0) * W_ + X)
                                : ((size_t)(b * H_ + X) * W_ + r0);
        size_t s1i = transposed ? ((size_t)(b * H_ + r1) * W_ + X)
                                : ((size_t)(b * H_ + X) * W_ + r1);
        mstat[s0i] = m0;  sstat[s0i] = s0;
        mstat[s1i] = m1;  sstat[s1i] = s1;
    }

    float dO[4][4];
#pragma unroll
    for (int nt = 0; nt < 4; nt++)
#pragma unroll
        for (int u = 0; u < 4; u++) dO[nt][u] = 0.f;

#pragma unroll
    for (int kb = 0; kb < 8; kb++) {
        uint_ ah[4], al[4];
        split_bf16(dE[2 * kb][0],     dE[2 * kb][1],     ah[0], al[0]);
        split_bf16(dE[2 * kb][2],     dE[2 * kb][3],     ah[1], al[1]);
        split_bf16(dE[2 * kb + 1][0], dE[2 * kb + 1][1], ah[2], al[2]);
        split_bf16(dE[2 * kb + 1][2], dE[2 * kb + 1][3], ah[3], al[3]);
#pragma unroll
        for (int nt = 0; nt < 4; nt++) {
            int off = (kb * 4 + nt) * 76 + g * 8 + tg * 2;
            uint2 bh2 = *reinterpret_cast<const uint2*>(&VFh[off]);
            uint2 bl2 = *reinterpret_cast<const uint2*>(&VFl[off]);
            uint_ bh[2] = { bh2.x, bh2.y };
            uint_ bl[2] = { bl2.x, bl2.y };
            mma_bf16(dO[nt], ah, bh);
            mma_bf16(dO[nt], ah, bl);
            mma_bf16(dO[nt], al, bh);
        }
    }

    __syncthreads();
#pragma unroll
    for (int nt = 0; nt < 4; nt++) {
        int c0 = nt * 8 + 2 * tg;
        stg[c0 * 130 + r0]       = dO[nt][0];
        stg[(c0 + 1) * 130 + r0] = dO[nt][1];
        stg[c0 * 130 + r1]       = dO[nt][2];
        stg[(c0 + 1) * 130 + r1] = dO[nt][3];
    }
    __syncthreads();
    for (int idx = tid; idx < CR_ * 128; idx += 256) {
        int c = idx >> 7, e = idx & 127;
        outp[base + (size_t)c * HW_ + e] = stg[c * 130 + e];
    }
}

// ---------------- kernel 4: combine, channel-sliced (grid (H,B,4), 256 thr) ---
// CTA computes 64 out channels x 128 pixels. 3 CTAs/SM.
#define CB_WZH  0
#define CB_WZL  (64 * 18)
#define CB_MGH  (2 * 64 * 18)
#define CB_MGL  (2 * 64 * 18 + 16 * 132)
#define CB_F    (2 * 64 * 18 + 2 * 16 * 132)
#define COMB_SMEM ((2 * 64 * 18 + 2 * 16 * 132 + 256) * 4)

__global__ void __launch_bounds__(256, 3) combine_kernel(
    const float* __restrict__ x, const float* __restrict__ Wz,
    const float* __restrict__ bz, float* __restrict__ out)
{
    extern __shared__ uint_ cu[];
    uint_* Wzh = cu + CB_WZH;
    uint_* Wzl = cu + CB_WZL;
    uint_* Mgh = cu + CB_MGH;
    uint_* Mgl = cu + CB_MGL;
    float* fH  = reinterpret_cast<float*>(cu + CB_F);
    float* fW  = fH + 128;

    int h = blockIdx.x, b = blockIdx.y;
    int cbase = blockIdx.z * 64;
    int tid = threadIdx.x;
    int wp = tid >> 5, lane = tid & 31;
    int g = lane >> 2, tg = lane & 3;
    int wm = wp >> 2, wn = wp & 3;           // 2 x 4 warp grid
    int m0 = wm * 32, n0 = wn * 32;

    if (tid < 128) {
        int w = tid;
        size_t sidx = (size_t)(b * H_ + h) * W_ + w;
        float mh = g_mH[sidx], mw = g_mW[sidx];
        float sh = g_sH[sidx], sw = g_sW[sidx];
        float m  = fmaxf(mh, mw);
        float eh = __expf(mh - m), ew = __expf(mw - m);
        float inv = 1.0f / (sh * eh + sw * ew);
        fH[w] = eh * inv;
        fW[w] = ew * inv;
    }
    // Wz slice: rows cbase..cbase+63
    for (int idx = tid; idx < 64 * 8; idx += 256) {
        int r = idx >> 3, f4 = idx & 7;
        float4 w4 = *reinterpret_cast<const float4*>(&Wz[(cbase + r) * 32 + 4 * f4]);
        uint_ h0, l0, h1, l1;
        split_bf16(w4.x, w4.y, h0, l0);
        split_bf16(w4.z, w4.w, h1, l1);
        Wzh[r * 18 + 2 * f4]     = h0;
        Wzh[r * 18 + 2 * f4 + 1] = h1;
        Wzl[r * 18 + 2 * f4]     = l0;
        Wzl[r * 18 + 2 * f4 + 1] = l1;
    }
    __syncthreads();

    for (int idx = tid; idx < 16 * 32; idx += 256) {
        int kp = idx >> 5, w4 = (idx & 31) * 4;
        size_t off0 = (size_t)(b * CR_ + 2 * kp) * HW_ + (size_t)h * W_ + w4;
        size_t off1 = off0 + HW_;
        float4 oh0 = *reinterpret_cast<const float4*>(&g_oHt[off0]);
        float4 ow0 = *reinterpret_cast<const float4*>(&g_oW [off0]);
        float4 oh1 = *reinterpret_cast<const float4*>(&g_oHt[off1]);
        float4 ow1 = *reinterpret_cast<const float4*>(&g_oW [off1]);
        float fh0 = fH[w4], fh1 = fH[w4 + 1], fh2 = fH[w4 + 2], fh3 = fH[w4 + 3];
        float fw0 = fW[w4], fw1 = fW[w4 + 1], fw2 = fW[w4 + 2], fw3 = fW[w4 + 3];
        float c0p0 = oh0.x * fh0 + ow0.x * fw0;
        float c0p1 = oh0.y * fh1 + ow0.y * fw1;
        float c0p2 = oh0.z * fh2 + ow0.z * fw2;
        float c0p3 = oh0.w * fh3 + ow0.w * fw3;
        float c1p0 = oh1.x * fh0 + ow1.x * fw0;
        float c1p1 = oh1.y * fh1 + ow1.y * fw1;
        float c1p2 = oh1.z * fh2 + ow1.z * fw2;
        float c1p3 = oh1.w * fh3 + ow1.w * fw3;
        uint_ hh[4], ll[4];
        split_bf16(c0p0, c1p0, hh[0], ll[0]);
        split_bf16(c0p1, c1p1, hh[1], ll[1]);
        split_bf16(c0p2, c1p2, hh[2], ll[2]);
        split_bf16(c0p3, c1p3, hh[3], ll[3]);
        *reinterpret_cast<uint4*>(&Mgh[kp * 132 + w4]) = make_uint4(hh[0], hh[1], hh[2], hh[3]);
        *reinterpret_cast<uint4*>(&Mgl[kp * 132 + w4]) = make_uint4(ll[0], ll[1], ll[2], ll[3]);
    }
    __syncthreads();

    float acc[2][4][4];
#pragma unroll
    for (int mt = 0; mt < 2; mt++)
#pragma unroll
        for (int nt = 0; nt < 4; nt++)
#pragma unroll
            for (int u = 0; u < 4; u++) acc[mt][nt][u] = 0.f;

#pragma unroll
    for (int ks = 0; ks < 2; ks++) {
        int kpb = ks * 8;
        uint_ bh[4][2], bl[4][2];
#pragma unroll
        for (int nt = 0; nt < 4; nt++) {
            int n = n0 + nt * 8 + g;
            bh[nt][0] = Mgh[(kpb + tg) * 132 + n];
            bh[nt][1] = Mgh[(kpb + tg + 4) * 132 + n];
            bl[nt][0] = Mgl[(kpb + tg) * 132 + n];
            bl[nt][1] = Mgl[(kpb + tg + 4) * 132 + n];
        }
#pragma unroll
        for (int mt = 0; mt < 2; mt++) {
            int m = m0 + mt * 16 + g;
            uint_ ah[4], al[4];
            ah[0] = Wzh[m * 18 + kpb + tg];
            ah[1] = Wzh[(m + 8) * 18 + kpb + tg];
            ah[2] = Wzh[m * 18 + kpb + tg + 4];
            ah[3] = Wzh[(m + 8) * 18 + kpb + tg + 4];
            al[0] = Wzl[m * 18 + kpb + tg];
            al[1] = Wzl[(m + 8) * 18 + kpb + tg];
            al[2] = Wzl[m * 18 + kpb + tg + 4];
            al[3] = Wzl[(m + 8) * 18 + kpb + tg + 4];
#pragma unroll
            for (int nt = 0; nt < 4; nt++) {
                mma_bf16(acc[mt][nt], ah, bh[nt]);
                mma_bf16(acc[mt][nt], ah, bl[nt]);
                mma_bf16(acc[mt][nt], al, bh[nt]);
            }
        }
    }

#pragma unroll
    for (int mt = 0; mt < 2; mt++) {
#pragma unroll
        for (int half = 0; half < 2; half++) {
            int o = cbase + m0 + mt * 16 + g + 8 * half;
            float bias = bz[o];
            size_t obase = ((size_t)(b * C_ + o) * H_ + h) * W_;
#pragma unroll
            for (int nt = 0; nt < 4; nt++) {
                int pix = n0 + nt * 8 + 2 * tg;
                float2 xv = *reinterpret_cast<const float2*>(&x[obase + pix]);
                float2 v;
                v.x = acc[mt][nt][2 * half]     + bias + xv.x;
                v.y = acc[mt][nt][2 * half + 1] + bias + xv.y;
                *reinterpret_cast<float2*>(&out[obase + pix]) = v;
            }
        }
    }
}

// ---------------- launch ------------------------------------------------------
extern "C" void kernel_launch(void* const* d_in, const int* in_sizes, int n_in,
                              void* d_out, int out_size)
{
    const float* x  = (const float*)d_in[0];
    const float* Wq = (const float*)d_in[1];
    const float* bq = (const float*)d_in[2];
    const float* Wk = (const float*)d_in[3];
    const float* bk = (const float*)d_in[4];
    const float* Wv = (const float*)d_in[5];
    const float* bv = (const float*)d_in[6];
    const float* Wz = (const float*)d_in[7];
    const float* bz = (const float*)d_in[8];
    float* out = (float*)d_out;

    cudaFuncSetAttribute(proj_mma_kernel, cudaFuncAttributeMaxDynamicSharedMemorySize, PROJ_SMEM);
    cudaFuncSetAttribute(attn_kernel,     cudaFuncAttributeMaxDynamicSharedMemorySize, ATTN_SMEM);
    cudaFuncSetAttribute(combine_kernel,  cudaFuncAttributeMaxDynamicSharedMemorySize, COMB_SMEM);

    proj_mma_kernel<<<dim3(H_, B_, 2), 256, PROJ_SMEM>>>(x, Wq, bq, Wk, bk, Wv, bv);
    transpose_kernel<<<dim3(4, 4, 3 * 256), dim3(32, 8)>>>(0);   // q,k,v -> qt,kt,vt
    attn_kernel<<<dim3(W_, B_), 256, ATTN_SMEM>>>(1);            // H path
    attn_kernel<<<dim3(H_, B_), 256, ATTN_SMEM>>>(0);            // W path
    transpose_kernel<<<dim3(4, 4, 256), dim3(32, 8)>>>(3);       // oH -> oHt
    combine_kernel<<<dim3(H_, B_, 4), 256, COMB_SMEM>>>(x, Wz, bz, out);
}